// round 1
// baseline (speedup 1.0000x reference)
#include <cuda_runtime.h>
#include <math.h>

// ---------------- problem constants ----------------
#define NB   4
#define LQ   8192
#define SS   8192
#define DD   256
#define HH   8
#define HD   32
#define D2   512
#define MR   (NB*LQ)        // 32768 rows (== NB*SS)
#define EPS_ATTN 1e-6f
#define EPS_LN   1e-5f

// ---------------- scratch (device globals; no allocation allowed) ----------
__device__ float g_Q  [(size_t)MR*DD];
__device__ float g_K  [(size_t)MR*DD];
__device__ float g_V  [(size_t)MR*DD];
__device__ float g_KV [NB*HH*HD*HD];
__device__ float g_Ksum[NB*HH*HD];
__device__ float g_msg [(size_t)MR*DD];
__device__ float g_msg2[(size_t)MR*DD];
__device__ float g_cat [(size_t)MR*D2];
__device__ float g_h1  [(size_t)MR*D2];
__device__ float g_h2  [(size_t)MR*DD];

// ---------------- generic TN GEMM: C[m,n] = act(sum_k A[m,k]*B[n,k]) * mask[m] * scale
#define BM 128
#define BN 128
#define BK 16

enum { ACT_NONE = 0, ACT_ELU1 = 1, ACT_RELU = 2 };

template<int ACT, bool HASMASK>
__global__ __launch_bounds__(256)
void gemm_tn(const float* __restrict__ A, const float* __restrict__ B,
             float* __restrict__ C, int M, int Nc, int K,
             const float* __restrict__ mask, float scale)
{
    __shared__ float As[BK][BM + 4];
    __shared__ float Bs[BK][BN + 4];

    const int bm  = blockIdx.y * BM;
    const int bn  = blockIdx.x * BN;
    const int tid = threadIdx.x;
    const int tr  = tid >> 4;    // 0..15
    const int tc  = tid & 15;    // 0..15

    float acc[8][8];
#pragma unroll
    for (int i = 0; i < 8; i++)
#pragma unroll
        for (int j = 0; j < 8; j++) acc[i][j] = 0.f;

    for (int k0 = 0; k0 < K; k0 += BK) {
#pragma unroll
        for (int i = 0; i < 2; i++) {
            int idx = tid * 2 + i;          // 0..511
            int row = idx >> 2;             // 0..127
            int c4  = (idx & 3) * 4;        // 0,4,8,12
            float4 a = *(const float4*)(A + (size_t)(bm + row) * K + k0 + c4);
            As[c4 + 0][row] = a.x; As[c4 + 1][row] = a.y;
            As[c4 + 2][row] = a.z; As[c4 + 3][row] = a.w;
            float4 b = *(const float4*)(B + (size_t)(bn + row) * K + k0 + c4);
            Bs[c4 + 0][row] = b.x; Bs[c4 + 1][row] = b.y;
            Bs[c4 + 2][row] = b.z; Bs[c4 + 3][row] = b.w;
        }
        __syncthreads();

#pragma unroll
        for (int k = 0; k < BK; k++) {
            float a[8], b[8];
            *(float4*)(a)     = *(const float4*)&As[k][tr * 8];
            *(float4*)(a + 4) = *(const float4*)&As[k][tr * 8 + 4];
            *(float4*)(b)     = *(const float4*)&Bs[k][tc * 8];
            *(float4*)(b + 4) = *(const float4*)&Bs[k][tc * 8 + 4];
#pragma unroll
            for (int i = 0; i < 8; i++)
#pragma unroll
                for (int j = 0; j < 8; j++)
                    acc[i][j] += a[i] * b[j];
        }
        __syncthreads();
    }

#pragma unroll
    for (int i = 0; i < 8; i++) {
        int m = bm + tr * 8 + i;
        float mk = HASMASK ? mask[m] : 1.f;
#pragma unroll
        for (int j = 0; j < 8; j++) {
            float v = acc[i][j];
            if (ACT == ACT_ELU1) v = (v > 0.f) ? (v + 1.f) : expf(v);
            else if (ACT == ACT_RELU) v = fmaxf(v, 0.f);
            acc[i][j] = v * mk * scale;
        }
        float4* cp = (float4*)(C + (size_t)m * Nc + bn + tc * 8);
        cp[0] = make_float4(acc[i][0], acc[i][1], acc[i][2], acc[i][3]);
        cp[1] = make_float4(acc[i][4], acc[i][5], acc[i][6], acc[i][7]);
    }
}

// ---------------- zero KV/Ksum accumulators ----------------
__global__ void zero_kv_kernel()
{
    int i = blockIdx.x * blockDim.x + threadIdx.x;
    if (i < NB * HH * HD * HD) g_KV[i] = 0.f;
    if (i < NB * HH * HD)      g_Ksum[i] = 0.f;
}

// ---------------- KV = sum_s K[n,s,h,:] (x) v[n,s,h,:] ; Ksum = sum_s K ----
#define KVSPLIT 64
#define SCHUNK  (SS / KVSPLIT)   // 128

__global__ __launch_bounds__(256)
void kv_kernel(const float* __restrict__ Kp, const float* __restrict__ Vp)
{
    __shared__ float Ks[SCHUNK][HD];
    __shared__ float Vs[SCHUNK][HD];

    const int nh = blockIdx.x;        // 0..31
    const int n  = nh >> 3;
    const int h  = nh & 7;
    const int s0 = blockIdx.y * SCHUNK;
    const int tid = threadIdx.x;

#pragma unroll
    for (int i = 0; i < 4; i++) {
        int idx = tid + 256 * i;          // 0..1023
        int row = idx >> 3;               // 0..127
        int c   = (idx & 7) * 4;          // 0..28
        size_t g = ((size_t)(n * SS + s0 + row)) * DD + h * HD + c;
        *(float4*)&Ks[row][c] = *(const float4*)(Kp + g);
        *(float4*)&Vs[row][c] = *(const float4*)(Vp + g);
    }
    __syncthreads();

    const int d  = tid >> 3;            // 0..31
    const int e0 = (tid & 7) * 4;       // 0..28
    float a0 = 0.f, a1 = 0.f, a2 = 0.f, a3 = 0.f, ks = 0.f;
    for (int s = 0; s < SCHUNK; s++) {
        float kd = Ks[s][d];
        float4 v = *(const float4*)&Vs[s][e0];
        a0 += kd * v.x; a1 += kd * v.y; a2 += kd * v.z; a3 += kd * v.w;
        ks += kd;
    }
    float* KV = g_KV + (size_t)nh * HD * HD + d * HD + e0;
    atomicAdd(KV + 0, a0); atomicAdd(KV + 1, a1);
    atomicAdd(KV + 2, a2); atomicAdd(KV + 3, a3);
    if ((tid & 7) == 0) atomicAdd(g_Ksum + nh * HD + d, ks);
}

// ---------------- msg[n,l,h,e] = S * Z * sum_d Q[n,l,h,d]*KV[n,h,d,e] -------
#define MROWS 8
__global__ __launch_bounds__(256)
void msg_kernel(const float* __restrict__ Qp, float* __restrict__ msg)
{
    __shared__ float KVs[HH][HD][HD];    // 32 KB
    __shared__ float Ksums[HH * HD];
    __shared__ float Qs[DD];

    const int r0  = blockIdx.x * MROWS;
    const int n   = r0 / LQ;
    const int tid = threadIdx.x;

    {
        const float4* kv4  = (const float4*)(g_KV + (size_t)n * HH * HD * HD);
        float4*       kvs4 = (float4*)&KVs[0][0][0];
#pragma unroll
        for (int i = 0; i < 8; i++) kvs4[tid + 256 * i] = kv4[tid + 256 * i];
        Ksums[tid] = g_Ksum[n * HH * HD + tid];
    }
    __syncthreads();

    const int h    = tid >> 5;   // warp == head
    const int lane = tid & 31;

    for (int r = 0; r < MROWS; r++) {
        Qs[tid] = Qp[(size_t)(r0 + r) * DD + tid];
        __syncthreads();

        float p = Qs[h * HD + lane] * Ksums[h * HD + lane];
#pragma unroll
        for (int o = 16; o > 0; o >>= 1) p += __shfl_xor_sync(0xffffffffu, p, o);
        float z = 1.0f / (p + EPS_ATTN);

        float acc = 0.f;
#pragma unroll
        for (int d = 0; d < HD; d++) acc += Qs[h * HD + d] * KVs[h][d][lane];

        msg[(size_t)(r0 + r) * DD + tid] = acc * z * (float)SS;
        __syncthreads();
    }
}

// ---------------- block reduce helper ----------------
__device__ __forceinline__ float blk_sum(float v, float* sbuf)
{
#pragma unroll
    for (int o = 16; o > 0; o >>= 1) v += __shfl_xor_sync(0xffffffffu, v, o);
    if ((threadIdx.x & 31) == 0) sbuf[threadIdx.x >> 5] = v;
    __syncthreads();
    float r = 0.f;
#pragma unroll
    for (int i = 0; i < 8; i++) r += sbuf[i];
    __syncthreads();
    return r;
}

// ---------------- LN(msg2) + build concat buffer [x | ln(msg2)] -------------
__global__ __launch_bounds__(256)
void ln_concat_kernel(const float* __restrict__ m2, const float* __restrict__ x,
                      const float* __restrict__ g, const float* __restrict__ b,
                      float* __restrict__ cat)
{
    __shared__ float sbuf[8];
    const size_t row = blockIdx.x;
    const int t = threadIdx.x;
    float v = m2[row * DD + t];
    float mu = blk_sum(v, sbuf) * (1.f / DD);
    float dv = v - mu;
    float var = blk_sum(dv * dv, sbuf) * (1.f / DD);
    float y = dv * rsqrtf(var + EPS_LN) * g[t] + b[t];
    cat[row * D2 + t]      = x[row * DD + t];
    cat[row * D2 + DD + t] = y;
}

// ---------------- out = x + LN(h2) ----------------
__global__ __launch_bounds__(256)
void ln_residual_kernel(const float* __restrict__ h2, const float* __restrict__ x,
                        const float* __restrict__ g, const float* __restrict__ b,
                        float* __restrict__ out)
{
    __shared__ float sbuf[8];
    const size_t row = blockIdx.x;
    const int t = threadIdx.x;
    float v = h2[row * DD + t];
    float mu = blk_sum(v, sbuf) * (1.f / DD);
    float dv = v - mu;
    float var = blk_sum(dv * dv, sbuf) * (1.f / DD);
    float y = dv * rsqrtf(var + EPS_LN) * g[t] + b[t];
    out[row * DD + t] = x[row * DD + t] + y;
}

// ---------------- host launcher ----------------
static float* sym_addr(const void* sym)
{
    void* p = nullptr;
    cudaGetSymbolAddress(&p, sym);
    return (float*)p;
}

extern "C" void kernel_launch(void* const* d_in, const int* in_sizes, int n_in,
                              void* d_out, int out_size)
{
    const float* x           = (const float*)d_in[0];
    const float* source      = (const float*)d_in[1];
    const float* x_mask      = (const float*)d_in[2];
    const float* source_mask = (const float*)d_in[3];
    const float* Wq          = (const float*)d_in[4];
    const float* Wk          = (const float*)d_in[5];
    const float* Wv          = (const float*)d_in[6];
    const float* Wm          = (const float*)d_in[7];
    const float* W1          = (const float*)d_in[8];
    const float* W2          = (const float*)d_in[9];
    const float* g1          = (const float*)d_in[10];
    const float* b1          = (const float*)d_in[11];
    const float* g2          = (const float*)d_in[12];
    const float* b2          = (const float*)d_in[13];
    float* out = (float*)d_out;

    float* pQ    = sym_addr(g_Q);
    float* pK    = sym_addr(g_K);
    float* pV    = sym_addr(g_V);
    float* pMsg  = sym_addr(g_msg);
    float* pMsg2 = sym_addr(g_msg2);
    float* pCat  = sym_addr(g_cat);
    float* pH1   = sym_addr(g_h1);
    float* pH2   = sym_addr(g_h2);

    dim3 blk(256);
    dim3 g256(DD / BN, MR / BM);   // (2, 256)
    dim3 g512(D2 / BN, MR / BM);   // (4, 256)

    zero_kv_kernel<<<(NB * HH * HD * HD + 255) / 256, 256>>>();

    // Q = (elu(x@Wq.T)+1) * x_mask ; K likewise with source_mask ; V = (source@Wv.T)*mask/S
    gemm_tn<ACT_ELU1, true ><<<g256, blk>>>(x,      Wq, pQ, MR, DD, DD, x_mask,      1.f);
    gemm_tn<ACT_ELU1, true ><<<g256, blk>>>(source, Wk, pK, MR, DD, DD, source_mask, 1.f);
    gemm_tn<ACT_NONE, true ><<<g256, blk>>>(source, Wv, pV, MR, DD, DD, source_mask, 1.f / (float)SS);

    // KV[n,h,d,e], Ksum[n,h,d]
    kv_kernel<<<dim3(NB * HH, KVSPLIT), blk>>>(pK, pV);

    // msg[n,l,:] (heads merged)
    msg_kernel<<<MR / MROWS, blk>>>(pQ, pMsg);

    // msg2 = msg @ Wm.T
    gemm_tn<ACT_NONE, false><<<g256, blk>>>(pMsg, Wm, pMsg2, MR, DD, DD, nullptr, 1.f);

    // cat = [x | LN(msg2)]
    ln_concat_kernel<<<MR, blk>>>(pMsg2, x, g1, b1, pCat);

    // h1 = relu(cat @ W1.T) ; h2 = h1 @ W2.T
    gemm_tn<ACT_RELU, false><<<g512, blk>>>(pCat, W1, pH1, MR, D2, D2, nullptr, 1.f);
    gemm_tn<ACT_NONE, false><<<g256, blk>>>(pH1,  W2, pH2, MR, DD, D2, nullptr, 1.f);

    // out = x + LN(h2)
    ln_residual_kernel<<<MR, blk>>>(pH2, x, g2, b2, out);
}

// round 3
// speedup vs baseline: 2.1278x; 2.1278x over previous
#include <cuda_runtime.h>
#include <cuda_bf16.h>
#include <math.h>
#include <stdint.h>

// ---------------- problem constants ----------------
#define NB   4
#define LQ   8192
#define SS   8192
#define DD   256
#define HH   8
#define HD   32
#define D2   512
#define MR   (NB*LQ)        // 32768
#define EPS_ATTN 1e-6f
#define EPS_LN   1e-5f

// ---------------- scratch (device globals) ----------------
__device__ float g_Q   [(size_t)MR*DD];
__device__ float g_K   [(size_t)MR*DD];
__device__ float g_V   [(size_t)MR*DD];
__device__ float g_KV  [NB*HH*HD*HD];
__device__ float g_Ksum[NB*HH*HD];
__device__ float g_msg2[(size_t)MR*DD];
__device__ float g_h2  [(size_t)MR*DD];

// split bf16 activations
__device__ __nv_bfloat16 g_xs_h [(size_t)MR*DD];
__device__ __nv_bfloat16 g_xs_l [(size_t)MR*DD];
__device__ __nv_bfloat16 g_ss_h [(size_t)MR*DD];
__device__ __nv_bfloat16 g_ss_l [(size_t)MR*DD];
__device__ __nv_bfloat16 g_msg_h[(size_t)MR*DD];
__device__ __nv_bfloat16 g_msg_l[(size_t)MR*DD];
__device__ __nv_bfloat16 g_cat_h[(size_t)MR*D2];
__device__ __nv_bfloat16 g_cat_l[(size_t)MR*D2];
__device__ __nv_bfloat16 g_h1_h [(size_t)MR*D2];
__device__ __nv_bfloat16 g_h1_l [(size_t)MR*D2];

// split bf16 weights
__device__ __nv_bfloat16 g_wq_h[DD*DD], g_wq_l[DD*DD];
__device__ __nv_bfloat16 g_wk_h[DD*DD], g_wk_l[DD*DD];
__device__ __nv_bfloat16 g_wv_h[DD*DD], g_wv_l[DD*DD];
__device__ __nv_bfloat16 g_wm_h[DD*DD], g_wm_l[DD*DD];
__device__ __nv_bfloat16 g_w1_h[D2*D2], g_w1_l[D2*D2];
__device__ __nv_bfloat16 g_w2_h[DD*D2], g_w2_l[DD*D2];

// ---------------- low-level helpers ----------------
__device__ __forceinline__ uint32_t smem_u32(const void* p) {
    uint32_t a;
    asm("{ .reg .u64 t; cvta.to.shared.u64 t, %1; cvt.u32.u64 %0, t; }"
        : "=r"(a) : "l"(p));
    return a;
}

__device__ __forceinline__ uint32_t sw128(uint32_t off) {
    return off ^ ((off >> 3) & 0x70);
}

#define CPASYNC16(sa, ga) \
    asm volatile("cp.async.cg.shared.global [%0], [%1], 16;" \
                 :: "r"(sa), "l"(ga) : "memory")
#define CPCOMMIT() asm volatile("cp.async.commit_group;" ::: "memory")
#define CPWAIT0()  asm volatile("cp.async.wait_group 0;" ::: "memory")
#define CPWAIT1()  asm volatile("cp.async.wait_group 1;" ::: "memory")

#define LDSM4(r, addr) \
    asm volatile("ldmatrix.sync.aligned.m8n8.x4.shared.b16 {%0,%1,%2,%3}, [%4];" \
        : "=r"((r)[0]), "=r"((r)[1]), "=r"((r)[2]), "=r"((r)[3]) : "r"(addr))

__device__ __forceinline__ void mma_bf16(float* c, const uint32_t* a,
                                         uint32_t b0, uint32_t b1) {
    asm volatile(
        "mma.sync.aligned.m16n8k16.row.col.f32.bf16.bf16.f32 "
        "{%0,%1,%2,%3}, {%4,%5,%6,%7}, {%8,%9}, {%0,%1,%2,%3};"
        : "+f"(c[0]), "+f"(c[1]), "+f"(c[2]), "+f"(c[3])
        : "r"(a[0]), "r"(a[1]), "r"(a[2]), "r"(a[3]), "r"(b0), "r"(b1));
}

// ---------------- split helper ----------------
__device__ __forceinline__ void split1(float v, __nv_bfloat16& h, __nv_bfloat16& l) {
    h = __float2bfloat16_rn(v);
    l = __float2bfloat16_rn(v - __bfloat162float(h));
}

// ---------------- tensor-core GEMM (HMMA mma.sync) ----------------
// C[m,n] = act(sum_k A[m,k]*B[n,k]) * mask[m] * scale ; A,B as bf16 (hi,lo)
// CTA tile 128x128, 8 warps as 4(M) x 2(N), warp tile 32x64.
// K staged in chunks of 64 bf16 (SW128 swizzled), double-buffered cp.async.
#define T_BYTES   16384u           // 128 rows x 128B per matrix tile
#define STG_BYTES (4u*T_BYTES)     // Ah,Al,Bh,Bl per stage = 64KB
#define GSMEM     (2u*STG_BYTES)   // 128KB

enum { ACT_NONE = 0, ACT_ELU1 = 1, ACT_RELU = 2 };

template<int ACT, bool HASMASK, bool SPLITOUT>
__global__ __launch_bounds__(256, 1)
void gemm_tc(const __nv_bfloat16* __restrict__ Ahp, const __nv_bfloat16* __restrict__ Alp,
             const __nv_bfloat16* __restrict__ Bhp, const __nv_bfloat16* __restrict__ Blp,
             float* __restrict__ C, __nv_bfloat16* __restrict__ Ch, __nv_bfloat16* __restrict__ Cl,
             int Nc, int K, const float* __restrict__ mask, float scale)
{
    extern __shared__ char smem[];
    const uint32_t sb = smem_u32(smem);
    const int tid  = threadIdx.x;
    const int lane = tid & 31;
    const int wid  = tid >> 5;
    const int wm   = wid >> 1;     // 0..3  (M offset wm*32)
    const int wn   = wid & 1;      // 0..1  (N offset wn*64)
    const int bm   = blockIdx.y * 128;
    const int bn   = blockIdx.x * 128;

    float acc[2][8][4];
#pragma unroll
    for (int i = 0; i < 2; i++)
#pragma unroll
        for (int j = 0; j < 8; j++)
#pragma unroll
            for (int v = 0; v < 4; v++) acc[i][j][v] = 0.f;

    // per-thread cp.async slots: 4 iterations x (row, chunk) per tile
    const int NCC = K >> 6;

    // issue one chunk's loads into stage st
    auto load_chunk = [&](int st, int c) {
        const int k0 = c * 64;
        const uint32_t stb = sb + st * STG_BYTES;
#pragma unroll
        for (int i = 0; i < 4; i++) {
            int ci  = tid + 256 * i;      // 0..1023
            int row = ci >> 3;            // 0..127
            int c16 = ci & 7;             // 16B chunk
            uint32_t so = sw128((uint32_t)(row * 128 + c16 * 16));
            size_t ga = (size_t)(bm + row) * K + k0 + c16 * 8;
            size_t gb = (size_t)(bn + row) * K + k0 + c16 * 8;
            CPASYNC16(stb + 0 * T_BYTES + so, Ahp + ga);
            CPASYNC16(stb + 1 * T_BYTES + so, Alp + ga);
            CPASYNC16(stb + 2 * T_BYTES + so, Bhp + gb);
            CPASYNC16(stb + 3 * T_BYTES + so, Blp + gb);
        }
        CPCOMMIT();
    };

    load_chunk(0, 0);

    // ldmatrix per-lane address components
    const int a_row = wm * 32 + (lane & 15);                       // + mt*16
    const int a_kb  = (lane >> 4) * 16;                            // byte offset within k-step
    const int b_row = wn * 64 + (lane & 7) + ((lane >> 4) << 3);   // + ntp*16
    const int b_kb  = ((lane >> 3) & 1) * 16;

    for (int c = 0; c < NCC; c++) {
        if (c + 1 < NCC) { load_chunk((c + 1) & 1, c + 1); CPWAIT1(); }
        else             { CPWAIT0(); }
        __syncthreads();

        const uint32_t stb = sb + (c & 1) * STG_BYTES;
#pragma unroll
        for (int ks = 0; ks < 4; ks++) {
            uint32_t ah[2][4], al[2][4], bh[4][4], bl[4][4];
#pragma unroll
            for (int mt = 0; mt < 2; mt++) {
                uint32_t ra = sw128((uint32_t)((a_row + mt * 16) * 128 + ks * 32 + a_kb));
                LDSM4(ah[mt], stb + 0 * T_BYTES + ra);
                LDSM4(al[mt], stb + 1 * T_BYTES + ra);
            }
#pragma unroll
            for (int ntp = 0; ntp < 4; ntp++) {
                uint32_t rb = sw128((uint32_t)((b_row + ntp * 16) * 128 + ks * 32 + b_kb));
                LDSM4(bh[ntp], stb + 2 * T_BYTES + rb);
                LDSM4(bl[ntp], stb + 3 * T_BYTES + rb);
            }
#pragma unroll
            for (int mt = 0; mt < 2; mt++)
#pragma unroll
                for (int nt = 0; nt < 8; nt++) {
                    const int ntp = nt >> 1, o = (nt & 1) * 2;
                    mma_bf16(acc[mt][nt], ah[mt], bh[ntp][o], bh[ntp][o + 1]);
                    mma_bf16(acc[mt][nt], ah[mt], bl[ntp][o], bl[ntp][o + 1]);
                    mma_bf16(acc[mt][nt], al[mt], bh[ntp][o], bh[ntp][o + 1]);
                }
        }
        __syncthreads();
    }

    // ---------------- epilogue: act/mask/scale -> smem -> coalesced out ----
    float* sf = (float*)smem;   // 128 x 132 floats (67.5KB, reuses stages)
    {
        float mk[2][2];   // [mt][half(+8)]
#pragma unroll
        for (int mt = 0; mt < 2; mt++)
#pragma unroll
            for (int hh = 0; hh < 2; hh++) {
                int m = bm + wm * 32 + mt * 16 + (lane >> 2) + hh * 8;
                mk[mt][hh] = (HASMASK ? mask[m] : 1.f) * scale;
            }
#pragma unroll
        for (int mt = 0; mt < 2; mt++)
#pragma unroll
            for (int nt = 0; nt < 8; nt++) {
                int r0 = wm * 32 + mt * 16 + (lane >> 2);
                int c0 = wn * 64 + nt * 8 + (lane & 3) * 2;
#pragma unroll
                for (int v = 0; v < 4; v++) {
                    int row = r0 + (v >> 1) * 8;
                    int col = c0 + (v & 1);
                    float x = acc[mt][nt][v];
                    if (ACT == ACT_ELU1)      x = (x > 0.f) ? (x + 1.f) : expf(x);
                    else if (ACT == ACT_RELU) x = fmaxf(x, 0.f);
                    sf[row * 132 + col] = x * mk[mt][v >> 1];
                }
            }
    }
    __syncthreads();

#pragma unroll 8
    for (int i = 0; i < 64; i++) {
        int e   = tid + 256 * i;        // 0..16383
        int row = e >> 7;
        int col = e & 127;
        float v = sf[row * 132 + col];
        size_t gi = (size_t)(bm + row) * Nc + bn + col;
        if (SPLITOUT) {
            __nv_bfloat16 h, l; split1(v, h, l);
            Ch[gi] = h; Cl[gi] = l;
        } else {
            C[gi] = v;
        }
    }
}

// ---------------- fp32 -> (hi,lo) bf16 split ----------------
__global__ __launch_bounds__(256)
void split_kernel(const float* __restrict__ s, __nv_bfloat16* __restrict__ hi,
                  __nv_bfloat16* __restrict__ lo, int n4)
{
    int i = blockIdx.x * 256 + threadIdx.x;
    if (i >= n4) return;
    float4 v = *(const float4*)(s + (size_t)i * 4);
    __nv_bfloat16 h[4], l[4];
    split1(v.x, h[0], l[0]); split1(v.y, h[1], l[1]);
    split1(v.z, h[2], l[2]); split1(v.w, h[3], l[3]);
    __nv_bfloat162* hp = (__nv_bfloat162*)(hi + (size_t)i * 4);
    __nv_bfloat162* lp = (__nv_bfloat162*)(lo + (size_t)i * 4);
    hp[0] = __nv_bfloat162(h[0], h[1]); hp[1] = __nv_bfloat162(h[2], h[3]);
    lp[0] = __nv_bfloat162(l[0], l[1]); lp[1] = __nv_bfloat162(l[2], l[3]);
}

// ---------------- zero KV/Ksum ----------------
__global__ void zero_kv_kernel()
{
    int i = blockIdx.x * blockDim.x + threadIdx.x;
    if (i < NB * HH * HD * HD) g_KV[i] = 0.f;
    if (i < NB * HH * HD)      g_Ksum[i] = 0.f;
}

// ---------------- KV = sum_s K (x) v ; Ksum = sum_s K ----------------
#define KVSPLIT 64
#define SCHUNK  (SS / KVSPLIT)   // 128

__global__ __launch_bounds__(256)
void kv_kernel(const float* __restrict__ Kp, const float* __restrict__ Vp)
{
    __shared__ float Ks[SCHUNK][HD];
    __shared__ float Vs[SCHUNK][HD];

    const int nh = blockIdx.x;
    const int n  = nh >> 3;
    const int h  = nh & 7;
    const int s0 = blockIdx.y * SCHUNK;
    const int tid = threadIdx.x;

#pragma unroll
    for (int i = 0; i < 4; i++) {
        int idx = tid + 256 * i;
        int row = idx >> 3;
        int c   = (idx & 7) * 4;
        size_t g = ((size_t)(n * SS + s0 + row)) * DD + h * HD + c;
        *(float4*)&Ks[row][c] = *(const float4*)(Kp + g);
        *(float4*)&Vs[row][c] = *(const float4*)(Vp + g);
    }
    __syncthreads();

    const int d  = tid >> 3;
    const int e0 = (tid & 7) * 4;
    float a0 = 0.f, a1 = 0.f, a2 = 0.f, a3 = 0.f, ks = 0.f;
    for (int s = 0; s < SCHUNK; s++) {
        float kd = Ks[s][d];
        float4 v = *(const float4*)&Vs[s][e0];
        a0 += kd * v.x; a1 += kd * v.y; a2 += kd * v.z; a3 += kd * v.w;
        ks += kd;
    }
    float* KV = g_KV + (size_t)nh * HD * HD + d * HD + e0;
    atomicAdd(KV + 0, a0); atomicAdd(KV + 1, a1);
    atomicAdd(KV + 2, a2); atomicAdd(KV + 3, a3);
    if ((tid & 7) == 0) atomicAdd(g_Ksum + nh * HD + d, ks);
}

// ---------------- msg (split bf16 output) ----------------
#define MROWS 8
__global__ __launch_bounds__(256)
void msg_kernel(const float* __restrict__ Qp,
                __nv_bfloat16* __restrict__ mh, __nv_bfloat16* __restrict__ ml)
{
    __shared__ float KVs[HH][HD][HD];
    __shared__ float Ksums[HH * HD];
    __shared__ float Qs[DD];

    const int r0  = blockIdx.x * MROWS;
    const int n   = r0 / LQ;
    const int tid = threadIdx.x;

    {
        const float4* kv4  = (const float4*)(g_KV + (size_t)n * HH * HD * HD);
        float4*       kvs4 = (float4*)&KVs[0][0][0];
#pragma unroll
        for (int i = 0; i < 8; i++) kvs4[tid + 256 * i] = kv4[tid + 256 * i];
        Ksums[tid] = g_Ksum[n * HH * HD + tid];
    }
    __syncthreads();

    const int h    = tid >> 5;
    const int lane = tid & 31;

    for (int r = 0; r < MROWS; r++) {
        Qs[tid] = Qp[(size_t)(r0 + r) * DD + tid];
        __syncthreads();

        float p = Qs[h * HD + lane] * Ksums[h * HD + lane];
#pragma unroll
        for (int o = 16; o > 0; o >>= 1) p += __shfl_xor_sync(0xffffffffu, p, o);
        float z = 1.0f / (p + EPS_ATTN);

        float accv = 0.f;
#pragma unroll
        for (int d = 0; d < HD; d++) accv += Qs[h * HD + d] * KVs[h][d][lane];

        float v = accv * z * (float)SS;
        __nv_bfloat16 hh, ll; split1(v, hh, ll);
        mh[(size_t)(r0 + r) * DD + tid] = hh;
        ml[(size_t)(r0 + r) * DD + tid] = ll;
        __syncthreads();
    }
}

// ---------------- block reduce ----------------
__device__ __forceinline__ float blk_sum(float v, float* sbuf)
{
#pragma unroll
    for (int o = 16; o > 0; o >>= 1) v += __shfl_xor_sync(0xffffffffu, v, o);
    if ((threadIdx.x & 31) == 0) sbuf[threadIdx.x >> 5] = v;
    __syncthreads();
    float r = 0.f;
#pragma unroll
    for (int i = 0; i < 8; i++) r += sbuf[i];
    __syncthreads();
    return r;
}

// ---------------- LN(msg2) + concat (split bf16) ----------------
__global__ __launch_bounds__(256)
void ln_concat_kernel(const float* __restrict__ m2, const float* __restrict__ x,
                      const float* __restrict__ g, const float* __restrict__ b,
                      __nv_bfloat16* __restrict__ ch, __nv_bfloat16* __restrict__ cl)
{
    __shared__ float sbuf[8];
    const size_t row = blockIdx.x;
    const int t = threadIdx.x;
    float v = m2[row * DD + t];
    float mu = blk_sum(v, sbuf) * (1.f / DD);
    float dv = v - mu;
    float var = blk_sum(dv * dv, sbuf) * (1.f / DD);
    float y = dv * rsqrtf(var + EPS_LN) * g[t] + b[t];

    __nv_bfloat16 hh, ll;
    float xv = x[row * DD + t];
    split1(xv, hh, ll);
    ch[row * D2 + t] = hh; cl[row * D2 + t] = ll;
    split1(y, hh, ll);
    ch[row * D2 + DD + t] = hh; cl[row * D2 + DD + t] = ll;
}

// ---------------- out = x + LN(h2) ----------------
__global__ __launch_bounds__(256)
void ln_residual_kernel(const float* __restrict__ h2, const float* __restrict__ x,
                        const float* __restrict__ g, const float* __restrict__ b,
                        float* __restrict__ out)
{
    __shared__ float sbuf[8];
    const size_t row = blockIdx.x;
    const int t = threadIdx.x;
    float v = h2[row * DD + t];
    float mu = blk_sum(v, sbuf) * (1.f / DD);
    float dv = v - mu;
    float var = blk_sum(dv * dv, sbuf) * (1.f / DD);
    float y = dv * rsqrtf(var + EPS_LN) * g[t] + b[t];
    out[row * DD + t] = x[row * DD + t] + y;
}

// ---------------- host ----------------
static float* sym_f(const void* s) { void* p = nullptr; cudaGetSymbolAddress(&p, s); return (float*)p; }
static __nv_bfloat16* sym_b(const void* s) { void* p = nullptr; cudaGetSymbolAddress(&p, s); return (__nv_bfloat16*)p; }

extern "C" void kernel_launch(void* const* d_in, const int* in_sizes, int n_in,
                              void* d_out, int out_size)
{
    const float* x           = (const float*)d_in[0];
    const float* source      = (const float*)d_in[1];
    const float* x_mask      = (const float*)d_in[2];
    const float* source_mask = (const float*)d_in[3];
    const float* Wq          = (const float*)d_in[4];
    const float* Wk          = (const float*)d_in[5];
    const float* Wv          = (const float*)d_in[6];
    const float* Wm          = (const float*)d_in[7];
    const float* W1          = (const float*)d_in[8];
    const float* W2          = (const float*)d_in[9];
    const float* g1          = (const float*)d_in[10];
    const float* b1          = (const float*)d_in[11];
    const float* g2          = (const float*)d_in[12];
    const float* b2          = (const float*)d_in[13];
    float* out = (float*)d_out;

    float* pQ    = sym_f(g_Q);
    float* pK    = sym_f(g_K);
    float* pV    = sym_f(g_V);
    float* pMsg2 = sym_f(g_msg2);
    float* pH2   = sym_f(g_h2);

    __nv_bfloat16 *pxs_h = sym_b(g_xs_h), *pxs_l = sym_b(g_xs_l);
    __nv_bfloat16 *pss_h = sym_b(g_ss_h), *pss_l = sym_b(g_ss_l);
    __nv_bfloat16 *pmg_h = sym_b(g_msg_h), *pmg_l = sym_b(g_msg_l);
    __nv_bfloat16 *pct_h = sym_b(g_cat_h), *pct_l = sym_b(g_cat_l);
    __nv_bfloat16 *ph1_h = sym_b(g_h1_h), *ph1_l = sym_b(g_h1_l);
    __nv_bfloat16 *pwq_h = sym_b(g_wq_h), *pwq_l = sym_b(g_wq_l);
    __nv_bfloat16 *pwk_h = sym_b(g_wk_h), *pwk_l = sym_b(g_wk_l);
    __nv_bfloat16 *pwv_h = sym_b(g_wv_h), *pwv_l = sym_b(g_wv_l);
    __nv_bfloat16 *pwm_h = sym_b(g_wm_h), *pwm_l = sym_b(g_wm_l);
    __nv_bfloat16 *pw1_h = sym_b(g_w1_h), *pw1_l = sym_b(g_w1_l);
    __nv_bfloat16 *pw2_h = sym_b(g_w2_h), *pw2_l = sym_b(g_w2_l);

    cudaFuncSetAttribute(gemm_tc<ACT_ELU1, true,  false>, cudaFuncAttributeMaxDynamicSharedMemorySize, GSMEM);
    cudaFuncSetAttribute(gemm_tc<ACT_NONE, true,  false>, cudaFuncAttributeMaxDynamicSharedMemorySize, GSMEM);
    cudaFuncSetAttribute(gemm_tc<ACT_NONE, false, false>, cudaFuncAttributeMaxDynamicSharedMemorySize, GSMEM);
    cudaFuncSetAttribute(gemm_tc<ACT_RELU, false, true >, cudaFuncAttributeMaxDynamicSharedMemorySize, GSMEM);

    dim3 blk(256);
    dim3 gN256(DD / 128, MR / 128);   // (2, 256)
    dim3 gN512(D2 / 128, MR / 128);   // (4, 256)

    zero_kv_kernel<<<(NB * HH * HD * HD + 255) / 256, 256>>>();

    // splits
    split_kernel<<<(MR * DD / 4 + 255) / 256, 256>>>(x,      pxs_h, pxs_l, MR * DD / 4);
    split_kernel<<<(MR * DD / 4 + 255) / 256, 256>>>(source, pss_h, pss_l, MR * DD / 4);
    split_kernel<<<(DD * DD / 4 + 255) / 256, 256>>>(Wq, pwq_h, pwq_l, DD * DD / 4);
    split_kernel<<<(DD * DD / 4 + 255) / 256, 256>>>(Wk, pwk_h, pwk_l, DD * DD / 4);
    split_kernel<<<(DD * DD / 4 + 255) / 256, 256>>>(Wv, pwv_h, pwv_l, DD * DD / 4);
    split_kernel<<<(DD * DD / 4 + 255) / 256, 256>>>(Wm, pwm_h, pwm_l, DD * DD / 4);
    split_kernel<<<(D2 * D2 / 4 + 255) / 256, 256>>>(W1, pw1_h, pw1_l, D2 * D2 / 4);
    split_kernel<<<(DD * D2 / 4 + 255) / 256, 256>>>(W2, pw2_h, pw2_l, DD * D2 / 4);

    // projections
    gemm_tc<ACT_ELU1, true, false><<<gN256, blk, GSMEM>>>(pxs_h, pxs_l, pwq_h, pwq_l,
        pQ, nullptr, nullptr, DD, DD, x_mask, 1.f);
    gemm_tc<ACT_ELU1, true, false><<<gN256, blk, GSMEM>>>(pss_h, pss_l, pwk_h, pwk_l,
        pK, nullptr, nullptr, DD, DD, source_mask, 1.f);
    gemm_tc<ACT_NONE, true, false><<<gN256, blk, GSMEM>>>(pss_h, pss_l, pwv_h, pwv_l,
        pV, nullptr, nullptr, DD, DD, source_mask, 1.f / (float)SS);

    // attention core
    kv_kernel<<<dim3(NB * HH, KVSPLIT), blk>>>(pK, pV);
    msg_kernel<<<MR / MROWS, blk>>>(pQ, pmg_h, pmg_l);

    // msg2 = msg @ Wm.T
    gemm_tc<ACT_NONE, false, false><<<gN256, blk, GSMEM>>>(pmg_h, pmg_l, pwm_h, pwm_l,
        pMsg2, nullptr, nullptr, DD, DD, nullptr, 1.f);

    // cat = [x | LN(msg2)]
    ln_concat_kernel<<<MR, blk>>>(pMsg2, x, g1, b1, pct_h, pct_l);

    // h1 = relu(cat @ W1.T)  (split output)
    gemm_tc<ACT_RELU, false, true><<<gN512, blk, GSMEM>>>(pct_h, pct_l, pw1_h, pw1_l,
        nullptr, ph1_h, ph1_l, D2, D2, nullptr, 1.f);

    // h2 = h1 @ W2.T
    gemm_tc<ACT_NONE, false, false><<<gN256, blk, GSMEM>>>(ph1_h, ph1_l, pw2_h, pw2_l,
        pH2, nullptr, nullptr, DD, D2, nullptr, 1.f);

    // out = x + LN(h2)
    ln_residual_kernel<<<MR, blk>>>(pH2, x, g2, b2, out);
}

// round 4
// speedup vs baseline: 2.7788x; 1.3059x over previous
#include <cuda_runtime.h>
#include <cuda_fp16.h>
#include <math.h>
#include <stdint.h>

// ---------------- problem constants ----------------
#define NB   4
#define LQ   8192
#define SS   8192
#define DD   256
#define HH   8
#define HD   32
#define D2   512
#define MR   (NB*LQ)        // 32768
#define EPS_ATTN 1e-6f
#define EPS_LN   1e-5f

// ---------------- scratch (device globals) ----------------
__device__ float g_Q   [(size_t)MR*DD];
__device__ float g_K   [(size_t)MR*DD];
__device__ float g_V   [(size_t)MR*DD];
__device__ float g_KV  [NB*HH*HD*HD];
__device__ float g_Ksum[NB*HH*HD];
__device__ float g_msg2[(size_t)MR*DD];
__device__ float g_h2  [(size_t)MR*DD];

// fp16 split activations (A-side: hi+lo)
__device__ __half g_xs_h [(size_t)MR*DD];
__device__ __half g_xs_l [(size_t)MR*DD];
__device__ __half g_ss_h [(size_t)MR*DD];
__device__ __half g_ss_l [(size_t)MR*DD];
__device__ __half g_qz_h [(size_t)MR*DD];
__device__ __half g_qz_l [(size_t)MR*DD];
__device__ __half g_cat_h[(size_t)MR*D2];
__device__ __half g_cat_l[(size_t)MR*D2];
__device__ __half g_h1_h [(size_t)MR*D2];
__device__ __half g_h1_l [(size_t)MR*D2];

// fp16 weights (B-side: single)
__device__ __half g_wq[DD*DD];
__device__ __half g_wk[DD*DD];
__device__ __half g_wv[DD*DD];
__device__ __half g_w1[D2*D2];
__device__ __half g_w2[DD*D2];
__device__ __half g_G [NB*DD*DD];     // per-batch effective weight KV@Wm

// ---------------- low-level helpers ----------------
__device__ __forceinline__ uint32_t smem_u32(const void* p) {
    uint32_t a;
    asm("{ .reg .u64 t; cvta.to.shared.u64 t, %1; cvt.u32.u64 %0, t; }"
        : "=r"(a) : "l"(p));
    return a;
}

__device__ __forceinline__ uint32_t sw128(uint32_t off) {
    return off ^ ((off >> 3) & 0x70);
}

#define CPASYNC16(sa, ga) \
    asm volatile("cp.async.cg.shared.global [%0], [%1], 16;" \
                 :: "r"(sa), "l"(ga) : "memory")
#define CPCOMMIT() asm volatile("cp.async.commit_group;" ::: "memory")
#define CPWAIT0()  asm volatile("cp.async.wait_group 0;" ::: "memory")
#define CPWAIT1()  asm volatile("cp.async.wait_group 1;" ::: "memory")

#define LDSM4(r, addr) \
    asm volatile("ldmatrix.sync.aligned.m8n8.x4.shared.b16 {%0,%1,%2,%3}, [%4];" \
        : "=r"((r)[0]), "=r"((r)[1]), "=r"((r)[2]), "=r"((r)[3]) : "r"(addr))

__device__ __forceinline__ void mma_f16(float* c, const uint32_t* a,
                                        uint32_t b0, uint32_t b1) {
    asm volatile(
        "mma.sync.aligned.m16n8k16.row.col.f32.f16.f16.f32 "
        "{%0,%1,%2,%3}, {%4,%5,%6,%7}, {%8,%9}, {%0,%1,%2,%3};"
        : "+f"(c[0]), "+f"(c[1]), "+f"(c[2]), "+f"(c[3])
        : "r"(a[0]), "r"(a[1]), "r"(a[2]), "r"(a[3]), "r"(b0), "r"(b1));
}

// ---------------- split helper (fp32 -> fp16 hi + lo) ----------------
__device__ __forceinline__ void split1(float v, __half& h, __half& l) {
    h = __float2half_rn(v);
    l = __float2half_rn(v - __half2float(h));
}

// ---------------- tensor-core GEMM (HMMA mma.sync, fp16 2-term) ----------
// C[m,n] = act(sum_k A[m,k]*B[n,k]) * mask[m] * scale
// A = Ah + Al (fp16 pair), B = Bh (fp16). Terms: Ah*Bh + Al*Bh.
// CTA tile 128x128, 8 warps 4(M)x2(N), warp tile 32x64.
// K chunks of 64 halves, SW128 swizzle, double-buffered cp.async. 2 CTAs/SM.
#define T_BYTES   16384u           // 128 rows x 128B
#define STG_BYTES (3u*T_BYTES)     // Ah,Al,Bh = 48KB
#define GSMEM     (2u*STG_BYTES)   // 96KB

enum { ACT_NONE = 0, ACT_ELU1 = 1, ACT_RELU = 2 };

template<int ACT, bool HASMASK, bool SPLITOUT, bool BATCHB>
__global__ __launch_bounds__(256, 2)
void gemm_tc(const __half* __restrict__ Ahp, const __half* __restrict__ Alp,
             const __half* __restrict__ Bhp,
             float* __restrict__ C, __half* __restrict__ Ch, __half* __restrict__ Cl,
             int Nc, int K, const float* __restrict__ mask, float scale)
{
    extern __shared__ char smem[];
    const uint32_t sb = smem_u32(smem);
    const int tid  = threadIdx.x;
    const int lane = tid & 31;
    const int wid  = tid >> 5;
    const int wm   = wid >> 1;
    const int wn   = wid & 1;
    const int bm   = blockIdx.y * 128;
    const int bn   = blockIdx.x * 128;

    if (BATCHB) Bhp += (size_t)(bm / LQ) * DD * DD;   // per-batch B matrix

    float acc[2][8][4];
#pragma unroll
    for (int i = 0; i < 2; i++)
#pragma unroll
        for (int j = 0; j < 8; j++)
#pragma unroll
            for (int v = 0; v < 4; v++) acc[i][j][v] = 0.f;

    const int NCC = K >> 6;

    auto load_chunk = [&](int st, int c) {
        const int k0 = c * 64;
        const uint32_t stb = sb + st * STG_BYTES;
#pragma unroll
        for (int i = 0; i < 4; i++) {
            int ci  = tid + 256 * i;      // 0..1023
            int row = ci >> 3;
            int c16 = ci & 7;
            uint32_t so = sw128((uint32_t)(row * 128 + c16 * 16));
            size_t ga = (size_t)(bm + row) * K + k0 + c16 * 8;
            size_t gb = (size_t)(bn + row) * K + k0 + c16 * 8;
            CPASYNC16(stb + 0 * T_BYTES + so, Ahp + ga);
            CPASYNC16(stb + 1 * T_BYTES + so, Alp + ga);
            CPASYNC16(stb + 2 * T_BYTES + so, Bhp + gb);
        }
        CPCOMMIT();
    };

    load_chunk(0, 0);

    const int a_row = wm * 32 + (lane & 15);
    const int a_kb  = (lane >> 4) * 16;
    const int b_row = wn * 64 + (lane & 7) + ((lane >> 4) << 3);
    const int b_kb  = ((lane >> 3) & 1) * 16;

    for (int c = 0; c < NCC; c++) {
        if (c + 1 < NCC) { load_chunk((c + 1) & 1, c + 1); CPWAIT1(); }
        else             { CPWAIT0(); }
        __syncthreads();

        const uint32_t stb = sb + (c & 1) * STG_BYTES;
#pragma unroll
        for (int ks = 0; ks < 4; ks++) {
            uint32_t ah[2][4], al[2][4], bh[4][4];
#pragma unroll
            for (int mt = 0; mt < 2; mt++) {
                uint32_t ra = sw128((uint32_t)((a_row + mt * 16) * 128 + ks * 32 + a_kb));
                LDSM4(ah[mt], stb + 0 * T_BYTES + ra);
                LDSM4(al[mt], stb + 1 * T_BYTES + ra);
            }
#pragma unroll
            for (int ntp = 0; ntp < 4; ntp++) {
                uint32_t rb = sw128((uint32_t)((b_row + ntp * 16) * 128 + ks * 32 + b_kb));
                LDSM4(bh[ntp], stb + 2 * T_BYTES + rb);
            }
#pragma unroll
            for (int mt = 0; mt < 2; mt++)
#pragma unroll
                for (int nt = 0; nt < 8; nt++) {
                    const int ntp = nt >> 1, o = (nt & 1) * 2;
                    mma_f16(acc[mt][nt], ah[mt], bh[ntp][o], bh[ntp][o + 1]);
                    mma_f16(acc[mt][nt], al[mt], bh[ntp][o], bh[ntp][o + 1]);
                }
        }
        __syncthreads();
    }

    // ---------------- epilogue ----------------
    float* sf = (float*)smem;   // 128 x 132 fp32 = 67.5KB (fits in 96KB)
    {
        float mk[2][2];
#pragma unroll
        for (int mt = 0; mt < 2; mt++)
#pragma unroll
            for (int hh = 0; hh < 2; hh++) {
                int m = bm + wm * 32 + mt * 16 + (lane >> 2) + hh * 8;
                mk[mt][hh] = (HASMASK ? mask[m] : 1.f) * scale;
            }
#pragma unroll
        for (int mt = 0; mt < 2; mt++)
#pragma unroll
            for (int nt = 0; nt < 8; nt++) {
                int r0 = wm * 32 + mt * 16 + (lane >> 2);
                int c0 = wn * 64 + nt * 8 + (lane & 3) * 2;
#pragma unroll
                for (int v = 0; v < 4; v++) {
                    int row = r0 + (v >> 1) * 8;
                    int col = c0 + (v & 1);
                    float x = acc[mt][nt][v];
                    if (ACT == ACT_ELU1)      x = (x > 0.f) ? (x + 1.f) : expf(x);
                    else if (ACT == ACT_RELU) x = fmaxf(x, 0.f);
                    sf[row * 132 + col] = x * mk[mt][v >> 1];
                }
            }
    }
    __syncthreads();

#pragma unroll 8
    for (int i = 0; i < 64; i++) {
        int e   = tid + 256 * i;
        int row = e >> 7;
        int col = e & 127;
        float v = sf[row * 132 + col];
        size_t gi = (size_t)(bm + row) * Nc + bn + col;
        if (SPLITOUT) {
            __half h, l; split1(v, h, l);
            Ch[gi] = h; Cl[gi] = l;
        } else {
            C[gi] = v;
        }
    }
}

// ---------------- fp32 -> (hi,lo) fp16 split ----------------
__global__ __launch_bounds__(256)
void split_kernel(const float* __restrict__ s, __half* __restrict__ hi,
                  __half* __restrict__ lo, int n4)
{
    int i = blockIdx.x * 256 + threadIdx.x;
    if (i >= n4) return;
    float4 v = *(const float4*)(s + (size_t)i * 4);
    __half h[4], l[4];
    split1(v.x, h[0], l[0]); split1(v.y, h[1], l[1]);
    split1(v.z, h[2], l[2]); split1(v.w, h[3], l[3]);
    __half2* hp = (__half2*)(hi + (size_t)i * 4);
    __half2* lp = (__half2*)(lo + (size_t)i * 4);
    hp[0] = __halves2half2(h[0], h[1]); hp[1] = __halves2half2(h[2], h[3]);
    lp[0] = __halves2half2(l[0], l[1]); lp[1] = __halves2half2(l[2], l[3]);
}

// ---------------- fp32 -> fp16 convert (weights) ----------------
__global__ __launch_bounds__(256)
void tohalf_kernel(const float* __restrict__ s, __half* __restrict__ d, int n4)
{
    int i = blockIdx.x * 256 + threadIdx.x;
    if (i >= n4) return;
    float4 v = *(const float4*)(s + (size_t)i * 4);
    __half2* dp = (__half2*)(d + (size_t)i * 4);
    dp[0] = __halves2half2(__float2half_rn(v.x), __float2half_rn(v.y));
    dp[1] = __halves2half2(__float2half_rn(v.z), __float2half_rn(v.w));
}

// ---------------- zero KV/Ksum ----------------
__global__ void zero_kv_kernel()
{
    int i = blockIdx.x * blockDim.x + threadIdx.x;
    if (i < NB * HH * HD * HD) g_KV[i] = 0.f;
    if (i < NB * HH * HD)      g_Ksum[i] = 0.f;
}

// ---------------- KV = sum_s K (x) v ; Ksum = sum_s K ----------------
#define KVSPLIT 64
#define SCHUNK  (SS / KVSPLIT)   // 128

__global__ __launch_bounds__(256)
void kv_kernel(const float* __restrict__ Kp, const float* __restrict__ Vp)
{
    __shared__ float Ks[SCHUNK][HD];
    __shared__ float Vs[SCHUNK][HD];

    const int nh = blockIdx.x;
    const int n  = nh >> 3;
    const int h  = nh & 7;
    const int s0 = blockIdx.y * SCHUNK;
    const int tid = threadIdx.x;

#pragma unroll
    for (int i = 0; i < 4; i++) {
        int idx = tid + 256 * i;
        int row = idx >> 3;
        int c   = (idx & 7) * 4;
        size_t g = ((size_t)(n * SS + s0 + row)) * DD + h * HD + c;
        *(float4*)&Ks[row][c] = *(const float4*)(Kp + g);
        *(float4*)&Vs[row][c] = *(const float4*)(Vp + g);
    }
    __syncthreads();

    const int d  = tid >> 3;
    const int e0 = (tid & 7) * 4;
    float a0 = 0.f, a1 = 0.f, a2 = 0.f, a3 = 0.f, ks = 0.f;
    for (int s = 0; s < SCHUNK; s++) {
        float kd = Ks[s][d];
        float4 v = *(const float4*)&Vs[s][e0];
        a0 += kd * v.x; a1 += kd * v.y; a2 += kd * v.z; a3 += kd * v.w;
        ks += kd;
    }
    float* KV = g_KV + (size_t)nh * HD * HD + d * HD + e0;
    atomicAdd(KV + 0, a0); atomicAdd(KV + 1, a1);
    atomicAdd(KV + 2, a2); atomicAdd(KV + 3, a3);
    if ((tid & 7) == 0) atomicAdd(g_Ksum + nh * HD + d, ks);
}

// ---------------- G[n][j][h*32+d] = sum_e KV[n,h,d,e] * Wm[j, h*32+e] ------
__global__ __launch_bounds__(256)
void g_kernel(const float* __restrict__ Wm)
{
    __shared__ float KVs[HD][HD];
    const int h = blockIdx.x;
    const int n = blockIdx.y;
    const int tid = threadIdx.x;

    {
        const float4* src = (const float4*)(g_KV + ((size_t)(n * HH + h)) * HD * HD);
        ((float4*)&KVs[0][0])[tid] = src[tid];   // 256 x 16B = 4KB
    }
    __syncthreads();

    const int j = tid;
    float w[HD];
#pragma unroll
    for (int e = 0; e < HD; e++) w[e] = Wm[(size_t)j * DD + h * HD + e];

    __half* Gp = (__half*)g_G + ((size_t)n * DD + j) * DD + h * HD;
#pragma unroll
    for (int d = 0; d < HD; d++) {
        float acc = 0.f;
#pragma unroll
        for (int e = 0; e < HD; e++) acc += KVs[d][e] * w[e];
        Gp[d] = __float2half_rn(acc);
    }
}

// ---------------- Qz[l,k] = Q[l,k] * Z[l,h] * SS (split fp16) ---------------
__global__ __launch_bounds__(256)
void qz_kernel(const float* __restrict__ Qp,
               __half* __restrict__ qh, __half* __restrict__ ql)
{
    const size_t row = blockIdx.x;
    const int n   = (int)(row / LQ);
    const int t   = threadIdx.x;

    float q  = Qp[row * DD + t];
    float ks = g_Ksum[n * DD + t];
    float p  = q * ks;
#pragma unroll
    for (int o = 16; o > 0; o >>= 1) p += __shfl_xor_sync(0xffffffffu, p, o);
    float z = 1.0f / (p + EPS_ATTN);

    float v = q * z * (float)SS;
    __half h, l; split1(v, h, l);
    qh[row * DD + t] = h;
    ql[row * DD + t] = l;
}

// ---------------- block reduce ----------------
__device__ __forceinline__ float blk_sum(float v, float* sbuf)
{
#pragma unroll
    for (int o = 16; o > 0; o >>= 1) v += __shfl_xor_sync(0xffffffffu, v, o);
    if ((threadIdx.x & 31) == 0) sbuf[threadIdx.x >> 5] = v;
    __syncthreads();
    float r = 0.f;
#pragma unroll
    for (int i = 0; i < 8; i++) r += sbuf[i];
    __syncthreads();
    return r;
}

// ---------------- LN(msg2) + concat (split fp16) ----------------
__global__ __launch_bounds__(256)
void ln_concat_kernel(const float* __restrict__ m2, const float* __restrict__ x,
                      const float* __restrict__ g, const float* __restrict__ b,
                      __half* __restrict__ ch, __half* __restrict__ cl)
{
    __shared__ float sbuf[8];
    const size_t row = blockIdx.x;
    const int t = threadIdx.x;
    float v = m2[row * DD + t];
    float mu = blk_sum(v, sbuf) * (1.f / DD);
    float dv = v - mu;
    float var = blk_sum(dv * dv, sbuf) * (1.f / DD);
    float y = dv * rsqrtf(var + EPS_LN) * g[t] + b[t];

    __half hh, ll;
    split1(x[row * DD + t], hh, ll);
    ch[row * D2 + t] = hh; cl[row * D2 + t] = ll;
    split1(y, hh, ll);
    ch[row * D2 + DD + t] = hh; cl[row * D2 + DD + t] = ll;
}

// ---------------- out = x + LN(h2) ----------------
__global__ __launch_bounds__(256)
void ln_residual_kernel(const float* __restrict__ h2, const float* __restrict__ x,
                        const float* __restrict__ g, const float* __restrict__ b,
                        float* __restrict__ out)
{
    __shared__ float sbuf[8];
    const size_t row = blockIdx.x;
    const int t = threadIdx.x;
    float v = h2[row * DD + t];
    float mu = blk_sum(v, sbuf) * (1.f / DD);
    float dv = v - mu;
    float var = blk_sum(dv * dv, sbuf) * (1.f / DD);
    float y = dv * rsqrtf(var + EPS_LN) * g[t] + b[t];
    out[row * DD + t] = x[row * DD + t] + y;
}

// ---------------- host ----------------
static float* sym_f(const void* s) { void* p = nullptr; cudaGetSymbolAddress(&p, s); return (float*)p; }
static __half* sym_h(const void* s) { void* p = nullptr; cudaGetSymbolAddress(&p, s); return (__half*)p; }

extern "C" void kernel_launch(void* const* d_in, const int* in_sizes, int n_in,
                              void* d_out, int out_size)
{
    const float* x           = (const float*)d_in[0];
    const float* source      = (const float*)d_in[1];
    const float* x_mask      = (const float*)d_in[2];
    const float* source_mask = (const float*)d_in[3];
    const float* Wq          = (const float*)d_in[4];
    const float* Wk          = (const float*)d_in[5];
    const float* Wv          = (const float*)d_in[6];
    const float* Wm          = (const float*)d_in[7];
    const float* W1          = (const float*)d_in[8];
    const float* W2          = (const float*)d_in[9];
    const float* g1          = (const float*)d_in[10];
    const float* b1          = (const float*)d_in[11];
    const float* g2          = (const float*)d_in[12];
    const float* b2          = (const float*)d_in[13];
    float* out = (float*)d_out;

    float* pQ    = sym_f(g_Q);
    float* pK    = sym_f(g_K);
    float* pV    = sym_f(g_V);
    float* pMsg2 = sym_f(g_msg2);
    float* pH2   = sym_f(g_h2);

    __half *pxs_h = sym_h(g_xs_h), *pxs_l = sym_h(g_xs_l);
    __half *pss_h = sym_h(g_ss_h), *pss_l = sym_h(g_ss_l);
    __half *pqz_h = sym_h(g_qz_h), *pqz_l = sym_h(g_qz_l);
    __half *pct_h = sym_h(g_cat_h), *pct_l = sym_h(g_cat_l);
    __half *ph1_h = sym_h(g_h1_h), *ph1_l = sym_h(g_h1_l);
    __half *pwq = sym_h(g_wq), *pwk = sym_h(g_wk), *pwv = sym_h(g_wv);
    __half *pw1 = sym_h(g_w1), *pw2 = sym_h(g_w2), *pG = sym_h(g_G);

    cudaFuncSetAttribute(gemm_tc<ACT_ELU1, true,  false, false>, cudaFuncAttributeMaxDynamicSharedMemorySize, GSMEM);
    cudaFuncSetAttribute(gemm_tc<ACT_NONE, true,  false, false>, cudaFuncAttributeMaxDynamicSharedMemorySize, GSMEM);
    cudaFuncSetAttribute(gemm_tc<ACT_NONE, false, false, true >, cudaFuncAttributeMaxDynamicSharedMemorySize, GSMEM);
    cudaFuncSetAttribute(gemm_tc<ACT_RELU, false, true,  false>, cudaFuncAttributeMaxDynamicSharedMemorySize, GSMEM);
    cudaFuncSetAttribute(gemm_tc<ACT_NONE, false, false, false>, cudaFuncAttributeMaxDynamicSharedMemorySize, GSMEM);

    dim3 blk(256);
    dim3 gN256(DD / 128, MR / 128);   // (2, 256)
    dim3 gN512(D2 / 128, MR / 128);   // (4, 256)

    zero_kv_kernel<<<(NB * HH * HD * HD + 255) / 256, 256>>>();

    // splits / converts
    split_kernel<<<(MR * DD / 4 + 255) / 256, 256>>>(x,      pxs_h, pxs_l, MR * DD / 4);
    split_kernel<<<(MR * DD / 4 + 255) / 256, 256>>>(source, pss_h, pss_l, MR * DD / 4);
    tohalf_kernel<<<(DD * DD / 4 + 255) / 256, 256>>>(Wq, pwq, DD * DD / 4);
    tohalf_kernel<<<(DD * DD / 4 + 255) / 256, 256>>>(Wk, pwk, DD * DD / 4);
    tohalf_kernel<<<(DD * DD / 4 + 255) / 256, 256>>>(Wv, pwv, DD * DD / 4);
    tohalf_kernel<<<(D2 * D2 / 4 + 255) / 256, 256>>>(W1, pw1, D2 * D2 / 4);
    tohalf_kernel<<<(DD * D2 / 4 + 255) / 256, 256>>>(W2, pw2, DD * D2 / 4);

    // projections
    gemm_tc<ACT_ELU1, true, false, false><<<gN256, blk, GSMEM>>>(pxs_h, pxs_l, pwq,
        pQ, nullptr, nullptr, DD, DD, x_mask, 1.f);
    gemm_tc<ACT_ELU1, true, false, false><<<gN256, blk, GSMEM>>>(pss_h, pss_l, pwk,
        pK, nullptr, nullptr, DD, DD, source_mask, 1.f);
    gemm_tc<ACT_NONE, true, false, false><<<gN256, blk, GSMEM>>>(pss_h, pss_l, pwv,
        pV, nullptr, nullptr, DD, DD, source_mask, 1.f / (float)SS);

    // attention core: KV/Ksum, then fold Wm into per-batch G, scale Q by Z
    kv_kernel<<<dim3(NB * HH, KVSPLIT), blk>>>(pK, pV);
    g_kernel<<<dim3(HH, NB), blk>>>(Wm);
    qz_kernel<<<MR, blk>>>(pQ, pqz_h, pqz_l);

    // msg2 = Qz @ G[n].T  (batch-indexed B)
    gemm_tc<ACT_NONE, false, false, true><<<gN256, blk, GSMEM>>>(pqz_h, pqz_l, pG,
        pMsg2, nullptr, nullptr, DD, DD, nullptr, 1.f);

    // cat = [x | LN(msg2)]
    ln_concat_kernel<<<MR, blk>>>(pMsg2, x, g1, b1, pct_h, pct_l);

    // h1 = relu(cat @ W1.T)  (split fp16 out)
    gemm_tc<ACT_RELU, false, true, false><<<gN512, blk, GSMEM>>>(pct_h, pct_l, pw1,
        nullptr, ph1_h, ph1_l, D2, D2, nullptr, 1.f);

    // h2 = h1 @ W2.T
    gemm_tc<ACT_NONE, false, false, false><<<gN256, blk, GSMEM>>>(ph1_h, ph1_l, pw2,
        pH2, nullptr, nullptr, DD, D2, nullptr, 1.f);

    // out = x + LN(h2)
    ln_residual_kernel<<<MR, blk>>>(pH2, x, g2, b2, out);
}

// round 5
// speedup vs baseline: 3.0304x; 1.0906x over previous
#include <cuda_runtime.h>
#include <cuda_fp16.h>
#include <math.h>
#include <stdint.h>

// ---------------- problem constants ----------------
#define NB   4
#define LQ   8192
#define SS   8192
#define DD   256
#define HH   8
#define HD   32
#define D2   512
#define MR   (NB*LQ)        // 32768
#define EPS_ATTN 1e-6f
#define EPS_LN   1e-5f

// ---------------- scratch (device globals) ----------------
__device__ float g_K   [(size_t)MR*DD];
__device__ float g_V   [(size_t)MR*DD];
__device__ float g_KV  [NB*HH*HD*HD];
__device__ float g_Ksum[NB*HH*HD];

__device__ __half g_ss_h [(size_t)MR*DD];
__device__ __half g_ss_l [(size_t)MR*DD];
__device__ __half g_qz_h [(size_t)MR*DD];
__device__ __half g_qz_l [(size_t)MR*DD];
__device__ __half g_cat_h[(size_t)MR*D2];
__device__ __half g_cat_l[(size_t)MR*D2];
__device__ __half g_h1_h [(size_t)MR*D2];
__device__ __half g_h1_l [(size_t)MR*D2];

__device__ __half g_wq[DD*DD];
__device__ __half g_wk[DD*DD];
__device__ __half g_wv[DD*DD];
__device__ __half g_w1[D2*D2];
__device__ __half g_w2[DD*D2];
__device__ __half g_G [NB*DD*DD];     // per-batch effective weight KV@Wm

// ---------------- low-level helpers ----------------
__device__ __forceinline__ uint32_t smem_u32(const void* p) {
    uint32_t a;
    asm("{ .reg .u64 t; cvta.to.shared.u64 t, %1; cvt.u32.u64 %0, t; }"
        : "=r"(a) : "l"(p));
    return a;
}

__device__ __forceinline__ uint32_t sw128(uint32_t off) {
    return off ^ ((off >> 3) & 0x70);
}

#define CPASYNC16(sa, ga) \
    asm volatile("cp.async.cg.shared.global [%0], [%1], 16;" \
                 :: "r"(sa), "l"(ga) : "memory")
#define CPCOMMIT() asm volatile("cp.async.commit_group;" ::: "memory")
#define CPWAIT0()  asm volatile("cp.async.wait_group 0;" ::: "memory")
#define CPWAIT1()  asm volatile("cp.async.wait_group 1;" ::: "memory")

#define LDSM4(r, addr) \
    asm volatile("ldmatrix.sync.aligned.m8n8.x4.shared.b16 {%0,%1,%2,%3}, [%4];" \
        : "=r"((r)[0]), "=r"((r)[1]), "=r"((r)[2]), "=r"((r)[3]) : "r"(addr))

__device__ __forceinline__ void mma_f16(float* c, const uint32_t* a,
                                        uint32_t b0, uint32_t b1) {
    asm volatile(
        "mma.sync.aligned.m16n8k16.row.col.f32.f16.f16.f32 "
        "{%0,%1,%2,%3}, {%4,%5,%6,%7}, {%8,%9}, {%0,%1,%2,%3};"
        : "+f"(c[0]), "+f"(c[1]), "+f"(c[2]), "+f"(c[3])
        : "r"(a[0]), "r"(a[1]), "r"(a[2]), "r"(a[3]), "r"(b0), "r"(b1));
}

__device__ __forceinline__ void split1(float v, __half& h, __half& l) {
    h = __float2half_rn(v);
    l = __float2half_rn(v - __half2float(h));
}

__device__ __forceinline__ float warp_sum(float v) {
#pragma unroll
    for (int o = 16; o > 0; o >>= 1) v += __shfl_xor_sync(0xffffffffu, v, o);
    return v;
}

enum { ACT_NONE = 0, ACT_ELU1 = 1, ACT_RELU = 2 };
enum { EPI_F32 = 0, EPI_SPLIT = 1, EPI_QZ = 2 };
enum { EPI_LNCAT = 0, EPI_LNRES = 1 };

#define GSMEM 98304u

// ================= GEMM 128x128 tile =================
// C[m,n] = act(sum_k A[m,k]*B[n,k]) * mask[m] * scale
// A = Ah+Al (fp16 pair, row stride lda), B fp16 (row stride K).
// 8 warps 4(M)x2(N). K chunks of 64, SW128, double-buffered. 2 CTAs/SM.
#define T_BYTES   16384u
#define STG_BYTES (3u*T_BYTES)

template<int ACT, bool HASMASK, int EPI>
__global__ __launch_bounds__(256, 2)
void gemm128(const __half* __restrict__ Ahp, const __half* __restrict__ Alp,
             const __half* __restrict__ Bhp, int lda,
             float* __restrict__ C, __half* __restrict__ Ch, __half* __restrict__ Cl,
             int Nc, int K, const float* __restrict__ mask, float scale,
             const float* __restrict__ Ksum)
{
    extern __shared__ char smem[];
    const uint32_t sb = smem_u32(smem);
    const int tid  = threadIdx.x;
    const int lane = tid & 31;
    const int wid  = tid >> 5;
    const int wm   = wid >> 1;
    const int wn   = wid & 1;
    const int bm   = blockIdx.y * 128;
    const int bn   = blockIdx.x * 128;

    float acc[2][8][4];
#pragma unroll
    for (int i = 0; i < 2; i++)
#pragma unroll
        for (int j = 0; j < 8; j++)
#pragma unroll
            for (int v = 0; v < 4; v++) acc[i][j][v] = 0.f;

    const int NCC = K >> 6;

    auto load_chunk = [&](int st, int c) {
        const int k0 = c * 64;
        const uint32_t stb = sb + st * STG_BYTES;
#pragma unroll
        for (int i = 0; i < 4; i++) {
            int ci  = tid + 256 * i;
            int row = ci >> 3;
            int c16 = ci & 7;
            uint32_t so = sw128((uint32_t)(row * 128 + c16 * 16));
            size_t ga = (size_t)(bm + row) * lda + k0 + c16 * 8;
            size_t gb = (size_t)(bn + row) * K + k0 + c16 * 8;
            CPASYNC16(stb + 0 * T_BYTES + so, Ahp + ga);
            CPASYNC16(stb + 1 * T_BYTES + so, Alp + ga);
            CPASYNC16(stb + 2 * T_BYTES + so, Bhp + gb);
        }
        CPCOMMIT();
    };

    load_chunk(0, 0);

    const int a_row = wm * 32 + (lane & 15);
    const int a_kb  = (lane >> 4) * 16;
    const int b_row = wn * 64 + (lane & 7) + ((lane >> 4) << 3);
    const int b_kb  = ((lane >> 3) & 1) * 16;

    for (int c = 0; c < NCC; c++) {
        if (c + 1 < NCC) { load_chunk((c + 1) & 1, c + 1); CPWAIT1(); }
        else             { CPWAIT0(); }
        __syncthreads();

        const uint32_t stb = sb + (c & 1) * STG_BYTES;
#pragma unroll
        for (int ks = 0; ks < 4; ks++) {
            uint32_t ah[2][4], al[2][4], bh[4][4];
#pragma unroll
            for (int mt = 0; mt < 2; mt++) {
                uint32_t ra = sw128((uint32_t)((a_row + mt * 16) * 128 + ks * 32 + a_kb));
                LDSM4(ah[mt], stb + 0 * T_BYTES + ra);
                LDSM4(al[mt], stb + 1 * T_BYTES + ra);
            }
#pragma unroll
            for (int ntp = 0; ntp < 4; ntp++) {
                uint32_t rb = sw128((uint32_t)((b_row + ntp * 16) * 128 + ks * 32 + b_kb));
                LDSM4(bh[ntp], stb + 2 * T_BYTES + rb);
            }
#pragma unroll
            for (int mt = 0; mt < 2; mt++)
#pragma unroll
                for (int nt = 0; nt < 8; nt++) {
                    const int ntp = nt >> 1, o = (nt & 1) * 2;
                    mma_f16(acc[mt][nt], ah[mt], bh[ntp][o], bh[ntp][o + 1]);
                    mma_f16(acc[mt][nt], al[mt], bh[ntp][o], bh[ntp][o + 1]);
                }
        }
        __syncthreads();
    }

    // ---------------- epilogue ----------------
    float* sf = (float*)smem;   // 128 x 132 fp32 = 67.6KB
    {
        float mk[2][2];
#pragma unroll
        for (int mt = 0; mt < 2; mt++)
#pragma unroll
            for (int hh = 0; hh < 2; hh++) {
                int m = bm + wm * 32 + mt * 16 + (lane >> 2) + hh * 8;
                mk[mt][hh] = (HASMASK ? mask[m] : 1.f) * scale;
            }
#pragma unroll
        for (int mt = 0; mt < 2; mt++)
#pragma unroll
            for (int nt = 0; nt < 8; nt++) {
                int r0 = wm * 32 + mt * 16 + (lane >> 2);
                int c0 = wn * 64 + nt * 8 + (lane & 3) * 2;
#pragma unroll
                for (int v = 0; v < 4; v++) {
                    int row = r0 + (v >> 1) * 8;
                    int col = c0 + (v & 1);
                    float x = acc[mt][nt][v];
                    if (ACT == ACT_ELU1)      x = (x > 0.f) ? (x + 1.f) : expf(x);
                    else if (ACT == ACT_RELU) x = fmaxf(x, 0.f);
                    sf[row * 132 + col] = x * mk[mt][v >> 1];
                }
            }
    }
    __syncthreads();

    if (EPI == EPI_QZ) {
        // Z[l,h] = 1/(dot(Q_row_head, Ksum_head) + eps); out = Q*Z*SS (split)
        float* ks_s = sf + 128 * 132;       // 128 floats
        float* zb   = ks_s + 128;           // 128 x 4
        const int n = bm / LQ;
        if (tid < 128) ks_s[tid] = Ksum[n * DD + bn + tid];
        __syncthreads();
#pragma unroll
        for (int u = tid; u < 512; u += 256) {
            int row = u >> 2, hl = u & 3;
            float s = 0.f;
#pragma unroll
            for (int d = 0; d < 32; d++)
                s += sf[row * 132 + hl * 32 + d] * ks_s[hl * 32 + d];
            zb[row * 4 + hl] = 1.0f / (s + EPS_ATTN);
        }
        __syncthreads();
#pragma unroll 8
        for (int i = 0; i < 64; i++) {
            int e   = tid + 256 * i;
            int row = e >> 7;
            int col = e & 127;
            float v = sf[row * 132 + col] * zb[row * 4 + (col >> 5)] * (float)SS;
            size_t gi = (size_t)(bm + row) * DD + bn + col;
            __half h, l; split1(v, h, l);
            Ch[gi] = h; Cl[gi] = l;
        }
    } else {
#pragma unroll 8
        for (int i = 0; i < 64; i++) {
            int e   = tid + 256 * i;
            int row = e >> 7;
            int col = e & 127;
            float v = sf[row * 132 + col];
            size_t gi = (size_t)(bm + row) * Nc + bn + col;
            if (EPI == EPI_SPLIT) {
                __half h, l; split1(v, h, l);
                Ch[gi] = h; Cl[gi] = l;
            } else {
                C[gi] = v;
            }
        }
    }
}

// ================= GEMM 64x256 tile (full-row, LN epilogue) =================
// 8 warps 2(M)x4(N), warp tile 32x64. Nc = 256 fixed (one tile spans the row).
#define A_REG  8192u
#define B_REG  16384u
#define STG256 49152u

template<int EPI, bool BATCHB>
__global__ __launch_bounds__(256, 2)
void gemm256(const __half* __restrict__ Ahp, const __half* __restrict__ Alp,
             const __half* __restrict__ Bhp, int lda, int K,
             const float* __restrict__ gv_, const float* __restrict__ bv_,
             const float* __restrict__ xres,
             float* __restrict__ outf, __half* __restrict__ Ch, __half* __restrict__ Cl)
{
    extern __shared__ char smem[];
    const uint32_t sb = smem_u32(smem);
    const int tid  = threadIdx.x;
    const int lane = tid & 31;
    const int wid  = tid >> 5;
    const int wm   = wid >> 2;     // 0..1
    const int wn   = wid & 3;      // 0..3
    const int bm   = blockIdx.x * 64;

    if (BATCHB) Bhp += (size_t)(bm / LQ) * DD * DD;

    float acc[2][8][4];
#pragma unroll
    for (int i = 0; i < 2; i++)
#pragma unroll
        for (int j = 0; j < 8; j++)
#pragma unroll
            for (int v = 0; v < 4; v++) acc[i][j][v] = 0.f;

    const int NCC = K >> 6;

    auto load_chunk = [&](int st, int c) {
        const int k0 = c * 64;
        const uint32_t stb = sb + st * STG256;
#pragma unroll
        for (int i = 0; i < 12; i++) {
            int ci = tid + 256 * i;   // 0..3071
            if (i < 2) {              // Ah: ci 0..511
                int row = ci >> 3, c16 = ci & 7;
                uint32_t so = sw128((uint32_t)(row * 128 + c16 * 16));
                CPASYNC16(stb + so, Ahp + (size_t)(bm + row) * lda + k0 + c16 * 8);
            } else if (i < 4) {       // Al: idx 0..511
                int idx = ci - 512;
                int row = idx >> 3, c16 = idx & 7;
                uint32_t so = sw128((uint32_t)(row * 128 + c16 * 16));
                CPASYNC16(stb + A_REG + so, Alp + (size_t)(bm + row) * lda + k0 + c16 * 8);
            } else {                  // B: idx 0..2047
                int idx = ci - 1024;
                int row = idx >> 3, c16 = idx & 7;
                uint32_t so = sw128((uint32_t)(row * 128 + c16 * 16));
                CPASYNC16(stb + B_REG + so, Bhp + (size_t)row * K + k0 + c16 * 8);
            }
        }
        CPCOMMIT();
    };

    load_chunk(0, 0);

    const int a_row = wm * 32 + (lane & 15);
    const int a_kb  = (lane >> 4) * 16;
    const int b_row = wn * 64 + (lane & 7) + ((lane >> 4) << 3);
    const int b_kb  = ((lane >> 3) & 1) * 16;

    for (int c = 0; c < NCC; c++) {
        if (c + 1 < NCC) { load_chunk((c + 1) & 1, c + 1); CPWAIT1(); }
        else             { CPWAIT0(); }
        __syncthreads();

        const uint32_t stb = sb + (c & 1) * STG256;
#pragma unroll
        for (int ks = 0; ks < 4; ks++) {
            uint32_t ah[2][4], al[2][4], bh[4][4];
#pragma unroll
            for (int mt = 0; mt < 2; mt++) {
                uint32_t ra = sw128((uint32_t)((a_row + mt * 16) * 128 + ks * 32 + a_kb));
                LDSM4(ah[mt], stb + ra);
                LDSM4(al[mt], stb + A_REG + ra);
            }
#pragma unroll
            for (int ntp = 0; ntp < 4; ntp++) {
                uint32_t rb = sw128((uint32_t)((b_row + ntp * 16) * 128 + ks * 32 + b_kb));
                LDSM4(bh[ntp], stb + B_REG + rb);
            }
#pragma unroll
            for (int mt = 0; mt < 2; mt++)
#pragma unroll
                for (int nt = 0; nt < 8; nt++) {
                    const int ntp = nt >> 1, o = (nt & 1) * 2;
                    mma_f16(acc[mt][nt], ah[mt], bh[ntp][o], bh[ntp][o + 1]);
                    mma_f16(acc[mt][nt], al[mt], bh[ntp][o], bh[ntp][o + 1]);
                }
        }
        __syncthreads();
    }

    // ---------------- epilogue: stage + row LN ----------------
    float* sf = (float*)smem;   // 64 x 260 fp32 = 66.6KB
#pragma unroll
    for (int mt = 0; mt < 2; mt++)
#pragma unroll
        for (int nt = 0; nt < 8; nt++) {
            int r0 = wm * 32 + mt * 16 + (lane >> 2);
            int c0 = wn * 64 + nt * 8 + (lane & 3) * 2;
#pragma unroll
            for (int v = 0; v < 4; v++) {
                int row = r0 + (v >> 1) * 8;
                int col = c0 + (v & 1);
                sf[row * 260 + col] = acc[mt][nt][v];
            }
        }
    __syncthreads();

    // per-lane fixed columns
    float gvr[8], bvr[8];
#pragma unroll
    for (int j = 0; j < 8; j++) {
        gvr[j] = gv_[lane * 8 + j];
        bvr[j] = bv_[lane * 8 + j];
    }

#pragma unroll
    for (int i = 0; i < 8; i++) {
        const int row = wid + 8 * i;
        float v[8];
#pragma unroll
        for (int j = 0; j < 8; j++) v[j] = sf[row * 260 + lane * 8 + j];
        float s = 0.f;
#pragma unroll
        for (int j = 0; j < 8; j++) s += v[j];
        s = warp_sum(s);
        const float mu = s * (1.f / 256.f);
        float s2 = 0.f;
#pragma unroll
        for (int j = 0; j < 8; j++) { float d = v[j] - mu; s2 += d * d; }
        s2 = warp_sum(s2);
        const float rs = rsqrtf(s2 * (1.f / 256.f) + EPS_LN);

        const size_t gr = (size_t)(bm + row);
#pragma unroll
        for (int j = 0; j < 8; j++) {
            const int col = lane * 8 + j;
            float y = (v[j] - mu) * rs * gvr[j] + bvr[j];
            if (EPI == EPI_LNCAT) {
                __half h, l; split1(y, h, l);
                Ch[gr * D2 + DD + col] = h;
                Cl[gr * D2 + DD + col] = l;
            } else {
                outf[gr * DD + col] = xres[gr * DD + col] + y;
            }
        }
    }
}

// ---------------- x split -> cat[:,0:256] ----------------
__global__ __launch_bounds__(256)
void split_x_kernel(const float* __restrict__ s, __half* __restrict__ hi,
                    __half* __restrict__ lo)
{
    int i = blockIdx.x * 256 + threadIdx.x;   // over MR*DD/4
    int e0  = i * 4;
    int row = e0 >> 8;
    int col = e0 & 255;
    float4 v = *(const float4*)(s + (size_t)i * 4);
    __half h[4], l[4];
    split1(v.x, h[0], l[0]); split1(v.y, h[1], l[1]);
    split1(v.z, h[2], l[2]); split1(v.w, h[3], l[3]);
    size_t o = (size_t)row * D2 + col;
    __half2* hp = (__half2*)(hi + o);
    __half2* lp = (__half2*)(lo + o);
    hp[0] = __halves2half2(h[0], h[1]); hp[1] = __halves2half2(h[2], h[3]);
    lp[0] = __halves2half2(l[0], l[1]); lp[1] = __halves2half2(l[2], l[3]);
}

// ---------------- flat fp32 -> (hi,lo) fp16 split ----------------
__global__ __launch_bounds__(256)
void split_kernel(const float* __restrict__ s, __half* __restrict__ hi,
                  __half* __restrict__ lo, int n4)
{
    int i = blockIdx.x * 256 + threadIdx.x;
    if (i >= n4) return;
    float4 v = *(const float4*)(s + (size_t)i * 4);
    __half h[4], l[4];
    split1(v.x, h[0], l[0]); split1(v.y, h[1], l[1]);
    split1(v.z, h[2], l[2]); split1(v.w, h[3], l[3]);
    __half2* hp = (__half2*)(hi + (size_t)i * 4);
    __half2* lp = (__half2*)(lo + (size_t)i * 4);
    hp[0] = __halves2half2(h[0], h[1]); hp[1] = __halves2half2(h[2], h[3]);
    lp[0] = __halves2half2(l[0], l[1]); lp[1] = __halves2half2(l[2], l[3]);
}

// ---------------- fp32 -> fp16 convert (weights) ----------------
__global__ __launch_bounds__(256)
void tohalf_kernel(const float* __restrict__ s, __half* __restrict__ d, int n4)
{
    int i = blockIdx.x * 256 + threadIdx.x;
    if (i >= n4) return;
    float4 v = *(const float4*)(s + (size_t)i * 4);
    __half2* dp = (__half2*)(d + (size_t)i * 4);
    dp[0] = __halves2half2(__float2half_rn(v.x), __float2half_rn(v.y));
    dp[1] = __halves2half2(__float2half_rn(v.z), __float2half_rn(v.w));
}

// ---------------- zero KV/Ksum ----------------
__global__ void zero_kv_kernel()
{
    int i = blockIdx.x * blockDim.x + threadIdx.x;
    if (i < NB * HH * HD * HD) g_KV[i] = 0.f;
    if (i < NB * HH * HD)      g_Ksum[i] = 0.f;
}

// ---------------- KV = sum_s K (x) v ; Ksum = sum_s K ----------------
#define KVSPLIT 64
#define SCHUNK  (SS / KVSPLIT)   // 128

__global__ __launch_bounds__(256)
void kv_kernel(const float* __restrict__ Kp, const float* __restrict__ Vp)
{
    __shared__ float Ks[SCHUNK][HD];
    __shared__ float Vs[SCHUNK][HD];

    const int nh = blockIdx.x;
    const int n  = nh >> 3;
    const int h  = nh & 7;
    const int s0 = blockIdx.y * SCHUNK;
    const int tid = threadIdx.x;

#pragma unroll
    for (int i = 0; i < 4; i++) {
        int idx = tid + 256 * i;
        int row = idx >> 3;
        int c   = (idx & 7) * 4;
        size_t g = ((size_t)(n * SS + s0 + row)) * DD + h * HD + c;
        *(float4*)&Ks[row][c] = *(const float4*)(Kp + g);
        *(float4*)&Vs[row][c] = *(const float4*)(Vp + g);
    }
    __syncthreads();

    const int d  = tid >> 3;
    const int e0 = (tid & 7) * 4;
    float a0 = 0.f, a1 = 0.f, a2 = 0.f, a3 = 0.f, ks = 0.f;
    for (int s = 0; s < SCHUNK; s++) {
        float kd = Ks[s][d];
        float4 v = *(const float4*)&Vs[s][e0];
        a0 += kd * v.x; a1 += kd * v.y; a2 += kd * v.z; a3 += kd * v.w;
        ks += kd;
    }
    float* KV = g_KV + (size_t)nh * HD * HD + d * HD + e0;
    atomicAdd(KV + 0, a0); atomicAdd(KV + 1, a1);
    atomicAdd(KV + 2, a2); atomicAdd(KV + 3, a3);
    if ((tid & 7) == 0) atomicAdd(g_Ksum + nh * HD + d, ks);
}

// ---------------- G[n][j][h*32+d] = sum_e KV[n,h,d,e] * Wm[j, h*32+e] ------
__global__ __launch_bounds__(256)
void g_kernel(const float* __restrict__ Wm)
{
    __shared__ float KVs[HD][HD];
    const int h = blockIdx.x;
    const int n = blockIdx.y;
    const int tid = threadIdx.x;

    {
        const float4* src = (const float4*)(g_KV + ((size_t)(n * HH + h)) * HD * HD);
        ((float4*)&KVs[0][0])[tid] = src[tid];
    }
    __syncthreads();

    const int j = tid;
    float w[HD];
#pragma unroll
    for (int e = 0; e < HD; e++) w[e] = Wm[(size_t)j * DD + h * HD + e];

    __half* Gp = (__half*)g_G + ((size_t)n * DD + j) * DD + h * HD;
#pragma unroll
    for (int d = 0; d < HD; d++) {
        float acc = 0.f;
#pragma unroll
        for (int e = 0; e < HD; e++) acc += KVs[d][e] * w[e];
        Gp[d] = __float2half_rn(acc);
    }
}

// ---------------- host ----------------
static float* sym_f(const void* s) { void* p = nullptr; cudaGetSymbolAddress(&p, s); return (float*)p; }
static __half* sym_h(const void* s) { void* p = nullptr; cudaGetSymbolAddress(&p, s); return (__half*)p; }

extern "C" void kernel_launch(void* const* d_in, const int* in_sizes, int n_in,
                              void* d_out, int out_size)
{
    const float* x           = (const float*)d_in[0];
    const float* source      = (const float*)d_in[1];
    const float* x_mask      = (const float*)d_in[2];
    const float* source_mask = (const float*)d_in[3];
    const float* Wq          = (const float*)d_in[4];
    const float* Wk          = (const float*)d_in[5];
    const float* Wv          = (const float*)d_in[6];
    const float* Wm          = (const float*)d_in[7];
    const float* W1          = (const float*)d_in[8];
    const float* W2          = (const float*)d_in[9];
    const float* g1          = (const float*)d_in[10];
    const float* b1          = (const float*)d_in[11];
    const float* g2          = (const float*)d_in[12];
    const float* b2          = (const float*)d_in[13];
    float* out = (float*)d_out;

    float* pK    = sym_f(g_K);
    float* pV    = sym_f(g_V);
    float* pKsum = sym_f(g_Ksum);

    __half *pss_h = sym_h(g_ss_h), *pss_l = sym_h(g_ss_l);
    __half *pqz_h = sym_h(g_qz_h), *pqz_l = sym_h(g_qz_l);
    __half *pct_h = sym_h(g_cat_h), *pct_l = sym_h(g_cat_l);
    __half *ph1_h = sym_h(g_h1_h), *ph1_l = sym_h(g_h1_l);
    __half *pwq = sym_h(g_wq), *pwk = sym_h(g_wk), *pwv = sym_h(g_wv);
    __half *pw1 = sym_h(g_w1), *pw2 = sym_h(g_w2), *pG = sym_h(g_G);

    cudaFuncSetAttribute(gemm128<ACT_ELU1, true,  EPI_F32  >, cudaFuncAttributeMaxDynamicSharedMemorySize, GSMEM);
    cudaFuncSetAttribute(gemm128<ACT_NONE, true,  EPI_F32  >, cudaFuncAttributeMaxDynamicSharedMemorySize, GSMEM);
    cudaFuncSetAttribute(gemm128<ACT_ELU1, true,  EPI_QZ   >, cudaFuncAttributeMaxDynamicSharedMemorySize, GSMEM);
    cudaFuncSetAttribute(gemm128<ACT_RELU, false, EPI_SPLIT>, cudaFuncAttributeMaxDynamicSharedMemorySize, GSMEM);
    cudaFuncSetAttribute(gemm256<EPI_LNCAT, true >, cudaFuncAttributeMaxDynamicSharedMemorySize, GSMEM);
    cudaFuncSetAttribute(gemm256<EPI_LNRES, false>, cudaFuncAttributeMaxDynamicSharedMemorySize, GSMEM);

    dim3 blk(256);
    dim3 gN256(DD / 128, MR / 128);   // (2, 256)
    dim3 gN512(D2 / 128, MR / 128);   // (4, 256)

    zero_kv_kernel<<<(NB * HH * HD * HD + 255) / 256, 256>>>();

    // splits / converts
    split_x_kernel<<<MR * DD / 4 / 256, 256>>>(x, pct_h, pct_l);
    split_kernel<<<(MR * DD / 4 + 255) / 256, 256>>>(source, pss_h, pss_l, MR * DD / 4);
    tohalf_kernel<<<(DD * DD / 4 + 255) / 256, 256>>>(Wq, pwq, DD * DD / 4);
    tohalf_kernel<<<(DD * DD / 4 + 255) / 256, 256>>>(Wk, pwk, DD * DD / 4);
    tohalf_kernel<<<(DD * DD / 4 + 255) / 256, 256>>>(Wv, pwv, DD * DD / 4);
    tohalf_kernel<<<(D2 * D2 / 4 + 255) / 256, 256>>>(W1, pw1, D2 * D2 / 4);
    tohalf_kernel<<<(DD * D2 / 4 + 255) / 256, 256>>>(W2, pw2, DD * D2 / 4);

    // K, V projections (fp32 out)
    gemm128<ACT_ELU1, true, EPI_F32><<<gN256, blk, GSMEM>>>(pss_h, pss_l, pwk, DD,
        pK, nullptr, nullptr, DD, DD, source_mask, 1.f, nullptr);
    gemm128<ACT_NONE, true, EPI_F32><<<gN256, blk, GSMEM>>>(pss_h, pss_l, pwv, DD,
        pV, nullptr, nullptr, DD, DD, source_mask, 1.f / (float)SS, nullptr);

    // KV, Ksum, G = KV@Wm
    kv_kernel<<<dim3(NB * HH, KVSPLIT), blk>>>(pK, pV);
    g_kernel<<<dim3(HH, NB), blk>>>(Wm);

    // Q projection with fused Z: qz = (elu(x@Wq.T)+1)*mask*Z*SS  (split out)
    gemm128<ACT_ELU1, true, EPI_QZ><<<gN256, blk, GSMEM>>>(pct_h, pct_l, pwq, D2,
        nullptr, pqz_h, pqz_l, DD, DD, x_mask, 1.f, pKsum);

    // msg2 = qz @ G[n].T  with fused LN(g1,b1) -> cat[:,256:512] (split)
    gemm256<EPI_LNCAT, true><<<MR / 64, blk, GSMEM>>>(pqz_h, pqz_l, pG, DD, DD,
        g1, b1, nullptr, nullptr, pct_h, pct_l);

    // h1 = relu(cat @ W1.T) (split out)
    gemm128<ACT_RELU, false, EPI_SPLIT><<<gN512, blk, GSMEM>>>(pct_h, pct_l, pw1, D2,
        nullptr, ph1_h, ph1_l, D2, D2, nullptr, 1.f, nullptr);

    // out = x + LN(h1 @ W2.T)
    gemm256<EPI_LNRES, false><<<MR / 64, blk, GSMEM>>>(ph1_h, ph1_l, pw2, D2, D2,
        g2, b2, x, out, nullptr, nullptr);
}

// round 6
// speedup vs baseline: 3.0827x; 1.0173x over previous
#include <cuda_runtime.h>
#include <cuda_fp16.h>
#include <math.h>
#include <stdint.h>

// ---------------- problem constants ----------------
#define NB   4
#define LQ   8192
#define SS   8192
#define DD   256
#define HH   8
#define HD   32
#define D2   512
#define MR   (NB*LQ)        // 32768
#define EPS_ATTN 1e-6f
#define EPS_LN   1e-5f

// ---------------- scratch (device globals) ----------------
__device__ float g_K   [(size_t)MR*DD];
__device__ float g_V   [(size_t)MR*DD];
__device__ float g_KV  [NB*HH*HD*HD];
__device__ float g_Ksum[NB*HH*HD];

__device__ __half g_ss_h [(size_t)MR*DD];
__device__ __half g_ss_l [(size_t)MR*DD];
__device__ __half g_qz_h [(size_t)MR*DD];
__device__ __half g_qz_l [(size_t)MR*DD];
__device__ __half g_cat_h[(size_t)MR*D2];
__device__ __half g_cat_l[(size_t)MR*D2];
__device__ __half g_h1_h [(size_t)MR*D2];
__device__ __half g_h1_l [(size_t)MR*D2];

__device__ __half g_wq[DD*DD];
__device__ __half g_wk[DD*DD];
__device__ __half g_wv[DD*DD];
__device__ __half g_w1[D2*D2];
__device__ __half g_w2[DD*D2];
__device__ __half g_G [NB*DD*DD];     // per-batch effective weight KV@Wm

// ---------------- low-level helpers ----------------
__device__ __forceinline__ uint32_t smem_u32(const void* p) {
    uint32_t a;
    asm("{ .reg .u64 t; cvta.to.shared.u64 t, %1; cvt.u32.u64 %0, t; }"
        : "=r"(a) : "l"(p));
    return a;
}

__device__ __forceinline__ uint32_t sw128(uint32_t off) {
    return off ^ ((off >> 3) & 0x70);
}

#define CPASYNC16(sa, ga) \
    asm volatile("cp.async.cg.shared.global [%0], [%1], 16;" \
                 :: "r"(sa), "l"(ga) : "memory")
#define CPCOMMIT() asm volatile("cp.async.commit_group;" ::: "memory")
#define CPWAIT0()  asm volatile("cp.async.wait_group 0;" ::: "memory")
#define CPWAIT1()  asm volatile("cp.async.wait_group 1;" ::: "memory")

#define LDSM4(r, addr) \
    asm volatile("ldmatrix.sync.aligned.m8n8.x4.shared.b16 {%0,%1,%2,%3}, [%4];" \
        : "=r"((r)[0]), "=r"((r)[1]), "=r"((r)[2]), "=r"((r)[3]) : "r"(addr))

__device__ __forceinline__ void mma_f16(float* c, const uint32_t* a,
                                        uint32_t b0, uint32_t b1) {
    asm volatile(
        "mma.sync.aligned.m16n8k16.row.col.f32.f16.f16.f32 "
        "{%0,%1,%2,%3}, {%4,%5,%6,%7}, {%8,%9}, {%0,%1,%2,%3};"
        : "+f"(c[0]), "+f"(c[1]), "+f"(c[2]), "+f"(c[3])
        : "r"(a[0]), "r"(a[1]), "r"(a[2]), "r"(a[3]), "r"(b0), "r"(b1));
}

__device__ __forceinline__ void split1(float v, __half& h, __half& l) {
    h = __float2half_rn(v);
    l = __float2half_rn(v - __half2float(h));
}

__device__ __forceinline__ float warp_sum(float v) {
#pragma unroll
    for (int o = 16; o > 0; o >>= 1) v += __shfl_xor_sync(0xffffffffu, v, o);
    return v;
}

enum { ACT_NONE = 0, ACT_ELU1 = 1, ACT_RELU = 2 };
enum { EPI_F32 = 0, EPI_SPLIT = 1, EPI_QZ = 2 };
enum { EPI_LNCAT = 0, EPI_LNRES = 1 };

#define GSMEM 98304u

// ================= persistent GEMM, 128x128 tile, direct-store epilogue ====
// C[m,n] = act(sum_k A[m,k]*B[n,k]) * mask[m] * scale
// A = Ah+Al (fp16 pair, row stride lda), B fp16 (row stride K).
// 8 warps 4(M)x2(N). K chunks of 64, SW128, double-buffered cp.async.
// Persistent: tile-strided loop with cross-tile chunk-0 prefetch.
#define T_BYTES   16384u
#define STG_BYTES (3u*T_BYTES)

template<int ACT, bool HASMASK, int EPI>
__global__ __launch_bounds__(256, 2)
void gemm128p(const __half* __restrict__ Ahp, const __half* __restrict__ Alp,
              const __half* __restrict__ Bhp, int lda,
              float* __restrict__ C, __half* __restrict__ Ch, __half* __restrict__ Cl,
              int Nc, int K, const float* __restrict__ mask, float scale,
              const float* __restrict__ Ksum)
{
    extern __shared__ char smem[];
    const uint32_t sb = smem_u32(smem);
    const int tid  = threadIdx.x;
    const int lane = tid & 31;
    const int wid  = tid >> 5;
    const int wm   = wid >> 1;
    const int wn   = wid & 1;

    const int Ntl = Nc >> 7;
    const int T   = (MR >> 7) * Ntl;
    const int NCC = K >> 6;

    auto load_chunk = [&](int st, int bm, int bn, int c) {
        const int k0 = c * 64;
        const uint32_t stb = sb + st * STG_BYTES;
#pragma unroll
        for (int i = 0; i < 4; i++) {
            int ci  = tid + 256 * i;
            int row = ci >> 3;
            int c16 = ci & 7;
            uint32_t so = sw128((uint32_t)(row * 128 + c16 * 16));
            size_t ga = (size_t)(bm + row) * lda + k0 + c16 * 8;
            size_t gb = (size_t)(bn + row) * K + k0 + c16 * 8;
            CPASYNC16(stb + 0 * T_BYTES + so, Ahp + ga);
            CPASYNC16(stb + 1 * T_BYTES + so, Alp + ga);
            CPASYNC16(stb + 2 * T_BYTES + so, Bhp + gb);
        }
        CPCOMMIT();
    };

    const int t0 = blockIdx.x;
    if (t0 >= T) return;
    load_chunk(0, (t0 / Ntl) * 128, (t0 % Ntl) * 128, 0);

    const int a_row = wm * 32 + (lane & 15);
    const int a_kb  = (lane >> 4) * 16;
    const int b_row = wn * 64 + (lane & 7) + ((lane >> 4) << 3);
    const int b_kb  = ((lane >> 3) & 1) * 16;

    int g = 0;
    for (int t = t0; t < T; t += gridDim.x) {
        const int bm = (t / Ntl) * 128;
        const int bn = (t % Ntl) * 128;

        float acc[2][8][4];
#pragma unroll
        for (int i = 0; i < 2; i++)
#pragma unroll
            for (int j = 0; j < 8; j++)
#pragma unroll
                for (int v = 0; v < 4; v++) acc[i][j][v] = 0.f;

        for (int c = 0; c < NCC; c++) {
            if (c + 1 < NCC) {
                load_chunk((g + 1) & 1, bm, bn, c + 1);
                CPWAIT1();
            } else {
                int tn = t + gridDim.x;
                if (tn < T) {
                    load_chunk((g + 1) & 1, (tn / Ntl) * 128, (tn % Ntl) * 128, 0);
                    CPWAIT1();
                } else {
                    CPWAIT0();
                }
            }
            __syncthreads();

            const uint32_t stb = sb + (g & 1) * STG_BYTES;
#pragma unroll
            for (int ks = 0; ks < 4; ks++) {
                uint32_t ah[2][4], al[2][4], bh[4][4];
#pragma unroll
                for (int mt = 0; mt < 2; mt++) {
                    uint32_t ra = sw128((uint32_t)((a_row + mt * 16) * 128 + ks * 32 + a_kb));
                    LDSM4(ah[mt], stb + 0 * T_BYTES + ra);
                    LDSM4(al[mt], stb + 1 * T_BYTES + ra);
                }
#pragma unroll
                for (int ntp = 0; ntp < 4; ntp++) {
                    uint32_t rb = sw128((uint32_t)((b_row + ntp * 16) * 128 + ks * 32 + b_kb));
                    LDSM4(bh[ntp], stb + 2 * T_BYTES + rb);
                }
#pragma unroll
                for (int mt = 0; mt < 2; mt++)
#pragma unroll
                    for (int nt = 0; nt < 8; nt++) {
                        const int ntp = nt >> 1, o = (nt & 1) * 2;
                        mma_f16(acc[mt][nt], ah[mt], bh[ntp][o], bh[ntp][o + 1]);
                        mma_f16(acc[mt][nt], al[mt], bh[ntp][o], bh[ntp][o + 1]);
                    }
            }
            g++;
            __syncthreads();
        }

        // ------------- epilogue (register-direct; prefetch of next tile in flight)
        {
            // act + mask*scale in place
            float mk[2][2];
#pragma unroll
            for (int mt = 0; mt < 2; mt++)
#pragma unroll
                for (int rh = 0; rh < 2; rh++) {
                    int m = bm + wm * 32 + mt * 16 + (lane >> 2) + rh * 8;
                    mk[mt][rh] = (HASMASK ? mask[m] : 1.f) * scale;
                }
#pragma unroll
            for (int mt = 0; mt < 2; mt++)
#pragma unroll
                for (int nt = 0; nt < 8; nt++)
#pragma unroll
                    for (int v = 0; v < 4; v++) {
                        float xv = acc[mt][nt][v];
                        if (ACT == ACT_ELU1)      xv = (xv > 0.f) ? (xv + 1.f) : expf(xv);
                        else if (ACT == ACT_RELU) xv = fmaxf(xv, 0.f);
                        acc[mt][nt][v] = xv * mk[mt][v >> 1];
                    }

            if (EPI == EPI_QZ) {
                const int n = bm / LQ;
                float ksv[8][2];
#pragma unroll
                for (int nt = 0; nt < 8; nt++)
#pragma unroll
                    for (int j = 0; j < 2; j++)
                        ksv[nt][j] = Ksum[n * DD + bn + wn * 64 + nt * 8 + (lane & 3) * 2 + j];

                float p[2][2][2];   // [mt][rh][hgrp]
#pragma unroll
                for (int mt = 0; mt < 2; mt++)
#pragma unroll
                    for (int rh = 0; rh < 2; rh++)
#pragma unroll
                        for (int hg = 0; hg < 2; hg++) p[mt][rh][hg] = 0.f;
#pragma unroll
                for (int mt = 0; mt < 2; mt++)
#pragma unroll
                    for (int nt = 0; nt < 8; nt++)
#pragma unroll
                        for (int v = 0; v < 4; v++)
                            p[mt][v >> 1][nt >> 2] += acc[mt][nt][v] * ksv[nt][v & 1];

                float z[2][2][2];
#pragma unroll
                for (int mt = 0; mt < 2; mt++)
#pragma unroll
                    for (int rh = 0; rh < 2; rh++)
#pragma unroll
                        for (int hg = 0; hg < 2; hg++) {
                            float s = p[mt][rh][hg];
                            s += __shfl_xor_sync(0xffffffffu, s, 1);
                            s += __shfl_xor_sync(0xffffffffu, s, 2);
                            z[mt][rh][hg] = (float)SS / (s + EPS_ATTN);
                        }

#pragma unroll
                for (int mt = 0; mt < 2; mt++)
#pragma unroll
                    for (int nt = 0; nt < 8; nt++)
#pragma unroll
                        for (int rh = 0; rh < 2; rh++) {
                            int row = bm + wm * 32 + mt * 16 + (lane >> 2) + rh * 8;
                            int col = bn + wn * 64 + nt * 8 + (lane & 3) * 2;
                            float zz = z[mt][rh][nt >> 2];
                            float v0 = acc[mt][nt][rh * 2]     * zz;
                            float v1 = acc[mt][nt][rh * 2 + 1] * zz;
                            __half h0, l0, h1, l1;
                            split1(v0, h0, l0); split1(v1, h1, l1);
                            size_t gi = (size_t)row * DD + col;
                            *(__half2*)(Ch + gi) = __halves2half2(h0, h1);
                            *(__half2*)(Cl + gi) = __halves2half2(l0, l1);
                        }
            } else {
#pragma unroll
                for (int mt = 0; mt < 2; mt++)
#pragma unroll
                    for (int nt = 0; nt < 8; nt++)
#pragma unroll
                        for (int rh = 0; rh < 2; rh++) {
                            int row = bm + wm * 32 + mt * 16 + (lane >> 2) + rh * 8;
                            int col = bn + wn * 64 + nt * 8 + (lane & 3) * 2;
                            float v0 = acc[mt][nt][rh * 2];
                            float v1 = acc[mt][nt][rh * 2 + 1];
                            size_t gi = (size_t)row * Nc + col;
                            if (EPI == EPI_SPLIT) {
                                __half h0, l0, h1, l1;
                                split1(v0, h0, l0); split1(v1, h1, l1);
                                *(__half2*)(Ch + gi) = __halves2half2(h0, h1);
                                *(__half2*)(Cl + gi) = __halves2half2(l0, l1);
                            } else {
                                *(float2*)(C + gi) = make_float2(v0, v1);
                            }
                        }
            }
        }
    }
}

// ================= GEMM 64x256 tile (full-row, LN epilogue) =================
#define A_REG  8192u
#define B_REG  16384u
#define STG256 49152u

template<int EPI, bool BATCHB>
__global__ __launch_bounds__(256, 2)
void gemm256(const __half* __restrict__ Ahp, const __half* __restrict__ Alp,
             const __half* __restrict__ Bhp, int lda, int K,
             const float* __restrict__ gv_, const float* __restrict__ bv_,
             const float* __restrict__ xres,
             float* __restrict__ outf, __half* __restrict__ Ch, __half* __restrict__ Cl)
{
    extern __shared__ char smem[];
    const uint32_t sb = smem_u32(smem);
    const int tid  = threadIdx.x;
    const int lane = tid & 31;
    const int wid  = tid >> 5;
    const int wm   = wid >> 2;
    const int wn   = wid & 3;
    const int bm   = blockIdx.x * 64;

    if (BATCHB) Bhp += (size_t)(bm / LQ) * DD * DD;

    float acc[2][8][4];
#pragma unroll
    for (int i = 0; i < 2; i++)
#pragma unroll
        for (int j = 0; j < 8; j++)
#pragma unroll
            for (int v = 0; v < 4; v++) acc[i][j][v] = 0.f;

    const int NCC = K >> 6;

    auto load_chunk = [&](int st, int c) {
        const int k0 = c * 64;
        const uint32_t stb = sb + st * STG256;
#pragma unroll
        for (int i = 0; i < 12; i++) {
            int ci = tid + 256 * i;
            if (i < 2) {
                int row = ci >> 3, c16 = ci & 7;
                uint32_t so = sw128((uint32_t)(row * 128 + c16 * 16));
                CPASYNC16(stb + so, Ahp + (size_t)(bm + row) * lda + k0 + c16 * 8);
            } else if (i < 4) {
                int idx = ci - 512;
                int row = idx >> 3, c16 = idx & 7;
                uint32_t so = sw128((uint32_t)(row * 128 + c16 * 16));
                CPASYNC16(stb + A_REG + so, Alp + (size_t)(bm + row) * lda + k0 + c16 * 8);
            } else {
                int idx = ci - 1024;
                int row = idx >> 3, c16 = idx & 7;
                uint32_t so = sw128((uint32_t)(row * 128 + c16 * 16));
                CPASYNC16(stb + B_REG + so, Bhp + (size_t)row * K + k0 + c16 * 8);
            }
        }
        CPCOMMIT();
    };

    load_chunk(0, 0);

    const int a_row = wm * 32 + (lane & 15);
    const int a_kb  = (lane >> 4) * 16;
    const int b_row = wn * 64 + (lane & 7) + ((lane >> 4) << 3);
    const int b_kb  = ((lane >> 3) & 1) * 16;

    for (int c = 0; c < NCC; c++) {
        if (c + 1 < NCC) { load_chunk((c + 1) & 1, c + 1); CPWAIT1(); }
        else             { CPWAIT0(); }
        __syncthreads();

        const uint32_t stb = sb + (c & 1) * STG256;
#pragma unroll
        for (int ks = 0; ks < 4; ks++) {
            uint32_t ah[2][4], al[2][4], bh[4][4];
#pragma unroll
            for (int mt = 0; mt < 2; mt++) {
                uint32_t ra = sw128((uint32_t)((a_row + mt * 16) * 128 + ks * 32 + a_kb));
                LDSM4(ah[mt], stb + ra);
                LDSM4(al[mt], stb + A_REG + ra);
            }
#pragma unroll
            for (int ntp = 0; ntp < 4; ntp++) {
                uint32_t rb = sw128((uint32_t)((b_row + ntp * 16) * 128 + ks * 32 + b_kb));
                LDSM4(bh[ntp], stb + B_REG + rb);
            }
#pragma unroll
            for (int mt = 0; mt < 2; mt++)
#pragma unroll
                for (int nt = 0; nt < 8; nt++) {
                    const int ntp = nt >> 1, o = (nt & 1) * 2;
                    mma_f16(acc[mt][nt], ah[mt], bh[ntp][o], bh[ntp][o + 1]);
                    mma_f16(acc[mt][nt], al[mt], bh[ntp][o], bh[ntp][o + 1]);
                }
        }
        __syncthreads();
    }

    // epilogue: stage + row LN
    float* sf = (float*)smem;
#pragma unroll
    for (int mt = 0; mt < 2; mt++)
#pragma unroll
        for (int nt = 0; nt < 8; nt++) {
            int r0 = wm * 32 + mt * 16 + (lane >> 2);
            int c0 = wn * 64 + nt * 8 + (lane & 3) * 2;
#pragma unroll
            for (int v = 0; v < 4; v++) {
                int row = r0 + (v >> 1) * 8;
                int col = c0 + (v & 1);
                sf[row * 260 + col] = acc[mt][nt][v];
            }
        }
    __syncthreads();

    float gvr[8], bvr[8];
#pragma unroll
    for (int j = 0; j < 8; j++) {
        gvr[j] = gv_[lane * 8 + j];
        bvr[j] = bv_[lane * 8 + j];
    }

#pragma unroll
    for (int i = 0; i < 8; i++) {
        const int row = wid + 8 * i;
        float v[8];
#pragma unroll
        for (int j = 0; j < 8; j++) v[j] = sf[row * 260 + lane * 8 + j];
        float s = 0.f;
#pragma unroll
        for (int j = 0; j < 8; j++) s += v[j];
        s = warp_sum(s);
        const float mu = s * (1.f / 256.f);
        float s2 = 0.f;
#pragma unroll
        for (int j = 0; j < 8; j++) { float d = v[j] - mu; s2 += d * d; }
        s2 = warp_sum(s2);
        const float rs = rsqrtf(s2 * (1.f / 256.f) + EPS_LN);

        const size_t gr = (size_t)(bm + row);
#pragma unroll
        for (int j = 0; j < 8; j++) {
            const int col = lane * 8 + j;
            float y = (v[j] - mu) * rs * gvr[j] + bvr[j];
            if (EPI == EPI_LNCAT) {
                __half h, l; split1(y, h, l);
                Ch[gr * D2 + DD + col] = h;
                Cl[gr * D2 + DD + col] = l;
            } else {
                outf[gr * DD + col] = xres[gr * DD + col] + y;
            }
        }
    }
}

// ---------------- merged prep: weight converts + splits + zero ----------------
__device__ __forceinline__ void tohalf4(const float* s, __half* d, int i) {
    float4 v = *(const float4*)(s + (size_t)i * 4);
    __half2* dp = (__half2*)(d + (size_t)i * 4);
    dp[0] = __halves2half2(__float2half_rn(v.x), __float2half_rn(v.y));
    dp[1] = __halves2half2(__float2half_rn(v.z), __float2half_rn(v.w));
}
__device__ __forceinline__ void split4(const float* s, __half* hi, __half* lo,
                                       size_t si, size_t di) {
    float4 v = *(const float4*)(s + si * 4);
    __half h[4], l[4];
    split1(v.x, h[0], l[0]); split1(v.y, h[1], l[1]);
    split1(v.z, h[2], l[2]); split1(v.w, h[3], l[3]);
    __half2* hp = (__half2*)(hi + di);
    __half2* lp = (__half2*)(lo + di);
    hp[0] = __halves2half2(h[0], h[1]); hp[1] = __halves2half2(h[2], h[3]);
    lp[0] = __halves2half2(l[0], l[1]); lp[1] = __halves2half2(l[2], l[3]);
}

#define NW4  16384          // 256*256/4
#define NW1  65536          // 512*512/4
#define NW2  32768          // 256*512/4
#define NACT 2097152        // 32768*256/4
#define PREP_TOTAL (3*NW4 + NW1 + NW2 + 2*NACT)

__global__ __launch_bounds__(256)
void prep_kernel(const float* __restrict__ Wq, const float* __restrict__ Wk,
                 const float* __restrict__ Wv, const float* __restrict__ W1,
                 const float* __restrict__ W2, const float* __restrict__ src,
                 const float* __restrict__ x)
{
    int i = blockIdx.x * 256 + threadIdx.x;
    if (i < NB * HH * HD * HD) g_KV[i] = 0.f;
    if (i < NB * HH * HD)      g_Ksum[i] = 0.f;
    if (i >= PREP_TOTAL) return;

    int r = i;
    if (r < NW4) { tohalf4(Wq, g_wq, r); return; }
    r -= NW4;
    if (r < NW4) { tohalf4(Wk, g_wk, r); return; }
    r -= NW4;
    if (r < NW4) { tohalf4(Wv, g_wv, r); return; }
    r -= NW4;
    if (r < NW1) { tohalf4(W1, g_w1, r); return; }
    r -= NW1;
    if (r < NW2) { tohalf4(W2, g_w2, r); return; }
    r -= NW2;
    if (r < NACT) { split4(src, g_ss_h, g_ss_l, r, (size_t)r * 4); return; }
    r -= NACT;
    {   // x -> cat[:, 0:256]
        int e0  = r * 4;
        int row = e0 >> 8;
        int col = e0 & 255;
        split4(x, g_cat_h, g_cat_l, r, (size_t)row * D2 + col);
    }
}

// ---------------- KV = sum_s K (x) v ; Ksum = sum_s K ----------------
#define KVSPLIT 64
#define SCHUNK  (SS / KVSPLIT)   // 128

__global__ __launch_bounds__(256)
void kv_kernel(const float* __restrict__ Kp, const float* __restrict__ Vp)
{
    __shared__ float Ks[SCHUNK][HD];
    __shared__ float Vs[SCHUNK][HD];

    const int nh = blockIdx.x;
    const int n  = nh >> 3;
    const int h  = nh & 7;
    const int s0 = blockIdx.y * SCHUNK;
    const int tid = threadIdx.x;

#pragma unroll
    for (int i = 0; i < 4; i++) {
        int idx = tid + 256 * i;
        int row = idx >> 3;
        int c   = (idx & 7) * 4;
        size_t g = ((size_t)(n * SS + s0 + row)) * DD + h * HD + c;
        *(float4*)&Ks[row][c] = *(const float4*)(Kp + g);
        *(float4*)&Vs[row][c] = *(const float4*)(Vp + g);
    }
    __syncthreads();

    const int d  = tid >> 3;
    const int e0 = (tid & 7) * 4;
    float a0 = 0.f, a1 = 0.f, a2 = 0.f, a3 = 0.f, ks = 0.f;
    for (int s = 0; s < SCHUNK; s++) {
        float kd = Ks[s][d];
        float4 v = *(const float4*)&Vs[s][e0];
        a0 += kd * v.x; a1 += kd * v.y; a2 += kd * v.z; a3 += kd * v.w;
        ks += kd;
    }
    float* KV = g_KV + (size_t)nh * HD * HD + d * HD + e0;
    atomicAdd(KV + 0, a0); atomicAdd(KV + 1, a1);
    atomicAdd(KV + 2, a2); atomicAdd(KV + 3, a3);
    if ((tid & 7) == 0) atomicAdd(g_Ksum + nh * HD + d, ks);
}

// ---------------- G[n][j][h*32+d] = sum_e KV[n,h,d,e] * Wm[j, h*32+e] ------
__global__ __launch_bounds__(256)
void g_kernel(const float* __restrict__ Wm)
{
    __shared__ float KVs[HD][HD];
    const int h = blockIdx.x;
    const int n = blockIdx.y;
    const int tid = threadIdx.x;

    {
        const float4* src = (const float4*)(g_KV + ((size_t)(n * HH + h)) * HD * HD);
        ((float4*)&KVs[0][0])[tid] = src[tid];
    }
    __syncthreads();

    const int j = tid;
    float w[HD];
#pragma unroll
    for (int e = 0; e < HD; e++) w[e] = Wm[(size_t)j * DD + h * HD + e];

    __half* Gp = (__half*)g_G + ((size_t)n * DD + j) * DD + h * HD;
#pragma unroll
    for (int d = 0; d < HD; d++) {
        float acc = 0.f;
#pragma unroll
        for (int e = 0; e < HD; e++) acc += KVs[d][e] * w[e];
        Gp[d] = __float2half_rn(acc);
    }
}

// ---------------- host ----------------
static float* sym_f(const void* s) { void* p = nullptr; cudaGetSymbolAddress(&p, s); return (float*)p; }
static __half* sym_h(const void* s) { void* p = nullptr; cudaGetSymbolAddress(&p, s); return (__half*)p; }

extern "C" void kernel_launch(void* const* d_in, const int* in_sizes, int n_in,
                              void* d_out, int out_size)
{
    const float* x           = (const float*)d_in[0];
    const float* source      = (const float*)d_in[1];
    const float* x_mask      = (const float*)d_in[2];
    const float* source_mask = (const float*)d_in[3];
    const float* Wq          = (const float*)d_in[4];
    const float* Wk          = (const float*)d_in[5];
    const float* Wv          = (const float*)d_in[6];
    const float* Wm          = (const float*)d_in[7];
    const float* W1          = (const float*)d_in[8];
    const float* W2          = (const float*)d_in[9];
    const float* g1          = (const float*)d_in[10];
    const float* b1          = (const float*)d_in[11];
    const float* g2          = (const float*)d_in[12];
    const float* b2          = (const float*)d_in[13];
    float* out = (float*)d_out;

    float* pK    = sym_f(g_K);
    float* pV    = sym_f(g_V);
    float* pKsum = sym_f(g_Ksum);

    __half *pss_h = sym_h(g_ss_h), *pss_l = sym_h(g_ss_l);
    __half *pqz_h = sym_h(g_qz_h), *pqz_l = sym_h(g_qz_l);
    __half *pct_h = sym_h(g_cat_h), *pct_l = sym_h(g_cat_l);
    __half *ph1_h = sym_h(g_h1_h), *ph1_l = sym_h(g_h1_l);
    __half *pwq = sym_h(g_wq), *pwk = sym_h(g_wk), *pwv = sym_h(g_wv);
    __half *pw1 = sym_h(g_w1), *pw2 = sym_h(g_w2), *pG = sym_h(g_G);

    cudaFuncSetAttribute(gemm128p<ACT_ELU1, true,  EPI_F32  >, cudaFuncAttributeMaxDynamicSharedMemorySize, GSMEM);
    cudaFuncSetAttribute(gemm128p<ACT_NONE, true,  EPI_F32  >, cudaFuncAttributeMaxDynamicSharedMemorySize, GSMEM);
    cudaFuncSetAttribute(gemm128p<ACT_ELU1, true,  EPI_QZ   >, cudaFuncAttributeMaxDynamicSharedMemorySize, GSMEM);
    cudaFuncSetAttribute(gemm128p<ACT_RELU, false, EPI_SPLIT>, cudaFuncAttributeMaxDynamicSharedMemorySize, GSMEM);
    cudaFuncSetAttribute(gemm256<EPI_LNCAT, true >, cudaFuncAttributeMaxDynamicSharedMemorySize, GSMEM);
    cudaFuncSetAttribute(gemm256<EPI_LNRES, false>, cudaFuncAttributeMaxDynamicSharedMemorySize, GSMEM);

    int nsm = 148;
    cudaDeviceGetAttribute(&nsm, cudaDevAttrMultiProcessorCount, 0);
    const int pgrid = 2 * nsm;

    dim3 blk(256);

    // prep: weights + splits + zero accumulators
    prep_kernel<<<(PREP_TOTAL + 255) / 256, 256>>>(Wq, Wk, Wv, W1, W2, source, x);

    // K, V projections (persistent, fp32 direct out)
    gemm128p<ACT_ELU1, true, EPI_F32><<<pgrid, blk, GSMEM>>>(pss_h, pss_l, pwk, DD,
        pK, nullptr, nullptr, DD, DD, source_mask, 1.f, nullptr);
    gemm128p<ACT_NONE, true, EPI_F32><<<pgrid, blk, GSMEM>>>(pss_h, pss_l, pwv, DD,
        pV, nullptr, nullptr, DD, DD, source_mask, 1.f / (float)SS, nullptr);

    // KV, Ksum, G = KV@Wm
    kv_kernel<<<dim3(NB * HH, KVSPLIT), blk>>>(pK, pV);
    g_kernel<<<dim3(HH, NB), blk>>>(Wm);

    // Q projection with fused Z (register epilogue): qz = Q*Z*SS (split)
    gemm128p<ACT_ELU1, true, EPI_QZ><<<pgrid, blk, GSMEM>>>(pct_h, pct_l, pwq, D2,
        nullptr, pqz_h, pqz_l, DD, DD, x_mask, 1.f, pKsum);

    // msg2 = qz @ G[n].T with fused LN(g1,b1) -> cat[:,256:512]
    gemm256<EPI_LNCAT, true><<<MR / 64, blk, GSMEM>>>(pqz_h, pqz_l, pG, DD, DD,
        g1, b1, nullptr, nullptr, pct_h, pct_l);

    // h1 = relu(cat @ W1.T) (persistent, split out)
    gemm128p<ACT_RELU, false, EPI_SPLIT><<<pgrid, blk, GSMEM>>>(pct_h, pct_l, pw1, D2,
        nullptr, ph1_h, ph1_l, D2, D2, nullptr, 1.f, nullptr);

    // out = x + LN(h1 @ W2.T)
    gemm256<EPI_LNRES, false><<<MR / 64, blk, GSMEM>>>(ph1_h, ph1_l, pw2, D2, D2,
        g2, b2, x, out, nullptr, nullptr);
}

// round 7
// speedup vs baseline: 4.0593x; 1.3168x over previous
#include <cuda_runtime.h>
#include <cuda_fp16.h>
#include <math.h>
#include <stdint.h>

// ---------------- problem constants ----------------
#define NB   4
#define LQ   8192
#define SS   8192
#define DD   256
#define HH   8
#define HD   32
#define D2   512
#define MR   (NB*LQ)        // 32768
#define EPS_ATTN 1e-6f
#define EPS_LN   1e-5f

// ---------------- scratch (device globals) ----------------
__device__ float g_K   [(size_t)MR*DD];
__device__ float g_V   [(size_t)MR*DD];
__device__ float g_KV  [NB*HH*HD*HD];
__device__ float g_Ksum[NB*HH*HD];

__device__ __half g_ss_h [(size_t)MR*DD];
__device__ __half g_qz_h [(size_t)MR*DD];
__device__ __half g_cat_h[(size_t)MR*D2];
__device__ __half g_h1_h [(size_t)MR*D2];

__device__ __half g_wq[DD*DD];
__device__ __half g_wk[DD*DD];
__device__ __half g_wv[DD*DD];
__device__ __half g_w1[D2*D2];
__device__ __half g_w2[DD*D2];
__device__ __half g_G [NB*DD*DD];     // per-batch effective weight KV@Wm

// ---------------- low-level helpers ----------------
__device__ __forceinline__ uint32_t smem_u32(const void* p) {
    uint32_t a;
    asm("{ .reg .u64 t; cvta.to.shared.u64 t, %1; cvt.u32.u64 %0, t; }"
        : "=r"(a) : "l"(p));
    return a;
}

__device__ __forceinline__ uint32_t sw128(uint32_t off) {
    return off ^ ((off >> 3) & 0x70);
}

#define CPASYNC16(sa, ga) \
    asm volatile("cp.async.cg.shared.global [%0], [%1], 16;" \
                 :: "r"(sa), "l"(ga) : "memory")
#define CPCOMMIT() asm volatile("cp.async.commit_group;" ::: "memory")
#define CPWAIT0()  asm volatile("cp.async.wait_group 0;" ::: "memory")
#define CPWAIT1()  asm volatile("cp.async.wait_group 1;" ::: "memory")

#define LDSM4(r, addr) \
    asm volatile("ldmatrix.sync.aligned.m8n8.x4.shared.b16 {%0,%1,%2,%3}, [%4];" \
        : "=r"((r)[0]), "=r"((r)[1]), "=r"((r)[2]), "=r"((r)[3]) : "r"(addr))

__device__ __forceinline__ void mma_f16(float* c, const uint32_t* a,
                                        uint32_t b0, uint32_t b1) {
    asm volatile(
        "mma.sync.aligned.m16n8k16.row.col.f32.f16.f16.f32 "
        "{%0,%1,%2,%3}, {%4,%5,%6,%7}, {%8,%9}, {%0,%1,%2,%3};"
        : "+f"(c[0]), "+f"(c[1]), "+f"(c[2]), "+f"(c[3])
        : "r"(a[0]), "r"(a[1]), "r"(a[2]), "r"(a[3]), "r"(b0), "r"(b1));
}

__device__ __forceinline__ float warp_sum(float v) {
#pragma unroll
    for (int o = 16; o > 0; o >>= 1) v += __shfl_xor_sync(0xffffffffu, v, o);
    return v;
}

enum { ACT_NONE = 0, ACT_ELU1 = 1, ACT_RELU = 2 };
enum { EPI_F32 = 0, EPI_HALF = 1, EPI_QZ = 2 };
enum { EPI_LNCAT = 0, EPI_LNRES = 1 };

// ================= persistent GEMM, 128x128 tile, 1-term fp16 =============
// C[m,n] = act(sum_k A[m,k]*B[n,k]) * mask[m] * scale
#define T_BYTES   16384u
#define STG128    (2u*T_BYTES)     // A,B = 32KB/stage
#define GSMEM128  (2u*STG128)      // 64KB

template<int ACT, bool HASMASK, int EPI>
__global__ __launch_bounds__(256, 2)
void gemm128p(const __half* __restrict__ Ap, const __half* __restrict__ Bp, int lda,
              float* __restrict__ C, __half* __restrict__ Ch,
              int Nc, int K, const float* __restrict__ mask, float scale,
              const float* __restrict__ Ksum)
{
    extern __shared__ char smem[];
    const uint32_t sb = smem_u32(smem);
    const int tid  = threadIdx.x;
    const int lane = tid & 31;
    const int wid  = tid >> 5;
    const int wm   = wid >> 1;
    const int wn   = wid & 1;

    const int Ntl = Nc >> 7;
    const int T   = (MR >> 7) * Ntl;
    const int NCC = K >> 6;

    auto load_chunk = [&](int st, int bm, int bn, int c) {
        const int k0 = c * 64;
        const uint32_t stb = sb + st * STG128;
#pragma unroll
        for (int i = 0; i < 4; i++) {
            int ci  = tid + 256 * i;
            int row = ci >> 3;
            int c16 = ci & 7;
            uint32_t so = sw128((uint32_t)(row * 128 + c16 * 16));
            CPASYNC16(stb + so,           Ap + (size_t)(bm + row) * lda + k0 + c16 * 8);
            CPASYNC16(stb + T_BYTES + so, Bp + (size_t)(bn + row) * K   + k0 + c16 * 8);
        }
        CPCOMMIT();
    };

    const int t0 = blockIdx.x;
    if (t0 >= T) return;
    load_chunk(0, (t0 / Ntl) * 128, (t0 % Ntl) * 128, 0);

    const int a_row = wm * 32 + (lane & 15);
    const int a_kb  = (lane >> 4) * 16;
    const int b_row = wn * 64 + (lane & 7) + ((lane >> 4) << 3);
    const int b_kb  = ((lane >> 3) & 1) * 16;

    int g = 0;
    for (int t = t0; t < T; t += gridDim.x) {
        const int bm = (t / Ntl) * 128;
        const int bn = (t % Ntl) * 128;

        float acc[2][8][4];
#pragma unroll
        for (int i = 0; i < 2; i++)
#pragma unroll
            for (int j = 0; j < 8; j++)
#pragma unroll
                for (int v = 0; v < 4; v++) acc[i][j][v] = 0.f;

        for (int c = 0; c < NCC; c++) {
            if (c + 1 < NCC) {
                load_chunk((g + 1) & 1, bm, bn, c + 1);
                CPWAIT1();
            } else {
                int tn = t + gridDim.x;
                if (tn < T) {
                    load_chunk((g + 1) & 1, (tn / Ntl) * 128, (tn % Ntl) * 128, 0);
                    CPWAIT1();
                } else {
                    CPWAIT0();
                }
            }
            __syncthreads();

            const uint32_t stb = sb + (g & 1) * STG128;
#pragma unroll
            for (int ks = 0; ks < 4; ks++) {
                uint32_t ah[2][4], bh[4][4];
#pragma unroll
                for (int mt = 0; mt < 2; mt++) {
                    uint32_t ra = sw128((uint32_t)((a_row + mt * 16) * 128 + ks * 32 + a_kb));
                    LDSM4(ah[mt], stb + ra);
                }
#pragma unroll
                for (int ntp = 0; ntp < 4; ntp++) {
                    uint32_t rb = sw128((uint32_t)((b_row + ntp * 16) * 128 + ks * 32 + b_kb));
                    LDSM4(bh[ntp], stb + T_BYTES + rb);
                }
#pragma unroll
                for (int mt = 0; mt < 2; mt++)
#pragma unroll
                    for (int nt = 0; nt < 8; nt++) {
                        const int ntp = nt >> 1, o = (nt & 1) * 2;
                        mma_f16(acc[mt][nt], ah[mt], bh[ntp][o], bh[ntp][o + 1]);
                    }
            }
            g++;
            __syncthreads();
        }

        // ------------- register-direct epilogue -------------
        {
            float mk[2][2];
#pragma unroll
            for (int mt = 0; mt < 2; mt++)
#pragma unroll
                for (int rh = 0; rh < 2; rh++) {
                    int m = bm + wm * 32 + mt * 16 + (lane >> 2) + rh * 8;
                    mk[mt][rh] = (HASMASK ? mask[m] : 1.f) * scale;
                }
#pragma unroll
            for (int mt = 0; mt < 2; mt++)
#pragma unroll
                for (int nt = 0; nt < 8; nt++)
#pragma unroll
                    for (int v = 0; v < 4; v++) {
                        float xv = acc[mt][nt][v];
                        if (ACT == ACT_ELU1)      xv = (xv > 0.f) ? (xv + 1.f) : expf(xv);
                        else if (ACT == ACT_RELU) xv = fmaxf(xv, 0.f);
                        acc[mt][nt][v] = xv * mk[mt][v >> 1];
                    }

            if (EPI == EPI_QZ) {
                const int n = bm / LQ;
                float ksv[8][2];
#pragma unroll
                for (int nt = 0; nt < 8; nt++)
#pragma unroll
                    for (int j = 0; j < 2; j++)
                        ksv[nt][j] = Ksum[n * DD + bn + wn * 64 + nt * 8 + (lane & 3) * 2 + j];

                float p[2][2][2];
#pragma unroll
                for (int mt = 0; mt < 2; mt++)
#pragma unroll
                    for (int rh = 0; rh < 2; rh++)
#pragma unroll
                        for (int hg = 0; hg < 2; hg++) p[mt][rh][hg] = 0.f;
#pragma unroll
                for (int mt = 0; mt < 2; mt++)
#pragma unroll
                    for (int nt = 0; nt < 8; nt++)
#pragma unroll
                        for (int v = 0; v < 4; v++)
                            p[mt][v >> 1][nt >> 2] += acc[mt][nt][v] * ksv[nt][v & 1];

                float z[2][2][2];
#pragma unroll
                for (int mt = 0; mt < 2; mt++)
#pragma unroll
                    for (int rh = 0; rh < 2; rh++)
#pragma unroll
                        for (int hg = 0; hg < 2; hg++) {
                            float s = p[mt][rh][hg];
                            s += __shfl_xor_sync(0xffffffffu, s, 1);
                            s += __shfl_xor_sync(0xffffffffu, s, 2);
                            z[mt][rh][hg] = (float)SS / (s + EPS_ATTN);
                        }

#pragma unroll
                for (int mt = 0; mt < 2; mt++)
#pragma unroll
                    for (int nt = 0; nt < 8; nt++)
#pragma unroll
                        for (int rh = 0; rh < 2; rh++) {
                            int row = bm + wm * 32 + mt * 16 + (lane >> 2) + rh * 8;
                            int col = bn + wn * 64 + nt * 8 + (lane & 3) * 2;
                            float zz = z[mt][rh][nt >> 2];
                            float v0 = acc[mt][nt][rh * 2]     * zz;
                            float v1 = acc[mt][nt][rh * 2 + 1] * zz;
                            *(__half2*)(Ch + (size_t)row * DD + col) =
                                __halves2half2(__float2half_rn(v0), __float2half_rn(v1));
                        }
            } else {
#pragma unroll
                for (int mt = 0; mt < 2; mt++)
#pragma unroll
                    for (int nt = 0; nt < 8; nt++)
#pragma unroll
                        for (int rh = 0; rh < 2; rh++) {
                            int row = bm + wm * 32 + mt * 16 + (lane >> 2) + rh * 8;
                            int col = bn + wn * 64 + nt * 8 + (lane & 3) * 2;
                            float v0 = acc[mt][nt][rh * 2];
                            float v1 = acc[mt][nt][rh * 2 + 1];
                            size_t gi = (size_t)row * Nc + col;
                            if (EPI == EPI_HALF) {
                                *(__half2*)(Ch + gi) =
                                    __halves2half2(__float2half_rn(v0), __float2half_rn(v1));
                            } else {
                                *(float2*)(C + gi) = make_float2(v0, v1);
                            }
                        }
            }
        }
    }
}

// ================= GEMM 64x256 tile (full-row, LN epilogue, 1-term) ========
#define A_SZ   8192u
#define B_SZ   32768u
#define STG256 (A_SZ + B_SZ)       // 40KB
#define GSMEM256 (2u*STG256)       // 80KB (epilogue 66.6KB fits)

template<int EPI, bool BATCHB>
__global__ __launch_bounds__(256, 2)
void gemm256(const __half* __restrict__ Ap, const __half* __restrict__ Bp,
             int lda, int K,
             const float* __restrict__ gv_, const float* __restrict__ bv_,
             const float* __restrict__ xres,
             float* __restrict__ outf, __half* __restrict__ Ch)
{
    extern __shared__ char smem[];
    const uint32_t sb = smem_u32(smem);
    const int tid  = threadIdx.x;
    const int lane = tid & 31;
    const int wid  = tid >> 5;
    const int wm   = wid >> 2;
    const int wn   = wid & 3;
    const int bm   = blockIdx.x * 64;

    if (BATCHB) Bp += (size_t)(bm / LQ) * DD * DD;

    float acc[2][8][4];
#pragma unroll
    for (int i = 0; i < 2; i++)
#pragma unroll
        for (int j = 0; j < 8; j++)
#pragma unroll
            for (int v = 0; v < 4; v++) acc[i][j][v] = 0.f;

    const int NCC = K >> 6;

    auto load_chunk = [&](int st, int c) {
        const int k0 = c * 64;
        const uint32_t stb = sb + st * STG256;
#pragma unroll
        for (int i = 0; i < 10; i++) {
            int ci = tid + 256 * i;
            if (i < 2) {            // A: 512 chunks (64 rows x 8)
                int row = ci >> 3, c16 = ci & 7;
                uint32_t so = sw128((uint32_t)(row * 128 + c16 * 16));
                CPASYNC16(stb + so, Ap + (size_t)(bm + row) * lda + k0 + c16 * 8);
            } else {                // B: 2048 chunks (256 rows x 8)
                int idx = ci - 512;
                int row = idx >> 3, c16 = idx & 7;
                uint32_t so = sw128((uint32_t)(row * 128 + c16 * 16));
                CPASYNC16(stb + A_SZ + so, Bp + (size_t)row * K + k0 + c16 * 8);
            }
        }
        CPCOMMIT();
    };

    load_chunk(0, 0);

    const int a_row = wm * 32 + (lane & 15);
    const int a_kb  = (lane >> 4) * 16;
    const int b_row = wn * 64 + (lane & 7) + ((lane >> 4) << 3);
    const int b_kb  = ((lane >> 3) & 1) * 16;

    for (int c = 0; c < NCC; c++) {
        if (c + 1 < NCC) { load_chunk((c + 1) & 1, c + 1); CPWAIT1(); }
        else             { CPWAIT0(); }
        __syncthreads();

        const uint32_t stb = sb + (c & 1) * STG256;
#pragma unroll
        for (int ks = 0; ks < 4; ks++) {
            uint32_t ah[2][4], bh[4][4];
#pragma unroll
            for (int mt = 0; mt < 2; mt++) {
                uint32_t ra = sw128((uint32_t)((a_row + mt * 16) * 128 + ks * 32 + a_kb));
                LDSM4(ah[mt], stb + ra);
            }
#pragma unroll
            for (int ntp = 0; ntp < 4; ntp++) {
                uint32_t rb = sw128((uint32_t)((b_row + ntp * 16) * 128 + ks * 32 + b_kb));
                LDSM4(bh[ntp], stb + A_SZ + rb);
            }
#pragma unroll
            for (int mt = 0; mt < 2; mt++)
#pragma unroll
                for (int nt = 0; nt < 8; nt++) {
                    const int ntp = nt >> 1, o = (nt & 1) * 2;
                    mma_f16(acc[mt][nt], ah[mt], bh[ntp][o], bh[ntp][o + 1]);
                }
        }
        __syncthreads();
    }

    // epilogue: stage + row LN
    float* sf = (float*)smem;
#pragma unroll
    for (int mt = 0; mt < 2; mt++)
#pragma unroll
        for (int nt = 0; nt < 8; nt++) {
            int r0 = wm * 32 + mt * 16 + (lane >> 2);
            int c0 = wn * 64 + nt * 8 + (lane & 3) * 2;
#pragma unroll
            for (int v = 0; v < 4; v++) {
                int row = r0 + (v >> 1) * 8;
                int col = c0 + (v & 1);
                sf[row * 260 + col] = acc[mt][nt][v];
            }
        }
    __syncthreads();

    float gvr[8], bvr[8];
#pragma unroll
    for (int j = 0; j < 8; j++) {
        gvr[j] = gv_[lane * 8 + j];
        bvr[j] = bv_[lane * 8 + j];
    }

#pragma unroll
    for (int i = 0; i < 8; i++) {
        const int row = wid + 8 * i;
        float v[8];
#pragma unroll
        for (int j = 0; j < 8; j++) v[j] = sf[row * 260 + lane * 8 + j];
        float s = 0.f;
#pragma unroll
        for (int j = 0; j < 8; j++) s += v[j];
        s = warp_sum(s);
        const float mu = s * (1.f / 256.f);
        float s2 = 0.f;
#pragma unroll
        for (int j = 0; j < 8; j++) { float d = v[j] - mu; s2 += d * d; }
        s2 = warp_sum(s2);
        const float rs = rsqrtf(s2 * (1.f / 256.f) + EPS_LN);

        const size_t gr = (size_t)(bm + row);
#pragma unroll
        for (int j = 0; j < 8; j++) {
            const int col = lane * 8 + j;
            float y = (v[j] - mu) * rs * gvr[j] + bvr[j];
            if (EPI == EPI_LNCAT) {
                Ch[gr * D2 + DD + col] = __float2half_rn(y);
            } else {
                outf[gr * DD + col] = xres[gr * DD + col] + y;
            }
        }
    }
}

// ---------------- merged prep ----------------
__device__ __forceinline__ void tohalf4(const float* s, __half* d, size_t si, size_t di) {
    float4 v = *(const float4*)(s + si * 4);
    __half2* dp = (__half2*)(d + di);
    dp[0] = __halves2half2(__float2half_rn(v.x), __float2half_rn(v.y));
    dp[1] = __halves2half2(__float2half_rn(v.z), __float2half_rn(v.w));
}

#define NW4  16384          // 256*256/4
#define NW1  65536          // 512*512/4
#define NW2  32768          // 256*512/4
#define NACT 2097152        // 32768*256/4
#define PREP_TOTAL (3*NW4 + NW1 + NW2 + 2*NACT)

__global__ __launch_bounds__(256)
void prep_kernel(const float* __restrict__ Wq, const float* __restrict__ Wk,
                 const float* __restrict__ Wv, const float* __restrict__ W1,
                 const float* __restrict__ W2, const float* __restrict__ src,
                 const float* __restrict__ x)
{
    int i = blockIdx.x * 256 + threadIdx.x;
    if (i < NB * HH * HD * HD) g_KV[i] = 0.f;
    if (i < NB * HH * HD)      g_Ksum[i] = 0.f;
    if (i >= PREP_TOTAL) return;

    int r = i;
    if (r < NW4) { tohalf4(Wq, g_wq, r, (size_t)r * 4); return; }
    r -= NW4;
    if (r < NW4) { tohalf4(Wk, g_wk, r, (size_t)r * 4); return; }
    r -= NW4;
    if (r < NW4) { tohalf4(Wv, g_wv, r, (size_t)r * 4); return; }
    r -= NW4;
    if (r < NW1) { tohalf4(W1, g_w1, r, (size_t)r * 4); return; }
    r -= NW1;
    if (r < NW2) { tohalf4(W2, g_w2, r, (size_t)r * 4); return; }
    r -= NW2;
    if (r < NACT) { tohalf4(src, g_ss_h, r, (size_t)r * 4); return; }
    r -= NACT;
    {   // x -> cat[:, 0:256]
        int e0  = r * 4;
        int row = e0 >> 8;
        int col = e0 & 255;
        tohalf4(x, g_cat_h, r, (size_t)row * D2 + col);
    }
}

// ---------------- KV = sum_s K (x) v ; Ksum = sum_s K (8x8 reg blocking) ---
#define KVSPLIT  32
#define SCHUNK   128
#define KVPAD    36

__global__ __launch_bounds__(256)
void kv_kernel(const float* __restrict__ Kp, const float* __restrict__ Vp)
{
    __shared__ float Ks[SCHUNK][KVPAD];
    __shared__ float Vs[SCHUNK][KVPAD];

    const int nh = blockIdx.x;        // 0..31
    const int n  = nh >> 3;
    const int h  = nh & 7;
    const int sb = blockIdx.y * 256;  // 256 s-rows per block (2 chunks of 128)
    const int tid = threadIdx.x;

    const int plane = tid >> 4;       // 0..15 (s-plane)
    const int dg    = (tid & 15) >> 2;
    const int eg    = tid & 3;
    const int d0    = dg * 8;
    const int e0    = eg * 8;

    float acc[8][8];
#pragma unroll
    for (int i = 0; i < 8; i++)
#pragma unroll
        for (int j = 0; j < 8; j++) acc[i][j] = 0.f;
    float ksum[8];
#pragma unroll
    for (int i = 0; i < 8; i++) ksum[i] = 0.f;

    for (int ch = 0; ch < 2; ch++) {
        const int s0 = sb + ch * SCHUNK;
        __syncthreads();
#pragma unroll
        for (int i = 0; i < 4; i++) {
            int idx = tid + 256 * i;       // 0..1023
            int row = idx >> 3;
            int c4  = (idx & 7) * 4;
            size_t g = ((size_t)(n * SS + s0 + row)) * DD + h * HD + c4;
            *(float4*)&Ks[row][c4] = *(const float4*)(Kp + g);
            *(float4*)&Vs[row][c4] = *(const float4*)(Vp + g);
        }
        __syncthreads();

#pragma unroll
        for (int it = 0; it < 8; it++) {
            const int s = plane + 16 * it;
            float4 k0 = *(const float4*)&Ks[s][d0];
            float4 k1 = *(const float4*)&Ks[s][d0 + 4];
            float4 v0 = *(const float4*)&Vs[s][e0];
            float4 v1 = *(const float4*)&Vs[s][e0 + 4];
            float kd[8] = {k0.x, k0.y, k0.z, k0.w, k1.x, k1.y, k1.z, k1.w};
            float vv[8] = {v0.x, v0.y, v0.z, v0.w, v1.x, v1.y, v1.z, v1.w};
#pragma unroll
            for (int i = 0; i < 8; i++)
#pragma unroll
                for (int j = 0; j < 8; j++) acc[i][j] += kd[i] * vv[j];
            if (eg == 0)
#pragma unroll
                for (int i = 0; i < 8; i++) ksum[i] += kd[i];
        }
    }

    // in-block reduction (reuse Ks storage)
    __syncthreads();
    float* buf = &Ks[0][0];            // 1024 KV + 32 ksum
    float* ksb = buf + 1024;
    for (int i = tid; i < 1056; i += 256) buf[i] = 0.f;
    __syncthreads();
#pragma unroll
    for (int i = 0; i < 8; i++)
#pragma unroll
        for (int j = 0; j < 8; j++)
            atomicAdd(&buf[(d0 + i) * 32 + e0 + j], acc[i][j]);
    if (eg == 0)
#pragma unroll
        for (int i = 0; i < 8; i++) atomicAdd(&ksb[d0 + i], ksum[i]);
    __syncthreads();

    float* KV = g_KV + (size_t)nh * HD * HD;
    for (int i = tid; i < 1024; i += 256) atomicAdd(KV + i, buf[i]);
    if (tid < 32) atomicAdd(g_Ksum + nh * HD + tid, ksb[tid]);
}

// ---------------- G[n][j][h*32+d] = sum_e KV[n,h,d,e] * Wm[j, h*32+e] ------
__global__ __launch_bounds__(256)
void g_kernel(const float* __restrict__ Wm)
{
    __shared__ float KVs[HD][HD];
    const int h = blockIdx.x;
    const int n = blockIdx.y;
    const int tid = threadIdx.x;

    {
        const float4* src = (const float4*)(g_KV + ((size_t)(n * HH + h)) * HD * HD);
        ((float4*)&KVs[0][0])[tid] = src[tid];
    }
    __syncthreads();

    const int j = tid;
    float w[HD];
#pragma unroll
    for (int e = 0; e < HD; e++) w[e] = Wm[(size_t)j * DD + h * HD + e];

    __half* Gp = (__half*)g_G + ((size_t)n * DD + j) * DD + h * HD;
#pragma unroll
    for (int d = 0; d < HD; d++) {
        float acc = 0.f;
#pragma unroll
        for (int e = 0; e < HD; e++) acc += KVs[d][e] * w[e];
        Gp[d] = __float2half_rn(acc);
    }
}

// ---------------- host ----------------
static float* sym_f(const void* s) { void* p = nullptr; cudaGetSymbolAddress(&p, s); return (float*)p; }
static __half* sym_h(const void* s) { void* p = nullptr; cudaGetSymbolAddress(&p, s); return (__half*)p; }

extern "C" void kernel_launch(void* const* d_in, const int* in_sizes, int n_in,
                              void* d_out, int out_size)
{
    const float* x           = (const float*)d_in[0];
    const float* source      = (const float*)d_in[1];
    const float* x_mask      = (const float*)d_in[2];
    const float* source_mask = (const float*)d_in[3];
    const float* Wq          = (const float*)d_in[4];
    const float* Wk          = (const float*)d_in[5];
    const float* Wv          = (const float*)d_in[6];
    const float* Wm          = (const float*)d_in[7];
    const float* W1          = (const float*)d_in[8];
    const float* W2          = (const float*)d_in[9];
    const float* g1          = (const float*)d_in[10];
    const float* b1          = (const float*)d_in[11];
    const float* g2          = (const float*)d_in[12];
    const float* b2          = (const float*)d_in[13];
    float* out = (float*)d_out;

    float* pK    = sym_f(g_K);
    float* pV    = sym_f(g_V);
    float* pKsum = sym_f(g_Ksum);

    __half *pss = sym_h(g_ss_h), *pqz = sym_h(g_qz_h);
    __half *pct = sym_h(g_cat_h), *ph1 = sym_h(g_h1_h);
    __half *pwq = sym_h(g_wq), *pwk = sym_h(g_wk), *pwv = sym_h(g_wv);
    __half *pw1 = sym_h(g_w1), *pw2 = sym_h(g_w2), *pG = sym_h(g_G);

    cudaFuncSetAttribute(gemm128p<ACT_ELU1, true,  EPI_F32 >, cudaFuncAttributeMaxDynamicSharedMemorySize, GSMEM128);
    cudaFuncSetAttribute(gemm128p<ACT_NONE, true,  EPI_F32 >, cudaFuncAttributeMaxDynamicSharedMemorySize, GSMEM128);
    cudaFuncSetAttribute(gemm128p<ACT_ELU1, true,  EPI_QZ  >, cudaFuncAttributeMaxDynamicSharedMemorySize, GSMEM128);
    cudaFuncSetAttribute(gemm128p<ACT_RELU, false, EPI_HALF>, cudaFuncAttributeMaxDynamicSharedMemorySize, GSMEM128);
    cudaFuncSetAttribute(gemm256<EPI_LNCAT, true >, cudaFuncAttributeMaxDynamicSharedMemorySize, GSMEM256);
    cudaFuncSetAttribute(gemm256<EPI_LNRES, false>, cudaFuncAttributeMaxDynamicSharedMemorySize, GSMEM256);

    int nsm = 148;
    cudaDeviceGetAttribute(&nsm, cudaDevAttrMultiProcessorCount, 0);
    const int pgrid = 2 * nsm;

    dim3 blk(256);

    // prep: weight converts + activation converts + zero accumulators
    prep_kernel<<<(PREP_TOTAL + 255) / 256, 256>>>(Wq, Wk, Wv, W1, W2, source, x);

    // K, V projections (fp32 out)
    gemm128p<ACT_ELU1, true, EPI_F32><<<pgrid, blk, GSMEM128>>>(pss, pwk, DD,
        pK, nullptr, DD, DD, source_mask, 1.f, nullptr);
    gemm128p<ACT_NONE, true, EPI_F32><<<pgrid, blk, GSMEM128>>>(pss, pwv, DD,
        pV, nullptr, DD, DD, source_mask, 1.f / (float)SS, nullptr);

    // KV, Ksum, G = KV@Wm
    kv_kernel<<<dim3(NB * HH, KVSPLIT), blk>>>(pK, pV);
    g_kernel<<<dim3(HH, NB), blk>>>(Wm);

    // Q projection with fused Z: qz = Q*Z*SS (fp16 out)
    gemm128p<ACT_ELU1, true, EPI_QZ><<<pgrid, blk, GSMEM128>>>(pct, pwq, D2,
        nullptr, pqz, DD, DD, x_mask, 1.f, pKsum);

    // msg2 = qz @ G[n].T with fused LN(g1,b1) -> cat[:,256:512]
    gemm256<EPI_LNCAT, true><<<MR / 64, blk, GSMEM256>>>(pqz, pG, DD, DD,
        g1, b1, nullptr, nullptr, pct);

    // h1 = relu(cat @ W1.T)
    gemm128p<ACT_RELU, false, EPI_HALF><<<pgrid, blk, GSMEM128>>>(pct, pw1, D2,
        nullptr, ph1, D2, D2, nullptr, 1.f, nullptr);

    // out = x + LN(h1 @ W2.T)
    gemm256<EPI_LNRES, false><<<MR / 64, blk, GSMEM256>>>(ph1, pw2, D2, D2,
        g2, b2, x, out, nullptr);
}

// round 10
// speedup vs baseline: 4.9079x; 1.2091x over previous
#include <cuda_runtime.h>
#include <cuda_fp16.h>
#include <math.h>
#include <stdint.h>

// ---------------- problem constants ----------------
#define NB   4
#define LQ   8192
#define SS   8192
#define DD   256
#define HH   8
#define HD   32
#define D2   512
#define MR   (NB*LQ)        // 32768
#define EPS_ATTN 1e-6f
#define EPS_LN   1e-5f

// ---------------- scratch (device globals) ----------------
__device__ float g_KV  [NB*HH*HD*HD];
__device__ float g_Ksum[NB*HH*HD];

__device__ __half g_ss_h [(size_t)MR*DD];
__device__ __half g_kvh  [(size_t)MR*D2];   // [row][0:256]=K, [256:512]=V (fp16)
__device__ __half g_qz_h [(size_t)MR*DD];
__device__ __half g_cat_h[(size_t)MR*D2];
__device__ __half g_h1_h [(size_t)MR*D2];

__device__ __half g_wq [DD*DD];
__device__ __half g_wkv[D2*DD];             // rows 0-255 Wk, 256-511 Wv
__device__ __half g_w1 [D2*D2];
__device__ __half g_w2 [DD*D2];
__device__ __half g_G  [NB*DD*DD];          // per-batch effective weight (KV@Wm)/SS

// ---------------- low-level helpers ----------------
__device__ __forceinline__ uint32_t smem_u32(const void* p) {
    uint32_t a;
    asm("{ .reg .u64 t; cvta.to.shared.u64 t, %1; cvt.u32.u64 %0, t; }"
        : "=r"(a) : "l"(p));
    return a;
}

__device__ __forceinline__ uint32_t sw128(uint32_t off) {
    return off ^ ((off >> 3) & 0x70);
}

#define CPASYNC16(sa, ga) \
    asm volatile("cp.async.cg.shared.global [%0], [%1], 16;" \
                 :: "r"(sa), "l"(ga) : "memory")
#define CPCOMMIT() asm volatile("cp.async.commit_group;" ::: "memory")
#define CPWAIT0()  asm volatile("cp.async.wait_group 0;" ::: "memory")
#define CPWAIT1()  asm volatile("cp.async.wait_group 1;" ::: "memory")

#define LDSM4(r, addr) \
    asm volatile("ldmatrix.sync.aligned.m8n8.x4.shared.b16 {%0,%1,%2,%3}, [%4];" \
        : "=r"((r)[0]), "=r"((r)[1]), "=r"((r)[2]), "=r"((r)[3]) : "r"(addr))

#define LDSM4T(r, addr) \
    asm volatile("ldmatrix.sync.aligned.m8n8.x4.trans.shared.b16 {%0,%1,%2,%3}, [%4];" \
        : "=r"((r)[0]), "=r"((r)[1]), "=r"((r)[2]), "=r"((r)[3]) : "r"(addr))

__device__ __forceinline__ void mma_f16(float* c, const uint32_t* a,
                                        uint32_t b0, uint32_t b1) {
    asm volatile(
        "mma.sync.aligned.m16n8k16.row.col.f32.f16.f16.f32 "
        "{%0,%1,%2,%3}, {%4,%5,%6,%7}, {%8,%9}, {%0,%1,%2,%3};"
        : "+f"(c[0]), "+f"(c[1]), "+f"(c[2]), "+f"(c[3])
        : "r"(a[0]), "r"(a[1]), "r"(a[2]), "r"(a[3]), "r"(b0), "r"(b1));
}

__device__ __forceinline__ float warp_sum(float v) {
#pragma unroll
    for (int o = 16; o > 0; o >>= 1) v += __shfl_xor_sync(0xffffffffu, v, o);
    return v;
}

enum { ACT_NONE = 0, ACT_ELU1 = 1, ACT_RELU = 2, ACT_KVMIX = 3 };
enum { EPI_F32 = 0, EPI_HALF = 1, EPI_QZ = 2 };
enum { EPI_LNCAT = 0, EPI_LNRES = 1 };

// ================= persistent GEMM, 128x128 tile, fp16 =====================
#define T_BYTES   16384u
#define STG128    (2u*T_BYTES)     // 32KB/stage
#define GSMEM128  (2u*STG128)      // 64KB

template<int ACT, bool HASMASK, int EPI>
__global__ __launch_bounds__(256, 2)
void gemm128p(const __half* __restrict__ Ap, const __half* __restrict__ Bp, int lda,
              float* __restrict__ C, __half* __restrict__ Ch,
              int Nc, int K, const float* __restrict__ mask, float scale,
              const float* __restrict__ Ksum)
{
    extern __shared__ char smem[];
    const uint32_t sb = smem_u32(smem);
    const int tid  = threadIdx.x;
    const int lane = tid & 31;
    const int wid  = tid >> 5;
    const int wm   = wid >> 1;
    const int wn   = wid & 1;

    const int Ntl = Nc >> 7;
    const int T   = (MR >> 7) * Ntl;
    const int NCC = K >> 6;

    auto load_chunk = [&](int st, int bm, int bn, int c) {
        const int k0 = c * 64;
        const uint32_t stb = sb + st * STG128;
#pragma unroll
        for (int i = 0; i < 4; i++) {
            int ci  = tid + 256 * i;
            int row = ci >> 3;
            int c16 = ci & 7;
            uint32_t so = sw128((uint32_t)(row * 128 + c16 * 16));
            CPASYNC16(stb + so,           Ap + (size_t)(bm + row) * lda + k0 + c16 * 8);
            CPASYNC16(stb + T_BYTES + so, Bp + (size_t)(bn + row) * K   + k0 + c16 * 8);
        }
        CPCOMMIT();
    };

    const int t0 = blockIdx.x;
    if (t0 >= T) return;
    load_chunk(0, (t0 / Ntl) * 128, (t0 % Ntl) * 128, 0);

    const int a_row = wm * 32 + (lane & 15);
    const int a_kb  = (lane >> 4) * 16;
    const int b_row = wn * 64 + (lane & 7) + ((lane >> 4) << 3);
    const int b_kb  = ((lane >> 3) & 1) * 16;

    int g = 0;
    for (int t = t0; t < T; t += gridDim.x) {
        const int bm = (t / Ntl) * 128;
        const int bn = (t % Ntl) * 128;

        float acc[2][8][4];
#pragma unroll
        for (int i = 0; i < 2; i++)
#pragma unroll
            for (int j = 0; j < 8; j++)
#pragma unroll
                for (int v = 0; v < 4; v++) acc[i][j][v] = 0.f;

        for (int c = 0; c < NCC; c++) {
            if (c + 1 < NCC) {
                load_chunk((g + 1) & 1, bm, bn, c + 1);
                CPWAIT1();
            } else {
                int tn = t + gridDim.x;
                if (tn < T) {
                    load_chunk((g + 1) & 1, (tn / Ntl) * 128, (tn % Ntl) * 128, 0);
                    CPWAIT1();
                } else {
                    CPWAIT0();
                }
            }
            __syncthreads();

            const uint32_t stb = sb + (g & 1) * STG128;
#pragma unroll
            for (int ks = 0; ks < 4; ks++) {
                uint32_t ah[2][4], bh[4][4];
#pragma unroll
                for (int mt = 0; mt < 2; mt++) {
                    uint32_t ra = sw128((uint32_t)((a_row + mt * 16) * 128 + ks * 32 + a_kb));
                    LDSM4(ah[mt], stb + ra);
                }
#pragma unroll
                for (int ntp = 0; ntp < 4; ntp++) {
                    uint32_t rb = sw128((uint32_t)((b_row + ntp * 16) * 128 + ks * 32 + b_kb));
                    LDSM4(bh[ntp], stb + T_BYTES + rb);
                }
#pragma unroll
                for (int mt = 0; mt < 2; mt++)
#pragma unroll
                    for (int nt = 0; nt < 8; nt++) {
                        const int ntp = nt >> 1, o = (nt & 1) * 2;
                        mma_f16(acc[mt][nt], ah[mt], bh[ntp][o], bh[ntp][o + 1]);
                    }
            }
            g++;
            __syncthreads();
        }

        // ------------- register-direct epilogue -------------
        {
            const bool elu = (ACT == ACT_ELU1) || (ACT == ACT_KVMIX && bn < DD);
            float mk[2][2];
#pragma unroll
            for (int mt = 0; mt < 2; mt++)
#pragma unroll
                for (int rh = 0; rh < 2; rh++) {
                    int m = bm + wm * 32 + mt * 16 + (lane >> 2) + rh * 8;
                    mk[mt][rh] = (HASMASK ? mask[m] : 1.f) * scale;
                }
#pragma unroll
            for (int mt = 0; mt < 2; mt++)
#pragma unroll
                for (int nt = 0; nt < 8; nt++)
#pragma unroll
                    for (int v = 0; v < 4; v++) {
                        float xv = acc[mt][nt][v];
                        if (ACT == ACT_ELU1 || ACT == ACT_KVMIX) {
                            if (elu) xv = (xv > 0.f) ? (xv + 1.f) : expf(xv);
                        } else if (ACT == ACT_RELU) xv = fmaxf(xv, 0.f);
                        acc[mt][nt][v] = xv * mk[mt][v >> 1];
                    }

            if (EPI == EPI_QZ) {
                const int n = bm / LQ;
                float ksv[8][2];
#pragma unroll
                for (int nt = 0; nt < 8; nt++)
#pragma unroll
                    for (int j = 0; j < 2; j++)
                        ksv[nt][j] = Ksum[n * DD + bn + wn * 64 + nt * 8 + (lane & 3) * 2 + j];

                float p[2][2][2];
#pragma unroll
                for (int mt = 0; mt < 2; mt++)
#pragma unroll
                    for (int rh = 0; rh < 2; rh++)
#pragma unroll
                        for (int hg = 0; hg < 2; hg++) p[mt][rh][hg] = 0.f;
#pragma unroll
                for (int mt = 0; mt < 2; mt++)
#pragma unroll
                    for (int nt = 0; nt < 8; nt++)
#pragma unroll
                        for (int v = 0; v < 4; v++)
                            p[mt][v >> 1][nt >> 2] += acc[mt][nt][v] * ksv[nt][v & 1];

                float z[2][2][2];
#pragma unroll
                for (int mt = 0; mt < 2; mt++)
#pragma unroll
                    for (int rh = 0; rh < 2; rh++)
#pragma unroll
                        for (int hg = 0; hg < 2; hg++) {
                            float s = p[mt][rh][hg];
                            s += __shfl_xor_sync(0xffffffffu, s, 1);
                            s += __shfl_xor_sync(0xffffffffu, s, 2);
                            // scale by SS so qz stays in fp16 normal range;
                            // compensated by 1/SS folded into G.
                            z[mt][rh][hg] = (float)SS / (s + EPS_ATTN);
                        }

#pragma unroll
                for (int mt = 0; mt < 2; mt++)
#pragma unroll
                    for (int nt = 0; nt < 8; nt++)
#pragma unroll
                        for (int rh = 0; rh < 2; rh++) {
                            int row = bm + wm * 32 + mt * 16 + (lane >> 2) + rh * 8;
                            int col = bn + wn * 64 + nt * 8 + (lane & 3) * 2;
                            float zz = z[mt][rh][nt >> 2];
                            float v0 = acc[mt][nt][rh * 2]     * zz;
                            float v1 = acc[mt][nt][rh * 2 + 1] * zz;
                            *(__half2*)(Ch + (size_t)row * DD + col) =
                                __halves2half2(__float2half_rn(v0), __float2half_rn(v1));
                        }
            } else {
#pragma unroll
                for (int mt = 0; mt < 2; mt++)
#pragma unroll
                    for (int nt = 0; nt < 8; nt++)
#pragma unroll
                        for (int rh = 0; rh < 2; rh++) {
                            int row = bm + wm * 32 + mt * 16 + (lane >> 2) + rh * 8;
                            int col = bn + wn * 64 + nt * 8 + (lane & 3) * 2;
                            float v0 = acc[mt][nt][rh * 2];
                            float v1 = acc[mt][nt][rh * 2 + 1];
                            size_t gi = (size_t)row * Nc + col;
                            if (EPI == EPI_HALF) {
                                *(__half2*)(Ch + gi) =
                                    __halves2half2(__float2half_rn(v0), __float2half_rn(v1));
                            } else {
                                *(float2*)(C + gi) = make_float2(v0, v1);
                            }
                        }
            }
        }
    }
}

// ================= GEMM 64x256 tile (full-row, LN epilogue) ================
#define A_SZ   8192u
#define B_SZ   32768u
#define STG256 (A_SZ + B_SZ)       // 40KB
#define GSMEM256 (2u*STG256)       // 80KB

template<int EPI, bool BATCHB>
__global__ __launch_bounds__(256, 2)
void gemm256(const __half* __restrict__ Ap, const __half* __restrict__ Bp,
             int lda, int K,
             const float* __restrict__ gv_, const float* __restrict__ bv_,
             const float* __restrict__ xres,
             float* __restrict__ outf, __half* __restrict__ Ch)
{
    extern __shared__ char smem[];
    const uint32_t sb = smem_u32(smem);
    const int tid  = threadIdx.x;
    const int lane = tid & 31;
    const int wid  = tid >> 5;
    const int wm   = wid >> 2;
    const int wn   = wid & 3;
    const int bm   = blockIdx.x * 64;

    if (BATCHB) Bp += (size_t)(bm / LQ) * DD * DD;

    float acc[2][8][4];
#pragma unroll
    for (int i = 0; i < 2; i++)
#pragma unroll
        for (int j = 0; j < 8; j++)
#pragma unroll
            for (int v = 0; v < 4; v++) acc[i][j][v] = 0.f;

    const int NCC = K >> 6;

    auto load_chunk = [&](int st, int c) {
        const int k0 = c * 64;
        const uint32_t stb = sb + st * STG256;
#pragma unroll
        for (int i = 0; i < 10; i++) {
            int ci = tid + 256 * i;
            if (i < 2) {
                int row = ci >> 3, c16 = ci & 7;
                uint32_t so = sw128((uint32_t)(row * 128 + c16 * 16));
                CPASYNC16(stb + so, Ap + (size_t)(bm + row) * lda + k0 + c16 * 8);
            } else {
                int idx = ci - 512;
                int row = idx >> 3, c16 = idx & 7;
                uint32_t so = sw128((uint32_t)(row * 128 + c16 * 16));
                CPASYNC16(stb + A_SZ + so, Bp + (size_t)row * K + k0 + c16 * 8);
            }
        }
        CPCOMMIT();
    };

    load_chunk(0, 0);

    const int a_row = wm * 32 + (lane & 15);
    const int a_kb  = (lane >> 4) * 16;
    const int b_row = wn * 64 + (lane & 7) + ((lane >> 4) << 3);
    const int b_kb  = ((lane >> 3) & 1) * 16;

    for (int c = 0; c < NCC; c++) {
        if (c + 1 < NCC) { load_chunk((c + 1) & 1, c + 1); CPWAIT1(); }
        else             { CPWAIT0(); }
        __syncthreads();

        const uint32_t stb = sb + (c & 1) * STG256;
#pragma unroll
        for (int ks = 0; ks < 4; ks++) {
            uint32_t ah[2][4], bh[4][4];
#pragma unroll
            for (int mt = 0; mt < 2; mt++) {
                uint32_t ra = sw128((uint32_t)((a_row + mt * 16) * 128 + ks * 32 + a_kb));
                LDSM4(ah[mt], stb + ra);
            }
#pragma unroll
            for (int ntp = 0; ntp < 4; ntp++) {
                uint32_t rb = sw128((uint32_t)((b_row + ntp * 16) * 128 + ks * 32 + b_kb));
                LDSM4(bh[ntp], stb + A_SZ + rb);
            }
#pragma unroll
            for (int mt = 0; mt < 2; mt++)
#pragma unroll
                for (int nt = 0; nt < 8; nt++) {
                    const int ntp = nt >> 1, o = (nt & 1) * 2;
                    mma_f16(acc[mt][nt], ah[mt], bh[ntp][o], bh[ntp][o + 1]);
                }
        }
        __syncthreads();
    }

    // epilogue: stage + row LN
    float* sf = (float*)smem;
#pragma unroll
    for (int mt = 0; mt < 2; mt++)
#pragma unroll
        for (int nt = 0; nt < 8; nt++) {
            int r0 = wm * 32 + mt * 16 + (lane >> 2);
            int c0 = wn * 64 + nt * 8 + (lane & 3) * 2;
#pragma unroll
            for (int v = 0; v < 4; v++) {
                int row = r0 + (v >> 1) * 8;
                int col = c0 + (v & 1);
                sf[row * 260 + col] = acc[mt][nt][v];
            }
        }
    __syncthreads();

    float gvr[8], bvr[8];
#pragma unroll
    for (int j = 0; j < 8; j++) {
        gvr[j] = gv_[lane * 8 + j];
        bvr[j] = bv_[lane * 8 + j];
    }

#pragma unroll
    for (int i = 0; i < 8; i++) {
        const int row = wid + 8 * i;
        float v[8];
#pragma unroll
        for (int j = 0; j < 8; j++) v[j] = sf[row * 260 + lane * 8 + j];
        float s = 0.f;
#pragma unroll
        for (int j = 0; j < 8; j++) s += v[j];
        s = warp_sum(s);
        const float mu = s * (1.f / 256.f);
        float s2 = 0.f;
#pragma unroll
        for (int j = 0; j < 8; j++) { float d = v[j] - mu; s2 += d * d; }
        s2 = warp_sum(s2);
        const float rs = rsqrtf(s2 * (1.f / 256.f) + EPS_LN);

        const size_t gr = (size_t)(bm + row);
#pragma unroll
        for (int j = 0; j < 8; j++) {
            const int col = lane * 8 + j;
            float y = (v[j] - mu) * rs * gvr[j] + bvr[j];
            if (EPI == EPI_LNCAT) {
                Ch[gr * D2 + DD + col] = __float2half_rn(y);
            } else {
                outf[gr * DD + col] = xres[gr * DD + col] + y;
            }
        }
    }
}

// ================= KV via tensor cores (fp16 in, fp32 accum) ===============
// KV[n,h,d,e] = sum_s K[s,d] * V[s,e]
// grid (32 nh, 32 s-splits), 256 threads. Each warp: 32 s, full 32x32 output.
#define KVPAD 40   // halves per row (80B): conflict-free ldmatrix.trans

__global__ __launch_bounds__(256)
void kv_tc(const __half* __restrict__ KVh)
{
    __shared__ __half Ks[256][KVPAD];
    __shared__ __half Vs[256][KVPAD];
    __shared__ float kvbuf[32][33];
    __shared__ float ksbuf[8][32];

    const int nh = blockIdx.x;
    const int n  = nh >> 3;
    const int h  = nh & 7;
    const int s0 = blockIdx.y * 256;
    const int tid = threadIdx.x, lane = tid & 31, w = tid >> 5;

    const uint32_t ksb = smem_u32(&Ks[0][0]);
    const uint32_t vsb = smem_u32(&Vs[0][0]);

#pragma unroll
    for (int i = 0; i < 4; i++) {
        int idx = tid + 256 * i;          // 0..1023
        int row = idx >> 2, c = idx & 3;  // 4x16B per 64B row
        size_t gk = (size_t)(n * SS + s0 + row) * D2 + h * HD + c * 8;
        CPASYNC16(ksb + (uint32_t)(row * 80 + c * 16), KVh + gk);
        CPASYNC16(vsb + (uint32_t)(row * 80 + c * 16), KVh + gk + DD);
    }
    CPCOMMIT();
    for (int i = tid; i < 32 * 33; i += 256) (&kvbuf[0][0])[i] = 0.f;
    CPWAIT0();
    __syncthreads();

    // Ksum partials
    {
        float kp = 0.f;
        int d = tid & 31, r0 = tid >> 5;
#pragma unroll
        for (int i = 0; i < 32; i++) kp += __half2float(Ks[r0 + 8 * i][d]);
        ksbuf[r0][d] = kp;
    }

    // MMA: warp w covers s in [w*32, w*32+32)
    float acc[2][4][4];
#pragma unroll
    for (int mt = 0; mt < 2; mt++)
#pragma unroll
        for (int nf = 0; nf < 4; nf++)
#pragma unroll
            for (int v = 0; v < 4; v++) acc[mt][nf][v] = 0.f;

    const int q = lane >> 3, r = lane & 7;
#pragma unroll
    for (int ks2 = 0; ks2 < 2; ks2++) {
        const int kr = w * 32 + ks2 * 16;
        uint32_t a[2][4], bx[4], by[4];
#pragma unroll
        for (int mt = 0; mt < 2; mt++) {
            uint32_t addr = ksb + (uint32_t)((kr + (q >> 1) * 8 + r) * 80
                                             + ((q & 1) * 8 + mt * 16) * 2);
            LDSM4T(a[mt], addr);
        }
        {
            uint32_t rowb = (uint32_t)((kr + (q & 1) * 8 + r) * 80);
            LDSM4T(bx, vsb + rowb + (uint32_t)(((q >> 1) * 8) * 2));
            LDSM4T(by, vsb + rowb + (uint32_t)(((q >> 1) * 8 + 16) * 2));
        }
#pragma unroll
        for (int mt = 0; mt < 2; mt++) {
            mma_f16(acc[mt][0], a[mt], bx[0], bx[1]);
            mma_f16(acc[mt][1], a[mt], bx[2], bx[3]);
            mma_f16(acc[mt][2], a[mt], by[0], by[1]);
            mma_f16(acc[mt][3], a[mt], by[2], by[3]);
        }
    }

    // reduce across warps in smem
#pragma unroll
    for (int mt = 0; mt < 2; mt++)
#pragma unroll
        for (int nf = 0; nf < 4; nf++)
#pragma unroll
            for (int v = 0; v < 4; v++) {
                int row = mt * 16 + (lane >> 2) + (v >> 1) * 8;
                int col = nf * 8 + (lane & 3) * 2 + (v & 1);
                atomicAdd(&kvbuf[row][col], acc[mt][nf][v]);
            }
    __syncthreads();

    if (tid < 32) {
        float s = 0.f;
#pragma unroll
        for (int i = 0; i < 8; i++) s += ksbuf[i][tid];
        atomicAdd(g_Ksum + nh * HD + tid, s);
    }
    for (int i = tid; i < 1024; i += 256)
        atomicAdd(g_KV + (size_t)nh * 1024 + i, kvbuf[i >> 5][i & 31]);
}

// ---------------- merged prep ----------------
__device__ __forceinline__ void tohalf4(const float* s, __half* d, size_t si, size_t di) {
    float4 v = *(const float4*)(s + si * 4);
    __half2* dp = (__half2*)(d + di);
    dp[0] = __halves2half2(__float2half_rn(v.x), __float2half_rn(v.y));
    dp[1] = __halves2half2(__float2half_rn(v.z), __float2half_rn(v.w));
}

#define NW4  16384          // 256*256/4
#define NW1  65536          // 512*512/4
#define NW2  32768          // 256*512/4
#define NACT 2097152        // 32768*256/4
#define PREP_TOTAL (3*NW4 + NW1 + NW2 + 2*NACT)

__global__ __launch_bounds__(256)
void prep_kernel(const float* __restrict__ Wq, const float* __restrict__ Wk,
                 const float* __restrict__ Wv, const float* __restrict__ W1,
                 const float* __restrict__ W2, const float* __restrict__ src,
                 const float* __restrict__ x)
{
    int i = blockIdx.x * 256 + threadIdx.x;
    if (i < NB * HH * HD * HD) g_KV[i] = 0.f;
    if (i < NB * HH * HD)      g_Ksum[i] = 0.f;
    if (i >= PREP_TOTAL) return;

    int r = i;
    if (r < NW4) { tohalf4(Wq, g_wq, r, (size_t)r * 4); return; }
    r -= NW4;
    if (r < NW4) { tohalf4(Wk, g_wkv, r, (size_t)r * 4); return; }
    r -= NW4;
    if (r < NW4) { tohalf4(Wv, g_wkv, r, (size_t)(65536 + r * 4)); return; }
    r -= NW4;
    if (r < NW1) { tohalf4(W1, g_w1, r, (size_t)r * 4); return; }
    r -= NW1;
    if (r < NW2) { tohalf4(W2, g_w2, r, (size_t)r * 4); return; }
    r -= NW2;
    if (r < NACT) { tohalf4(src, g_ss_h, r, (size_t)r * 4); return; }
    r -= NACT;
    {   // x -> cat[:, 0:256]
        int e0  = r * 4;
        int row = e0 >> 8;
        int col = e0 & 255;
        tohalf4(x, g_cat_h, r, (size_t)row * D2 + col);
    }
}

// ---------------- G[n][j][h*32+d] = (1/SS) sum_e KV[n,h,d,e]*Wm[j,h*32+e] --
__global__ __launch_bounds__(256)
void g_kernel(const float* __restrict__ Wm)
{
    __shared__ float KVs[HD][HD];
    const int h = blockIdx.x;
    const int n = blockIdx.y;
    const int tid = threadIdx.x;

    {
        const float4* src = (const float4*)(g_KV + ((size_t)(n * HH + h)) * HD * HD);
        ((float4*)&KVs[0][0])[tid] = src[tid];
    }
    __syncthreads();

    const int j = tid;
    float w[HD];
#pragma unroll
    for (int e = 0; e < HD; e++) w[e] = Wm[(size_t)j * DD + h * HD + e];

    __half* Gp = (__half*)g_G + ((size_t)n * DD + j) * DD + h * HD;
    const float inv_ss = 1.f / (float)SS;   // compensates the SS in qz
#pragma unroll
    for (int d = 0; d < HD; d++) {
        float acc = 0.f;
#pragma unroll
        for (int e = 0; e < HD; e++) acc += KVs[d][e] * w[e];
        Gp[d] = __float2half_rn(acc * inv_ss);
    }
}

// ---------------- host ----------------
static float* sym_f(const void* s) { void* p = nullptr; cudaGetSymbolAddress(&p, s); return (float*)p; }
static __half* sym_h(const void* s) { void* p = nullptr; cudaGetSymbolAddress(&p, s); return (__half*)p; }

extern "C" void kernel_launch(void* const* d_in, const int* in_sizes, int n_in,
                              void* d_out, int out_size)
{
    const float* x           = (const float*)d_in[0];
    const float* source      = (const float*)d_in[1];
    const float* x_mask      = (const float*)d_in[2];
    const float* source_mask = (const float*)d_in[3];
    const float* Wq          = (const float*)d_in[4];
    const float* Wk          = (const float*)d_in[5];
    const float* Wv          = (const float*)d_in[6];
    const float* Wm          = (const float*)d_in[7];
    const float* W1          = (const float*)d_in[8];
    const float* W2          = (const float*)d_in[9];
    const float* g1          = (const float*)d_in[10];
    const float* b1          = (const float*)d_in[11];
    const float* g2          = (const float*)d_in[12];
    const float* b2          = (const float*)d_in[13];
    float* out = (float*)d_out;

    float* pKsum = sym_f(g_Ksum);

    __half *pss = sym_h(g_ss_h), *pqz = sym_h(g_qz_h);
    __half *pct = sym_h(g_cat_h), *ph1 = sym_h(g_h1_h);
    __half *pkvh = sym_h(g_kvh);
    __half *pwq = sym_h(g_wq), *pwkv = sym_h(g_wkv);
    __half *pw1 = sym_h(g_w1), *pw2 = sym_h(g_w2), *pG = sym_h(g_G);

    cudaFuncSetAttribute(gemm128p<ACT_KVMIX, true,  EPI_HALF>, cudaFuncAttributeMaxDynamicSharedMemorySize, GSMEM128);
    cudaFuncSetAttribute(gemm128p<ACT_ELU1,  true,  EPI_QZ  >, cudaFuncAttributeMaxDynamicSharedMemorySize, GSMEM128);
    cudaFuncSetAttribute(gemm128p<ACT_RELU,  false, EPI_HALF>, cudaFuncAttributeMaxDynamicSharedMemorySize, GSMEM128);
    cudaFuncSetAttribute(gemm256<EPI_LNCAT, true >, cudaFuncAttributeMaxDynamicSharedMemorySize, GSMEM256);
    cudaFuncSetAttribute(gemm256<EPI_LNRES, false>, cudaFuncAttributeMaxDynamicSharedMemorySize, GSMEM256);

    int nsm = 148;
    cudaDeviceGetAttribute(&nsm, cudaDevAttrMultiProcessorCount, 0);
    const int pgrid = 2 * nsm;

    dim3 blk(256);

    // prep: weight converts + activation converts + zero accumulators
    prep_kernel<<<(PREP_TOTAL + 255) / 256, 256>>>(Wq, Wk, Wv, W1, W2, source, x);

    // merged K|V projection -> g_kvh (fp16), act: elu1 on K half only
    gemm128p<ACT_KVMIX, true, EPI_HALF><<<pgrid, blk, GSMEM128>>>(pss, pwkv, DD,
        nullptr, pkvh, D2, DD, source_mask, 1.f, nullptr);

    // KV + Ksum via tensor cores, then G = (KV@Wm)/SS
    kv_tc<<<dim3(NB * HH, SS / 256), blk>>>(pkvh);
    g_kernel<<<dim3(HH, NB), blk>>>(Wm);

    // Q projection with fused Z: qz = Q*SS/(Q.Ksum+eps)  (fp16-normal range)
    gemm128p<ACT_ELU1, true, EPI_QZ><<<pgrid, blk, GSMEM128>>>(pct, pwq, D2,
        nullptr, pqz, DD, DD, x_mask, 1.f, pKsum);

    // msg2 = qz @ G[n].T with fused LN(g1,b1) -> cat[:,256:512]
    gemm256<EPI_LNCAT, true><<<MR / 64, blk, GSMEM256>>>(pqz, pG, DD, DD,
        g1, b1, nullptr, nullptr, pct);

    // h1 = relu(cat @ W1.T)
    gemm128p<ACT_RELU, false, EPI_HALF><<<pgrid, blk, GSMEM128>>>(pct, pw1, D2,
        nullptr, ph1, D2, D2, nullptr, 1.f, nullptr);

    // out = x + LN(h1 @ W2.T)
    gemm256<EPI_LNRES, false><<<MR / 64, blk, GSMEM256>>>(ph1, pw2, D2, D2,
        g2, b2, x, out, nullptr);
}

// round 11
// speedup vs baseline: 5.7909x; 1.1799x over previous
#include <cuda_runtime.h>
#include <cuda_fp16.h>
#include <math.h>
#include <stdint.h>

// ---------------- problem constants ----------------
#define NB   4
#define LQ   8192
#define SS   8192
#define DD   256
#define HH   8
#define HD   32
#define D2   512
#define MR   (NB*LQ)        // 32768
#define EPS_ATTN 1e-6f
#define EPS_LN   1e-5f

// ---------------- scratch (device globals) ----------------
__device__ float g_KV  [NB*HH*HD*HD];
__device__ float g_Ksum[NB*HH*HD];

__device__ __half g_ss_h [(size_t)MR*DD];
__device__ __half g_kvh  [(size_t)MR*D2];   // [row][0:256]=K, [256:512]=V (fp16)
__device__ __half g_qz_h [(size_t)MR*DD];
__device__ __half g_cat_h[(size_t)MR*D2];
__device__ __half g_h1_h [(size_t)MR*D2];

__device__ __half g_wq [DD*DD];
__device__ __half g_wkv[D2*DD];             // rows 0-255 Wk, 256-511 Wv
__device__ __half g_w1 [D2*D2];
__device__ __half g_w2 [DD*D2];
__device__ __half g_G  [NB*DD*DD];          // per-batch effective weight (KV@Wm)/SS

// ---------------- low-level helpers ----------------
__device__ __forceinline__ uint32_t smem_u32(const void* p) {
    uint32_t a;
    asm("{ .reg .u64 t; cvta.to.shared.u64 t, %1; cvt.u32.u64 %0, t; }"
        : "=r"(a) : "l"(p));
    return a;
}

__device__ __forceinline__ uint32_t sw128(uint32_t off) {
    return off ^ ((off >> 3) & 0x70);
}

#define CPASYNC16(sa, ga) \
    asm volatile("cp.async.cg.shared.global [%0], [%1], 16;" \
                 :: "r"(sa), "l"(ga) : "memory")
#define CPCOMMIT() asm volatile("cp.async.commit_group;" ::: "memory")
#define CPWAIT0()  asm volatile("cp.async.wait_group 0;" ::: "memory")
#define CPWAIT1()  asm volatile("cp.async.wait_group 1;" ::: "memory")

#define LDSM4(r, addr) \
    asm volatile("ldmatrix.sync.aligned.m8n8.x4.shared.b16 {%0,%1,%2,%3}, [%4];" \
        : "=r"((r)[0]), "=r"((r)[1]), "=r"((r)[2]), "=r"((r)[3]) : "r"(addr))

#define LDSM4T(r, addr) \
    asm volatile("ldmatrix.sync.aligned.m8n8.x4.trans.shared.b16 {%0,%1,%2,%3}, [%4];" \
        : "=r"((r)[0]), "=r"((r)[1]), "=r"((r)[2]), "=r"((r)[3]) : "r"(addr))

__device__ __forceinline__ void mma_f16(float* c, const uint32_t* a,
                                        uint32_t b0, uint32_t b1) {
    asm volatile(
        "mma.sync.aligned.m16n8k16.row.col.f32.f16.f16.f32 "
        "{%0,%1,%2,%3}, {%4,%5,%6,%7}, {%8,%9}, {%0,%1,%2,%3};"
        : "+f"(c[0]), "+f"(c[1]), "+f"(c[2]), "+f"(c[3])
        : "r"(a[0]), "r"(a[1]), "r"(a[2]), "r"(a[3]), "r"(b0), "r"(b1));
}

enum { ACT_NONE = 0, ACT_ELU1 = 1, ACT_RELU = 2, ACT_KVMIX = 3 };
enum { EPI_F32 = 0, EPI_HALF = 1, EPI_QZ = 2 };
enum { EPI_LNCAT = 0, EPI_LNRES = 1 };

// ================= persistent GEMM, 128x128 tile, fp16 =====================
#define T_BYTES   16384u
#define STG128    (2u*T_BYTES)     // 32KB/stage
#define GSMEM128  (2u*STG128)      // 64KB

template<int ACT, bool HASMASK, int EPI>
__global__ __launch_bounds__(256, 2)
void gemm128p(const __half* __restrict__ Ap, const __half* __restrict__ Bp, int lda,
              float* __restrict__ C, __half* __restrict__ Ch,
              int Nc, int K, const float* __restrict__ mask, float scale,
              const float* __restrict__ Ksum)
{
    extern __shared__ char smem[];
    const uint32_t sb = smem_u32(smem);
    const int tid  = threadIdx.x;
    const int lane = tid & 31;
    const int wid  = tid >> 5;
    const int wm   = wid >> 1;
    const int wn   = wid & 1;

    const int Ntl = Nc >> 7;
    const int T   = (MR >> 7) * Ntl;
    const int NCC = K >> 6;

    auto load_chunk = [&](int st, int bm, int bn, int c) {
        const int k0 = c * 64;
        const uint32_t stb = sb + st * STG128;
#pragma unroll
        for (int i = 0; i < 4; i++) {
            int ci  = tid + 256 * i;
            int row = ci >> 3;
            int c16 = ci & 7;
            uint32_t so = sw128((uint32_t)(row * 128 + c16 * 16));
            CPASYNC16(stb + so,           Ap + (size_t)(bm + row) * lda + k0 + c16 * 8);
            CPASYNC16(stb + T_BYTES + so, Bp + (size_t)(bn + row) * K   + k0 + c16 * 8);
        }
        CPCOMMIT();
    };

    const int t0 = blockIdx.x;
    if (t0 >= T) return;
    load_chunk(0, (t0 / Ntl) * 128, (t0 % Ntl) * 128, 0);

    const int a_row = wm * 32 + (lane & 15);
    const int a_kb  = (lane >> 4) * 16;
    const int b_row = wn * 64 + (lane & 7) + ((lane >> 4) << 3);
    const int b_kb  = ((lane >> 3) & 1) * 16;

    int g = 0;
    for (int t = t0; t < T; t += gridDim.x) {
        const int bm = (t / Ntl) * 128;
        const int bn = (t % Ntl) * 128;

        float acc[2][8][4];
#pragma unroll
        for (int i = 0; i < 2; i++)
#pragma unroll
            for (int j = 0; j < 8; j++)
#pragma unroll
                for (int v = 0; v < 4; v++) acc[i][j][v] = 0.f;

        for (int c = 0; c < NCC; c++) {
            if (c + 1 < NCC) {
                load_chunk((g + 1) & 1, bm, bn, c + 1);
                CPWAIT1();
            } else {
                int tn = t + gridDim.x;
                if (tn < T) {
                    load_chunk((g + 1) & 1, (tn / Ntl) * 128, (tn % Ntl) * 128, 0);
                    CPWAIT1();
                } else {
                    CPWAIT0();
                }
            }
            __syncthreads();

            const uint32_t stb = sb + (g & 1) * STG128;
#pragma unroll
            for (int ks = 0; ks < 4; ks++) {
                uint32_t ah[2][4], bh[4][4];
#pragma unroll
                for (int mt = 0; mt < 2; mt++) {
                    uint32_t ra = sw128((uint32_t)((a_row + mt * 16) * 128 + ks * 32 + a_kb));
                    LDSM4(ah[mt], stb + ra);
                }
#pragma unroll
                for (int ntp = 0; ntp < 4; ntp++) {
                    uint32_t rb = sw128((uint32_t)((b_row + ntp * 16) * 128 + ks * 32 + b_kb));
                    LDSM4(bh[ntp], stb + T_BYTES + rb);
                }
#pragma unroll
                for (int mt = 0; mt < 2; mt++)
#pragma unroll
                    for (int nt = 0; nt < 8; nt++) {
                        const int ntp = nt >> 1, o = (nt & 1) * 2;
                        mma_f16(acc[mt][nt], ah[mt], bh[ntp][o], bh[ntp][o + 1]);
                    }
            }
            g++;
            __syncthreads();
        }

        // ------------- register-direct epilogue -------------
        {
            const bool elu = (ACT == ACT_ELU1) || (ACT == ACT_KVMIX && bn < DD);
            float mk[2][2];
#pragma unroll
            for (int mt = 0; mt < 2; mt++)
#pragma unroll
                for (int rh = 0; rh < 2; rh++) {
                    int m = bm + wm * 32 + mt * 16 + (lane >> 2) + rh * 8;
                    mk[mt][rh] = (HASMASK ? mask[m] : 1.f) * scale;
                }
#pragma unroll
            for (int mt = 0; mt < 2; mt++)
#pragma unroll
                for (int nt = 0; nt < 8; nt++)
#pragma unroll
                    for (int v = 0; v < 4; v++) {
                        float xv = acc[mt][nt][v];
                        if (ACT == ACT_ELU1 || ACT == ACT_KVMIX) {
                            if (elu) xv = (xv > 0.f) ? (xv + 1.f) : expf(xv);
                        } else if (ACT == ACT_RELU) xv = fmaxf(xv, 0.f);
                        acc[mt][nt][v] = xv * mk[mt][v >> 1];
                    }

            if (EPI == EPI_QZ) {
                const int n = bm / LQ;
                float ksv[8][2];
#pragma unroll
                for (int nt = 0; nt < 8; nt++)
#pragma unroll
                    for (int j = 0; j < 2; j++)
                        ksv[nt][j] = Ksum[n * DD + bn + wn * 64 + nt * 8 + (lane & 3) * 2 + j];

                float p[2][2][2];
#pragma unroll
                for (int mt = 0; mt < 2; mt++)
#pragma unroll
                    for (int rh = 0; rh < 2; rh++)
#pragma unroll
                        for (int hg = 0; hg < 2; hg++) p[mt][rh][hg] = 0.f;
#pragma unroll
                for (int mt = 0; mt < 2; mt++)
#pragma unroll
                    for (int nt = 0; nt < 8; nt++)
#pragma unroll
                        for (int v = 0; v < 4; v++)
                            p[mt][v >> 1][nt >> 2] += acc[mt][nt][v] * ksv[nt][v & 1];

                float z[2][2][2];
#pragma unroll
                for (int mt = 0; mt < 2; mt++)
#pragma unroll
                    for (int rh = 0; rh < 2; rh++)
#pragma unroll
                        for (int hg = 0; hg < 2; hg++) {
                            float s = p[mt][rh][hg];
                            s += __shfl_xor_sync(0xffffffffu, s, 1);
                            s += __shfl_xor_sync(0xffffffffu, s, 2);
                            // SS keeps qz in fp16-normal range; 1/SS folded into G.
                            z[mt][rh][hg] = (float)SS / (s + EPS_ATTN);
                        }

#pragma unroll
                for (int mt = 0; mt < 2; mt++)
#pragma unroll
                    for (int nt = 0; nt < 8; nt++)
#pragma unroll
                        for (int rh = 0; rh < 2; rh++) {
                            int row = bm + wm * 32 + mt * 16 + (lane >> 2) + rh * 8;
                            int col = bn + wn * 64 + nt * 8 + (lane & 3) * 2;
                            float zz = z[mt][rh][nt >> 2];
                            float v0 = acc[mt][nt][rh * 2]     * zz;
                            float v1 = acc[mt][nt][rh * 2 + 1] * zz;
                            *(__half2*)(Ch + (size_t)row * DD + col) =
                                __halves2half2(__float2half_rn(v0), __float2half_rn(v1));
                        }
            } else {
#pragma unroll
                for (int mt = 0; mt < 2; mt++)
#pragma unroll
                    for (int nt = 0; nt < 8; nt++)
#pragma unroll
                        for (int rh = 0; rh < 2; rh++) {
                            int row = bm + wm * 32 + mt * 16 + (lane >> 2) + rh * 8;
                            int col = bn + wn * 64 + nt * 8 + (lane & 3) * 2;
                            float v0 = acc[mt][nt][rh * 2];
                            float v1 = acc[mt][nt][rh * 2 + 1];
                            size_t gi = (size_t)row * Nc + col;
                            if (EPI == EPI_HALF) {
                                *(__half2*)(Ch + gi) =
                                    __halves2half2(__float2half_rn(v0), __float2half_rn(v1));
                            } else {
                                *(float2*)(C + gi) = make_float2(v0, v1);
                            }
                        }
            }
        }
    }
}

// ===== persistent GEMM 64x256 tile, fused row-LN epilogue (sum-based) ======
#define A_SZ   8192u
#define B_SZ   32768u
#define STG256 (A_SZ + B_SZ)            // 40KB
#define SUMS_OFF (2u*STG256)            // 80KB
#define GSMEM256 (SUMS_OFF + 2048u)     // +2KB for row sums

template<int EPI, bool BATCHB>
__global__ __launch_bounds__(256, 2)
void gemm256p(const __half* __restrict__ Ap, const __half* __restrict__ Bp,
              int lda, int K,
              const float* __restrict__ gv_, const float* __restrict__ bv_,
              const float* __restrict__ xres,
              float* __restrict__ outf, __half* __restrict__ Ch)
{
    extern __shared__ char smem[];
    const uint32_t sb = smem_u32(smem);
    float* sums  = (float*)(smem + SUMS_OFF);   // [64][4]
    float* sumsq = sums + 256;                  // [64][4]
    const int tid  = threadIdx.x;
    const int lane = tid & 31;
    const int wid  = tid >> 5;
    const int wm   = wid >> 2;
    const int wn   = wid & 3;

    const int T   = MR / 64;   // 512
    const int NCC = K >> 6;

    // preload gamma/beta for this thread's fixed 16 columns
    float gvr[8][2], bvr[8][2];
#pragma unroll
    for (int nt = 0; nt < 8; nt++)
#pragma unroll
        for (int j = 0; j < 2; j++) {
            int col = wn * 64 + nt * 8 + (lane & 3) * 2 + j;
            gvr[nt][j] = gv_[col];
            bvr[nt][j] = bv_[col];
        }

    auto load_chunk = [&](int st, int bm, int c) {
        const int k0 = c * 64;
        const uint32_t stb = sb + st * STG256;
        const __half* Bt = BATCHB ? Bp + (size_t)(bm / LQ) * DD * DD : Bp;
#pragma unroll
        for (int i = 0; i < 10; i++) {
            int ci = tid + 256 * i;
            if (i < 2) {
                int row = ci >> 3, c16 = ci & 7;
                uint32_t so = sw128((uint32_t)(row * 128 + c16 * 16));
                CPASYNC16(stb + so, Ap + (size_t)(bm + row) * lda + k0 + c16 * 8);
            } else {
                int idx = ci - 512;
                int row = idx >> 3, c16 = idx & 7;
                uint32_t so = sw128((uint32_t)(row * 128 + c16 * 16));
                CPASYNC16(stb + A_SZ + so, Bt + (size_t)row * K + k0 + c16 * 8);
            }
        }
        CPCOMMIT();
    };

    const int t0 = blockIdx.x;
    if (t0 >= T) return;
    load_chunk(0, t0 * 64, 0);

    const int a_row = wm * 32 + (lane & 15);
    const int a_kb  = (lane >> 4) * 16;
    const int b_row = wn * 64 + (lane & 7) + ((lane >> 4) << 3);
    const int b_kb  = ((lane >> 3) & 1) * 16;

    int g = 0;
    for (int t = t0; t < T; t += gridDim.x) {
        const int bm = t * 64;

        float acc[2][8][4];
#pragma unroll
        for (int i = 0; i < 2; i++)
#pragma unroll
            for (int j = 0; j < 8; j++)
#pragma unroll
                for (int v = 0; v < 4; v++) acc[i][j][v] = 0.f;

        for (int c = 0; c < NCC; c++) {
            if (c + 1 < NCC) {
                load_chunk((g + 1) & 1, bm, c + 1);
                CPWAIT1();
            } else {
                int tn = t + gridDim.x;
                if (tn < T) {
                    load_chunk((g + 1) & 1, tn * 64, 0);
                    CPWAIT1();
                } else {
                    CPWAIT0();
                }
            }
            __syncthreads();

            const uint32_t stb = sb + (g & 1) * STG256;
#pragma unroll
            for (int ks = 0; ks < 4; ks++) {
                uint32_t ah[2][4], bh[4][4];
#pragma unroll
                for (int mt = 0; mt < 2; mt++) {
                    uint32_t ra = sw128((uint32_t)((a_row + mt * 16) * 128 + ks * 32 + a_kb));
                    LDSM4(ah[mt], stb + ra);
                }
#pragma unroll
                for (int ntp = 0; ntp < 4; ntp++) {
                    uint32_t rb = sw128((uint32_t)((b_row + ntp * 16) * 128 + ks * 32 + b_kb));
                    LDSM4(bh[ntp], stb + A_SZ + rb);
                }
#pragma unroll
                for (int mt = 0; mt < 2; mt++)
#pragma unroll
                    for (int nt = 0; nt < 8; nt++) {
                        const int ntp = nt >> 1, o = (nt & 1) * 2;
                        mma_f16(acc[mt][nt], ah[mt], bh[ntp][o], bh[ntp][o + 1]);
                    }
            }
            g++;
            __syncthreads();
        }

        // ------- LN epilogue: quad-shfl partial sums + 2KB smem reduce -------
#pragma unroll
        for (int mt = 0; mt < 2; mt++)
#pragma unroll
            for (int rh = 0; rh < 2; rh++) {
                float s = 0.f, s2 = 0.f;
#pragma unroll
                for (int nt = 0; nt < 8; nt++) {
                    float v0 = acc[mt][nt][rh * 2], v1 = acc[mt][nt][rh * 2 + 1];
                    s  += v0 + v1;
                    s2 += v0 * v0 + v1 * v1;
                }
                s  += __shfl_xor_sync(0xffffffffu, s, 1);
                s  += __shfl_xor_sync(0xffffffffu, s, 2);
                s2 += __shfl_xor_sync(0xffffffffu, s2, 1);
                s2 += __shfl_xor_sync(0xffffffffu, s2, 2);
                int rloc = wm * 32 + mt * 16 + (lane >> 2) + rh * 8;
                if ((lane & 3) == 0) {
                    sums [rloc * 4 + wn] = s;
                    sumsq[rloc * 4 + wn] = s2;
                }
            }
        __syncthreads();

#pragma unroll
        for (int mt = 0; mt < 2; mt++)
#pragma unroll
            for (int rh = 0; rh < 2; rh++) {
                int rloc = wm * 32 + mt * 16 + (lane >> 2) + rh * 8;
                float st = 0.f, s2t = 0.f;
#pragma unroll
                for (int k2 = 0; k2 < 4; k2++) {
                    st  += sums [rloc * 4 + k2];
                    s2t += sumsq[rloc * 4 + k2];
                }
                const float mu  = st * (1.f / 256.f);
                const float var = s2t * (1.f / 256.f) - mu * mu;
                const float rs  = rsqrtf(var + EPS_LN);
                const size_t gr = (size_t)(bm + rloc);
#pragma unroll
                for (int nt = 0; nt < 8; nt++) {
                    int col = wn * 64 + nt * 8 + (lane & 3) * 2;
                    float y0 = (acc[mt][nt][rh * 2]     - mu) * rs * gvr[nt][0] + bvr[nt][0];
                    float y1 = (acc[mt][nt][rh * 2 + 1] - mu) * rs * gvr[nt][1] + bvr[nt][1];
                    if (EPI == EPI_LNCAT) {
                        *(__half2*)(Ch + gr * D2 + DD + col) =
                            __halves2half2(__float2half_rn(y0), __float2half_rn(y1));
                    } else {
                        float2 xr = *(const float2*)(xres + gr * DD + col);
                        *(float2*)(outf + gr * DD + col) =
                            make_float2(xr.x + y0, xr.y + y1);
                    }
                }
            }
        __syncthreads();
    }
}

// ================= KV via tensor cores (fp16 in, fp32 accum) ===============
#define KVPAD 40   // halves per row (80B): conflict-free ldmatrix.trans

__global__ __launch_bounds__(256)
void kv_tc(const __half* __restrict__ KVh)
{
    __shared__ __half Ks[256][KVPAD];
    __shared__ __half Vs[256][KVPAD];
    __shared__ float kvbuf[32][33];
    __shared__ float ksbuf[8][32];

    const int nh = blockIdx.x;
    const int n  = nh >> 3;
    const int h  = nh & 7;
    const int s0 = blockIdx.y * 256;
    const int tid = threadIdx.x, lane = tid & 31, w = tid >> 5;

    const uint32_t ksb = smem_u32(&Ks[0][0]);
    const uint32_t vsb = smem_u32(&Vs[0][0]);

#pragma unroll
    for (int i = 0; i < 4; i++) {
        int idx = tid + 256 * i;
        int row = idx >> 2, c = idx & 3;
        size_t gk = (size_t)(n * SS + s0 + row) * D2 + h * HD + c * 8;
        CPASYNC16(ksb + (uint32_t)(row * 80 + c * 16), KVh + gk);
        CPASYNC16(vsb + (uint32_t)(row * 80 + c * 16), KVh + gk + DD);
    }
    CPCOMMIT();
    for (int i = tid; i < 32 * 33; i += 256) (&kvbuf[0][0])[i] = 0.f;
    CPWAIT0();
    __syncthreads();

    {
        float kp = 0.f;
        int d = tid & 31, r0 = tid >> 5;
#pragma unroll
        for (int i = 0; i < 32; i++) kp += __half2float(Ks[r0 + 8 * i][d]);
        ksbuf[r0][d] = kp;
    }

    float acc[2][4][4];
#pragma unroll
    for (int mt = 0; mt < 2; mt++)
#pragma unroll
        for (int nf = 0; nf < 4; nf++)
#pragma unroll
            for (int v = 0; v < 4; v++) acc[mt][nf][v] = 0.f;

    const int q = lane >> 3, r = lane & 7;
#pragma unroll
    for (int ks2 = 0; ks2 < 2; ks2++) {
        const int kr = w * 32 + ks2 * 16;
        uint32_t a[2][4], bx[4], by[4];
#pragma unroll
        for (int mt = 0; mt < 2; mt++) {
            uint32_t addr = ksb + (uint32_t)((kr + (q >> 1) * 8 + r) * 80
                                             + ((q & 1) * 8 + mt * 16) * 2);
            LDSM4T(a[mt], addr);
        }
        {
            uint32_t rowb = (uint32_t)((kr + (q & 1) * 8 + r) * 80);
            LDSM4T(bx, vsb + rowb + (uint32_t)(((q >> 1) * 8) * 2));
            LDSM4T(by, vsb + rowb + (uint32_t)(((q >> 1) * 8 + 16) * 2));
        }
#pragma unroll
        for (int mt = 0; mt < 2; mt++) {
            mma_f16(acc[mt][0], a[mt], bx[0], bx[1]);
            mma_f16(acc[mt][1], a[mt], bx[2], bx[3]);
            mma_f16(acc[mt][2], a[mt], by[0], by[1]);
            mma_f16(acc[mt][3], a[mt], by[2], by[3]);
        }
    }

#pragma unroll
    for (int mt = 0; mt < 2; mt++)
#pragma unroll
        for (int nf = 0; nf < 4; nf++)
#pragma unroll
            for (int v = 0; v < 4; v++) {
                int row = mt * 16 + (lane >> 2) + (v >> 1) * 8;
                int col = nf * 8 + (lane & 3) * 2 + (v & 1);
                atomicAdd(&kvbuf[row][col], acc[mt][nf][v]);
            }
    __syncthreads();

    if (tid < 32) {
        float s = 0.f;
#pragma unroll
        for (int i = 0; i < 8; i++) s += ksbuf[i][tid];
        atomicAdd(g_Ksum + nh * HD + tid, s);
    }
    for (int i = tid; i < 1024; i += 256)
        atomicAdd(g_KV + (size_t)nh * 1024 + i, kvbuf[i >> 5][i & 31]);
}

// ---------------- merged prep ----------------
__device__ __forceinline__ void tohalf4(const float* s, __half* d, size_t si, size_t di) {
    float4 v = *(const float4*)(s + si * 4);
    __half2* dp = (__half2*)(d + di);
    dp[0] = __halves2half2(__float2half_rn(v.x), __float2half_rn(v.y));
    dp[1] = __halves2half2(__float2half_rn(v.z), __float2half_rn(v.w));
}

#define NW4  16384
#define NW1  65536
#define NW2  32768
#define NACT 2097152
#define PREP_TOTAL (3*NW4 + NW1 + NW2 + 2*NACT)

__global__ __launch_bounds__(256)
void prep_kernel(const float* __restrict__ Wq, const float* __restrict__ Wk,
                 const float* __restrict__ Wv, const float* __restrict__ W1,
                 const float* __restrict__ W2, const float* __restrict__ src,
                 const float* __restrict__ x)
{
    int i = blockIdx.x * 256 + threadIdx.x;
    if (i < NB * HH * HD * HD) g_KV[i] = 0.f;
    if (i < NB * HH * HD)      g_Ksum[i] = 0.f;
    if (i >= PREP_TOTAL) return;

    int r = i;
    if (r < NW4) { tohalf4(Wq, g_wq, r, (size_t)r * 4); return; }
    r -= NW4;
    if (r < NW4) { tohalf4(Wk, g_wkv, r, (size_t)r * 4); return; }
    r -= NW4;
    if (r < NW4) { tohalf4(Wv, g_wkv, r, (size_t)(65536 + r * 4)); return; }
    r -= NW4;
    if (r < NW1) { tohalf4(W1, g_w1, r, (size_t)r * 4); return; }
    r -= NW1;
    if (r < NW2) { tohalf4(W2, g_w2, r, (size_t)r * 4); return; }
    r -= NW2;
    if (r < NACT) { tohalf4(src, g_ss_h, r, (size_t)r * 4); return; }
    r -= NACT;
    {
        int e0  = r * 4;
        int row = e0 >> 8;
        int col = e0 & 255;
        tohalf4(x, g_cat_h, r, (size_t)row * D2 + col);
    }
}

// ------ G[n][j][h*32+d] = (1/SS) sum_e KV[n,h,d,e]*Wm[j,h*32+e] ------------
// grid (HH, NB, 8): block handles 32 j's. thread = (j-quad, d).
__global__ __launch_bounds__(256)
void g_kernel(const float* __restrict__ Wm)
{
    __shared__ float KVsT[HD][HD + 1];   // [e][d], padded
    const int h = blockIdx.x;
    const int n = blockIdx.y;
    const int z = blockIdx.z;
    const int tid = threadIdx.x;

    for (int i = tid; i < HD * HD; i += 256) {
        int d = i >> 5, e = i & 31;
        KVsT[e][d] = g_KV[((size_t)(n * HH + h)) * HD * HD + i];
    }
    __syncthreads();

    const int d  = tid & 31;
    const int j0 = z * 32 + (tid >> 5) * 4;
    const float inv_ss = 1.f / (float)SS;
#pragma unroll
    for (int i = 0; i < 4; i++) {
        int j = j0 + i;
        const float* wrow = Wm + (size_t)j * DD + h * HD;   // uniform per warp
        float acc = 0.f;
#pragma unroll
        for (int e = 0; e < HD; e++) acc += KVsT[e][d] * wrow[e];
        ((__half*)g_G)[((size_t)n * DD + j) * DD + h * HD + d] =
            __float2half_rn(acc * inv_ss);
    }
}

// ---------------- host ----------------
static float* sym_f(const void* s) { void* p = nullptr; cudaGetSymbolAddress(&p, s); return (float*)p; }
static __half* sym_h(const void* s) { void* p = nullptr; cudaGetSymbolAddress(&p, s); return (__half*)p; }

extern "C" void kernel_launch(void* const* d_in, const int* in_sizes, int n_in,
                              void* d_out, int out_size)
{
    const float* x           = (const float*)d_in[0];
    const float* source      = (const float*)d_in[1];
    const float* x_mask      = (const float*)d_in[2];
    const float* source_mask = (const float*)d_in[3];
    const float* Wq          = (const float*)d_in[4];
    const float* Wk          = (const float*)d_in[5];
    const float* Wv          = (const float*)d_in[6];
    const float* Wm          = (const float*)d_in[7];
    const float* W1          = (const float*)d_in[8];
    const float* W2          = (const float*)d_in[9];
    const float* g1          = (const float*)d_in[10];
    const float* b1          = (const float*)d_in[11];
    const float* g2          = (const float*)d_in[12];
    const float* b2          = (const float*)d_in[13];
    float* out = (float*)d_out;

    float* pKsum = sym_f(g_Ksum);

    __half *pss = sym_h(g_ss_h), *pqz = sym_h(g_qz_h);
    __half *pct = sym_h(g_cat_h), *ph1 = sym_h(g_h1_h);
    __half *pkvh = sym_h(g_kvh);
    __half *pwq = sym_h(g_wq), *pwkv = sym_h(g_wkv);
    __half *pw1 = sym_h(g_w1), *pw2 = sym_h(g_w2), *pG = sym_h(g_G);

    cudaFuncSetAttribute(gemm128p<ACT_KVMIX, true,  EPI_HALF>, cudaFuncAttributeMaxDynamicSharedMemorySize, GSMEM128);
    cudaFuncSetAttribute(gemm128p<ACT_ELU1,  true,  EPI_QZ  >, cudaFuncAttributeMaxDynamicSharedMemorySize, GSMEM128);
    cudaFuncSetAttribute(gemm128p<ACT_RELU,  false, EPI_HALF>, cudaFuncAttributeMaxDynamicSharedMemorySize, GSMEM128);
    cudaFuncSetAttribute(gemm256p<EPI_LNCAT, true >, cudaFuncAttributeMaxDynamicSharedMemorySize, GSMEM256);
    cudaFuncSetAttribute(gemm256p<EPI_LNRES, false>, cudaFuncAttributeMaxDynamicSharedMemorySize, GSMEM256);

    int nsm = 148;
    cudaDeviceGetAttribute(&nsm, cudaDevAttrMultiProcessorCount, 0);
    const int pgrid = 2 * nsm;

    dim3 blk(256);

    // prep: weight converts + activation converts + zero accumulators
    prep_kernel<<<(PREP_TOTAL + 255) / 256, 256>>>(Wq, Wk, Wv, W1, W2, source, x);

    // merged K|V projection -> g_kvh (fp16), act: elu1 on K half only
    gemm128p<ACT_KVMIX, true, EPI_HALF><<<pgrid, blk, GSMEM128>>>(pss, pwkv, DD,
        nullptr, pkvh, D2, DD, source_mask, 1.f, nullptr);

    // KV + Ksum via tensor cores, then G = (KV@Wm)/SS
    kv_tc<<<dim3(NB * HH, SS / 256), blk>>>(pkvh);
    g_kernel<<<dim3(HH, NB, 8), blk>>>(Wm);

    // Q projection with fused Z: qz = Q*SS/(Q.Ksum+eps)
    gemm128p<ACT_ELU1, true, EPI_QZ><<<pgrid, blk, GSMEM128>>>(pct, pwq, D2,
        nullptr, pqz, DD, DD, x_mask, 1.f, pKsum);

    // msg2 = qz @ G[n].T with fused LN(g1,b1) -> cat[:,256:512]
    gemm256p<EPI_LNCAT, true><<<pgrid, blk, GSMEM256>>>(pqz, pG, DD, DD,
        g1, b1, nullptr, nullptr, pct);

    // h1 = relu(cat @ W1.T)
    gemm128p<ACT_RELU, false, EPI_HALF><<<pgrid, blk, GSMEM128>>>(pct, pw1, D2,
        nullptr, ph1, D2, D2, nullptr, 1.f, nullptr);

    // out = x + LN(h1 @ W2.T)
    gemm256p<EPI_LNRES, false><<<pgrid, blk, GSMEM256>>>(ph1, pw2, D2, D2,
        g2, b2, x, out, nullptr);
}

// round 12
// speedup vs baseline: 5.9513x; 1.0277x over previous
#include <cuda_runtime.h>
#include <cuda_fp16.h>
#include <math.h>
#include <stdint.h>

// ---------------- problem constants ----------------
#define NB   4
#define LQ   8192
#define SS   8192
#define DD   256
#define HH   8
#define HD   32
#define D2   512
#define MR   (NB*LQ)        // 32768
#define EPS_ATTN 1e-6f
#define EPS_LN   1e-5f

// ---------------- scratch (device globals) ----------------
__device__ float g_KV  [NB*HH*HD*HD];
__device__ float g_Ksum[NB*HH*HD];

__device__ __half g_ss_h [(size_t)MR*DD];
__device__ __half g_kvh  [(size_t)MR*D2];   // [row][0:256]=K, [256:512]=V (fp16)
__device__ __half g_qz_h [(size_t)MR*DD];
__device__ __half g_cat_h[(size_t)MR*D2];
__device__ __half g_h1_h [(size_t)MR*D2];

__device__ __half g_wq [DD*DD];
__device__ __half g_wkv[D2*DD];             // rows 0-255 Wk, 256-511 Wv
__device__ __half g_w1 [D2*D2];
__device__ __half g_w2 [DD*D2];
__device__ __half g_G  [NB*DD*DD];          // per-batch effective weight (KV@Wm)/SS

// ---------------- low-level helpers ----------------
__device__ __forceinline__ uint32_t smem_u32(const void* p) {
    uint32_t a;
    asm("{ .reg .u64 t; cvta.to.shared.u64 t, %1; cvt.u32.u64 %0, t; }"
        : "=r"(a) : "l"(p));
    return a;
}

__device__ __forceinline__ uint32_t sw128(uint32_t off) {
    return off ^ ((off >> 3) & 0x70);
}

#define CPASYNC16(sa, ga) \
    asm volatile("cp.async.cg.shared.global [%0], [%1], 16;" \
                 :: "r"(sa), "l"(ga) : "memory")
#define CPCOMMIT() asm volatile("cp.async.commit_group;" ::: "memory")
#define CPWAIT0()  asm volatile("cp.async.wait_group 0;" ::: "memory")
#define CPWAIT1()  asm volatile("cp.async.wait_group 1;" ::: "memory")

#define LDSM4(r, addr) \
    asm volatile("ldmatrix.sync.aligned.m8n8.x4.shared.b16 {%0,%1,%2,%3}, [%4];" \
        : "=r"((r)[0]), "=r"((r)[1]), "=r"((r)[2]), "=r"((r)[3]) : "r"(addr))

#define LDSM4T(r, addr) \
    asm volatile("ldmatrix.sync.aligned.m8n8.x4.trans.shared.b16 {%0,%1,%2,%3}, [%4];" \
        : "=r"((r)[0]), "=r"((r)[1]), "=r"((r)[2]), "=r"((r)[3]) : "r"(addr))

__device__ __forceinline__ void mma_f16(float* c, const uint32_t* a,
                                        uint32_t b0, uint32_t b1) {
    asm volatile(
        "mma.sync.aligned.m16n8k16.row.col.f32.f16.f16.f32 "
        "{%0,%1,%2,%3}, {%4,%5,%6,%7}, {%8,%9}, {%0,%1,%2,%3};"
        : "+f"(c[0]), "+f"(c[1]), "+f"(c[2]), "+f"(c[3])
        : "r"(a[0]), "r"(a[1]), "r"(a[2]), "r"(a[3]), "r"(b0), "r"(b1));
}

enum { ACT_NONE = 0, ACT_ELU1 = 1, ACT_RELU = 2, ACT_KVMIX = 3 };
enum { EPI_F32 = 0, EPI_HALF = 1, EPI_QZ = 2 };
enum { EPI_LNCAT = 0, EPI_LNRES = 1 };

// ================= persistent GEMM, 128x128 tile, fp16 =====================
#define T_BYTES   16384u
#define STG128    (2u*T_BYTES)     // 32KB/stage
#define GSMEM128  (2u*STG128)      // 64KB

template<int ACT, bool HASMASK, int EPI>
__global__ __launch_bounds__(256, 2)
void gemm128p(const __half* __restrict__ Ap, const __half* __restrict__ Bp, int lda,
              float* __restrict__ C, __half* __restrict__ Ch,
              int Nc, int K, const float* __restrict__ mask, float scale,
              const float* __restrict__ Ksum)
{
    extern __shared__ char smem[];
    const uint32_t sb = smem_u32(smem);
    const int tid  = threadIdx.x;
    const int lane = tid & 31;
    const int wid  = tid >> 5;
    const int wm   = wid >> 1;
    const int wn   = wid & 1;

    const int Ntl = Nc >> 7;
    const int T   = (MR >> 7) * Ntl;
    const int NCC = K >> 6;

    auto load_chunk = [&](int st, int bm, int bn, int c) {
        const int k0 = c * 64;
        const uint32_t stb = sb + st * STG128;
#pragma unroll
        for (int i = 0; i < 4; i++) {
            int ci  = tid + 256 * i;
            int row = ci >> 3;
            int c16 = ci & 7;
            uint32_t so = sw128((uint32_t)(row * 128 + c16 * 16));
            CPASYNC16(stb + so,           Ap + (size_t)(bm + row) * lda + k0 + c16 * 8);
            CPASYNC16(stb + T_BYTES + so, Bp + (size_t)(bn + row) * K   + k0 + c16 * 8);
        }
        CPCOMMIT();
    };

    const int t0 = blockIdx.x;
    if (t0 >= T) return;
    load_chunk(0, (t0 / Ntl) * 128, (t0 % Ntl) * 128, 0);

    const int a_row = wm * 32 + (lane & 15);
    const int a_kb  = (lane >> 4) * 16;
    const int b_row = wn * 64 + (lane & 7) + ((lane >> 4) << 3);
    const int b_kb  = ((lane >> 3) & 1) * 16;

    int g = 0;
    for (int t = t0; t < T; t += gridDim.x) {
        const int bm = (t / Ntl) * 128;
        const int bn = (t % Ntl) * 128;

        float acc[2][8][4];
#pragma unroll
        for (int i = 0; i < 2; i++)
#pragma unroll
            for (int j = 0; j < 8; j++)
#pragma unroll
                for (int v = 0; v < 4; v++) acc[i][j][v] = 0.f;

        for (int c = 0; c < NCC; c++) {
            if (c + 1 < NCC) {
                load_chunk((g + 1) & 1, bm, bn, c + 1);
                CPWAIT1();
            } else {
                int tn = t + gridDim.x;
                if (tn < T) {
                    load_chunk((g + 1) & 1, (tn / Ntl) * 128, (tn % Ntl) * 128, 0);
                    CPWAIT1();
                } else {
                    CPWAIT0();
                }
            }
            __syncthreads();

            const uint32_t stb = sb + (g & 1) * STG128;
#pragma unroll
            for (int ks = 0; ks < 4; ks++) {
                uint32_t ah[2][4], bh[4][4];
#pragma unroll
                for (int mt = 0; mt < 2; mt++) {
                    uint32_t ra = sw128((uint32_t)((a_row + mt * 16) * 128 + ks * 32 + a_kb));
                    LDSM4(ah[mt], stb + ra);
                }
#pragma unroll
                for (int ntp = 0; ntp < 4; ntp++) {
                    uint32_t rb = sw128((uint32_t)((b_row + ntp * 16) * 128 + ks * 32 + b_kb));
                    LDSM4(bh[ntp], stb + T_BYTES + rb);
                }
#pragma unroll
                for (int mt = 0; mt < 2; mt++)
#pragma unroll
                    for (int nt = 0; nt < 8; nt++) {
                        const int ntp = nt >> 1, o = (nt & 1) * 2;
                        mma_f16(acc[mt][nt], ah[mt], bh[ntp][o], bh[ntp][o + 1]);
                    }
            }
            g++;
            __syncthreads();
        }

        // ------------- register-direct epilogue -------------
        {
            const bool elu = (ACT == ACT_ELU1) || (ACT == ACT_KVMIX && bn < DD);
            float mk[2][2];
#pragma unroll
            for (int mt = 0; mt < 2; mt++)
#pragma unroll
                for (int rh = 0; rh < 2; rh++) {
                    int m = bm + wm * 32 + mt * 16 + (lane >> 2) + rh * 8;
                    mk[mt][rh] = (HASMASK ? mask[m] : 1.f) * scale;
                }
#pragma unroll
            for (int mt = 0; mt < 2; mt++)
#pragma unroll
                for (int nt = 0; nt < 8; nt++)
#pragma unroll
                    for (int v = 0; v < 4; v++) {
                        float xv = acc[mt][nt][v];
                        if (ACT == ACT_ELU1 || ACT == ACT_KVMIX) {
                            if (elu) xv = (xv > 0.f) ? (xv + 1.f) : expf(xv);
                        } else if (ACT == ACT_RELU) xv = fmaxf(xv, 0.f);
                        acc[mt][nt][v] = xv * mk[mt][v >> 1];
                    }

            if (EPI == EPI_QZ) {
                const int n = bm / LQ;
                float ksv[8][2];
#pragma unroll
                for (int nt = 0; nt < 8; nt++)
#pragma unroll
                    for (int j = 0; j < 2; j++)
                        ksv[nt][j] = Ksum[n * DD + bn + wn * 64 + nt * 8 + (lane & 3) * 2 + j];

                float p[2][2][2];
#pragma unroll
                for (int mt = 0; mt < 2; mt++)
#pragma unroll
                    for (int rh = 0; rh < 2; rh++)
#pragma unroll
                        for (int hg = 0; hg < 2; hg++) p[mt][rh][hg] = 0.f;
#pragma unroll
                for (int mt = 0; mt < 2; mt++)
#pragma unroll
                    for (int nt = 0; nt < 8; nt++)
#pragma unroll
                        for (int v = 0; v < 4; v++)
                            p[mt][v >> 1][nt >> 2] += acc[mt][nt][v] * ksv[nt][v & 1];

                float z[2][2][2];
#pragma unroll
                for (int mt = 0; mt < 2; mt++)
#pragma unroll
                    for (int rh = 0; rh < 2; rh++)
#pragma unroll
                        for (int hg = 0; hg < 2; hg++) {
                            float s = p[mt][rh][hg];
                            s += __shfl_xor_sync(0xffffffffu, s, 1);
                            s += __shfl_xor_sync(0xffffffffu, s, 2);
                            // SS keeps qz in fp16-normal range; 1/SS folded into G.
                            z[mt][rh][hg] = (float)SS / (s + EPS_ATTN);
                        }

#pragma unroll
                for (int mt = 0; mt < 2; mt++)
#pragma unroll
                    for (int nt = 0; nt < 8; nt++)
#pragma unroll
                        for (int rh = 0; rh < 2; rh++) {
                            int row = bm + wm * 32 + mt * 16 + (lane >> 2) + rh * 8;
                            int col = bn + wn * 64 + nt * 8 + (lane & 3) * 2;
                            float zz = z[mt][rh][nt >> 2];
                            float v0 = acc[mt][nt][rh * 2]     * zz;
                            float v1 = acc[mt][nt][rh * 2 + 1] * zz;
                            *(__half2*)(Ch + (size_t)row * DD + col) =
                                __halves2half2(__float2half_rn(v0), __float2half_rn(v1));
                        }
            } else {
#pragma unroll
                for (int mt = 0; mt < 2; mt++)
#pragma unroll
                    for (int nt = 0; nt < 8; nt++)
#pragma unroll
                        for (int rh = 0; rh < 2; rh++) {
                            int row = bm + wm * 32 + mt * 16 + (lane >> 2) + rh * 8;
                            int col = bn + wn * 64 + nt * 8 + (lane & 3) * 2;
                            float v0 = acc[mt][nt][rh * 2];
                            float v1 = acc[mt][nt][rh * 2 + 1];
                            size_t gi = (size_t)row * Nc + col;
                            if (EPI == EPI_HALF) {
                                *(__half2*)(Ch + gi) =
                                    __halves2half2(__float2half_rn(v0), __float2half_rn(v1));
                            } else {
                                *(float2*)(C + gi) = make_float2(v0, v1);
                            }
                        }
            }
        }
    }
}

// ===== persistent GEMM 64x256 tile, fused row-LN epilogue (sum-based) ======
#define A_SZ   8192u
#define B_SZ   32768u
#define STG256 (A_SZ + B_SZ)            // 40KB
#define SUMS_OFF (2u*STG256)            // 80KB
#define GSMEM256 (SUMS_OFF + 2048u)     // +2KB for row sums

template<int EPI, bool BATCHB>
__global__ __launch_bounds__(256, 2)
void gemm256p(const __half* __restrict__ Ap, const __half* __restrict__ Bp,
              int lda, int K,
              const float* __restrict__ gv_, const float* __restrict__ bv_,
              const float* __restrict__ xres,
              float* __restrict__ outf, __half* __restrict__ Ch)
{
    extern __shared__ char smem[];
    const uint32_t sb = smem_u32(smem);
    float* sums  = (float*)(smem + SUMS_OFF);   // [64][4]
    float* sumsq = sums + 256;                  // [64][4]
    const int tid  = threadIdx.x;
    const int lane = tid & 31;
    const int wid  = tid >> 5;
    const int wm   = wid >> 2;
    const int wn   = wid & 3;

    const int T   = MR / 64;   // 512
    const int NCC = K >> 6;

    float gvr[8][2], bvr[8][2];
#pragma unroll
    for (int nt = 0; nt < 8; nt++)
#pragma unroll
        for (int j = 0; j < 2; j++) {
            int col = wn * 64 + nt * 8 + (lane & 3) * 2 + j;
            gvr[nt][j] = gv_[col];
            bvr[nt][j] = bv_[col];
        }

    auto load_chunk = [&](int st, int bm, int c) {
        const int k0 = c * 64;
        const uint32_t stb = sb + st * STG256;
        const __half* Bt = BATCHB ? Bp + (size_t)(bm / LQ) * DD * DD : Bp;
#pragma unroll
        for (int i = 0; i < 10; i++) {
            int ci = tid + 256 * i;
            if (i < 2) {
                int row = ci >> 3, c16 = ci & 7;
                uint32_t so = sw128((uint32_t)(row * 128 + c16 * 16));
                CPASYNC16(stb + so, Ap + (size_t)(bm + row) * lda + k0 + c16 * 8);
            } else {
                int idx = ci - 512;
                int row = idx >> 3, c16 = idx & 7;
                uint32_t so = sw128((uint32_t)(row * 128 + c16 * 16));
                CPASYNC16(stb + A_SZ + so, Bt + (size_t)row * K + k0 + c16 * 8);
            }
        }
        CPCOMMIT();
    };

    const int t0 = blockIdx.x;
    if (t0 >= T) return;
    load_chunk(0, t0 * 64, 0);

    const int a_row = wm * 32 + (lane & 15);
    const int a_kb  = (lane >> 4) * 16;
    const int b_row = wn * 64 + (lane & 7) + ((lane >> 4) << 3);
    const int b_kb  = ((lane >> 3) & 1) * 16;

    int g = 0;
    for (int t = t0; t < T; t += gridDim.x) {
        const int bm = t * 64;

        float acc[2][8][4];
#pragma unroll
        for (int i = 0; i < 2; i++)
#pragma unroll
            for (int j = 0; j < 8; j++)
#pragma unroll
                for (int v = 0; v < 4; v++) acc[i][j][v] = 0.f;

        for (int c = 0; c < NCC; c++) {
            if (c + 1 < NCC) {
                load_chunk((g + 1) & 1, bm, c + 1);
                CPWAIT1();
            } else {
                int tn = t + gridDim.x;
                if (tn < T) {
                    load_chunk((g + 1) & 1, tn * 64, 0);
                    CPWAIT1();
                } else {
                    CPWAIT0();
                }
            }
            __syncthreads();

            const uint32_t stb = sb + (g & 1) * STG256;
#pragma unroll
            for (int ks = 0; ks < 4; ks++) {
                uint32_t ah[2][4], bh[4][4];
#pragma unroll
                for (int mt = 0; mt < 2; mt++) {
                    uint32_t ra = sw128((uint32_t)((a_row + mt * 16) * 128 + ks * 32 + a_kb));
                    LDSM4(ah[mt], stb + ra);
                }
#pragma unroll
                for (int ntp = 0; ntp < 4; ntp++) {
                    uint32_t rb = sw128((uint32_t)((b_row + ntp * 16) * 128 + ks * 32 + b_kb));
                    LDSM4(bh[ntp], stb + A_SZ + rb);
                }
#pragma unroll
                for (int mt = 0; mt < 2; mt++)
#pragma unroll
                    for (int nt = 0; nt < 8; nt++) {
                        const int ntp = nt >> 1, o = (nt & 1) * 2;
                        mma_f16(acc[mt][nt], ah[mt], bh[ntp][o], bh[ntp][o + 1]);
                    }
            }
            g++;
            __syncthreads();
        }

        // ------- LN epilogue: quad-shfl partial sums + 2KB smem reduce -------
#pragma unroll
        for (int mt = 0; mt < 2; mt++)
#pragma unroll
            for (int rh = 0; rh < 2; rh++) {
                float s = 0.f, s2 = 0.f;
#pragma unroll
                for (int nt = 0; nt < 8; nt++) {
                    float v0 = acc[mt][nt][rh * 2], v1 = acc[mt][nt][rh * 2 + 1];
                    s  += v0 + v1;
                    s2 += v0 * v0 + v1 * v1;
                }
                s  += __shfl_xor_sync(0xffffffffu, s, 1);
                s  += __shfl_xor_sync(0xffffffffu, s, 2);
                s2 += __shfl_xor_sync(0xffffffffu, s2, 1);
                s2 += __shfl_xor_sync(0xffffffffu, s2, 2);
                int rloc = wm * 32 + mt * 16 + (lane >> 2) + rh * 8;
                if ((lane & 3) == 0) {
                    sums [rloc * 4 + wn] = s;
                    sumsq[rloc * 4 + wn] = s2;
                }
            }
        __syncthreads();

#pragma unroll
        for (int mt = 0; mt < 2; mt++)
#pragma unroll
            for (int rh = 0; rh < 2; rh++) {
                int rloc = wm * 32 + mt * 16 + (lane >> 2) + rh * 8;
                float st = 0.f, s2t = 0.f;
#pragma unroll
                for (int k2 = 0; k2 < 4; k2++) {
                    st  += sums [rloc * 4 + k2];
                    s2t += sumsq[rloc * 4 + k2];
                }
                const float mu  = st * (1.f / 256.f);
                const float var = s2t * (1.f / 256.f) - mu * mu;
                const float rs  = rsqrtf(var + EPS_LN);
                const size_t gr = (size_t)(bm + rloc);
#pragma unroll
                for (int nt = 0; nt < 8; nt++) {
                    int col = wn * 64 + nt * 8 + (lane & 3) * 2;
                    float y0 = (acc[mt][nt][rh * 2]     - mu) * rs * gvr[nt][0] + bvr[nt][0];
                    float y1 = (acc[mt][nt][rh * 2 + 1] - mu) * rs * gvr[nt][1] + bvr[nt][1];
                    if (EPI == EPI_LNCAT) {
                        *(__half2*)(Ch + gr * D2 + DD + col) =
                            __halves2half2(__float2half_rn(y0), __float2half_rn(y1));
                    } else {
                        float2 xr = *(const float2*)(xres + gr * DD + col);
                        *(float2*)(outf + gr * DD + col) =
                            make_float2(xr.x + y0, xr.y + y1);
                    }
                }
            }
        __syncthreads();
    }
}

// ================= KV via tensor cores (fp16 in, fp32 accum) ===============
#define KVPAD 40

__global__ __launch_bounds__(256)
void kv_tc(const __half* __restrict__ KVh)
{
    __shared__ __half Ks[256][KVPAD];
    __shared__ __half Vs[256][KVPAD];
    __shared__ float kvbuf[32][33];
    __shared__ float ksbuf[8][32];

    const int nh = blockIdx.x;
    const int n  = nh >> 3;
    const int h  = nh & 7;
    const int s0 = blockIdx.y * 256;
    const int tid = threadIdx.x, lane = tid & 31, w = tid >> 5;

    const uint32_t ksb = smem_u32(&Ks[0][0]);
    const uint32_t vsb = smem_u32(&Vs[0][0]);

#pragma unroll
    for (int i = 0; i < 4; i++) {
        int idx = tid + 256 * i;
        int row = idx >> 2, c = idx & 3;
        size_t gk = (size_t)(n * SS + s0 + row) * D2 + h * HD + c * 8;
        CPASYNC16(ksb + (uint32_t)(row * 80 + c * 16), KVh + gk);
        CPASYNC16(vsb + (uint32_t)(row * 80 + c * 16), KVh + gk + DD);
    }
    CPCOMMIT();
    for (int i = tid; i < 32 * 33; i += 256) (&kvbuf[0][0])[i] = 0.f;
    CPWAIT0();
    __syncthreads();

    {
        float kp = 0.f;
        int d = tid & 31, r0 = tid >> 5;
#pragma unroll
        for (int i = 0; i < 32; i++) kp += __half2float(Ks[r0 + 8 * i][d]);
        ksbuf[r0][d] = kp;
    }

    float acc[2][4][4];
#pragma unroll
    for (int mt = 0; mt < 2; mt++)
#pragma unroll
        for (int nf = 0; nf < 4; nf++)
#pragma unroll
            for (int v = 0; v < 4; v++) acc[mt][nf][v] = 0.f;

    const int q = lane >> 3, r = lane & 7;
#pragma unroll
    for (int ks2 = 0; ks2 < 2; ks2++) {
        const int kr = w * 32 + ks2 * 16;
        uint32_t a[2][4], bx[4], by[4];
#pragma unroll
        for (int mt = 0; mt < 2; mt++) {
            uint32_t addr = ksb + (uint32_t)((kr + (q >> 1) * 8 + r) * 80
                                             + ((q & 1) * 8 + mt * 16) * 2);
            LDSM4T(a[mt], addr);
        }
        {
            uint32_t rowb = (uint32_t)((kr + (q & 1) * 8 + r) * 80);
            LDSM4T(bx, vsb + rowb + (uint32_t)(((q >> 1) * 8) * 2));
            LDSM4T(by, vsb + rowb + (uint32_t)(((q >> 1) * 8 + 16) * 2));
        }
#pragma unroll
        for (int mt = 0; mt < 2; mt++) {
            mma_f16(acc[mt][0], a[mt], bx[0], bx[1]);
            mma_f16(acc[mt][1], a[mt], bx[2], bx[3]);
            mma_f16(acc[mt][2], a[mt], by[0], by[1]);
            mma_f16(acc[mt][3], a[mt], by[2], by[3]);
        }
    }

#pragma unroll
    for (int mt = 0; mt < 2; mt++)
#pragma unroll
        for (int nf = 0; nf < 4; nf++)
#pragma unroll
            for (int v = 0; v < 4; v++) {
                int row = mt * 16 + (lane >> 2) + (v >> 1) * 8;
                int col = nf * 8 + (lane & 3) * 2 + (v & 1);
                atomicAdd(&kvbuf[row][col], acc[mt][nf][v]);
            }
    __syncthreads();

    if (tid < 32) {
        float s = 0.f;
#pragma unroll
        for (int i = 0; i < 8; i++) s += ksbuf[i][tid];
        atomicAdd(g_Ksum + nh * HD + tid, s);
    }
    for (int i = tid; i < 1024; i += 256)
        atomicAdd(g_KV + (size_t)nh * 1024 + i, kvbuf[i >> 5][i & 31]);
}

// ---------------- prep (split A/B for stream overlap) ----------------
__device__ __forceinline__ void tohalf4(const float* s, __half* d, size_t si, size_t di) {
    float4 v = *(const float4*)(s + si * 4);
    __half2* dp = (__half2*)(d + di);
    dp[0] = __halves2half2(__float2half_rn(v.x), __float2half_rn(v.y));
    dp[1] = __halves2half2(__float2half_rn(v.z), __float2half_rn(v.w));
}

#define NW4  16384
#define NW1  65536
#define NW2  32768
#define NACT 2097152
#define PREPA_TOTAL (3*NW4 + NW1 + NW2 + NACT)

// weights + source + zero accumulators (critical path)
__global__ __launch_bounds__(256)
void prep_a_kernel(const float* __restrict__ Wq, const float* __restrict__ Wk,
                   const float* __restrict__ Wv, const float* __restrict__ W1,
                   const float* __restrict__ W2, const float* __restrict__ src)
{
    int i = blockIdx.x * 256 + threadIdx.x;
    if (i < NB * HH * HD * HD) g_KV[i] = 0.f;
    if (i < NB * HH * HD)      g_Ksum[i] = 0.f;
    if (i >= PREPA_TOTAL) return;

    int r = i;
    if (r < NW4) { tohalf4(Wq, g_wq, r, (size_t)r * 4); return; }
    r -= NW4;
    if (r < NW4) { tohalf4(Wk, g_wkv, r, (size_t)r * 4); return; }
    r -= NW4;
    if (r < NW4) { tohalf4(Wv, g_wkv, r, (size_t)(65536 + r * 4)); return; }
    r -= NW4;
    if (r < NW1) { tohalf4(W1, g_w1, r, (size_t)r * 4); return; }
    r -= NW1;
    if (r < NW2) { tohalf4(W2, g_w2, r, (size_t)r * 4); return; }
    r -= NW2;
    tohalf4(src, g_ss_h, r, (size_t)r * 4);
}

// x -> cat[:,0:256] (side stream; only needed by Q projection)
__global__ __launch_bounds__(256)
void prep_b_kernel(const float* __restrict__ x)
{
    int r = blockIdx.x * 256 + threadIdx.x;
    if (r >= NACT) return;
    int e0  = r * 4;
    int row = e0 >> 8;
    int col = e0 & 255;
    tohalf4(x, g_cat_h, r, (size_t)row * D2 + col);
}

// ------ G[n][j][h*32+d] = (1/SS) sum_e KV[n,h,d,e]*Wm[j,h*32+e] ------------
__global__ __launch_bounds__(256)
void g_kernel(const float* __restrict__ Wm)
{
    __shared__ float KVsT[HD][HD + 1];
    const int h = blockIdx.x;
    const int n = blockIdx.y;
    const int z = blockIdx.z;
    const int tid = threadIdx.x;

    for (int i = tid; i < HD * HD; i += 256) {
        int d = i >> 5, e = i & 31;
        KVsT[e][d] = g_KV[((size_t)(n * HH + h)) * HD * HD + i];
    }
    __syncthreads();

    const int d  = tid & 31;
    const int j0 = z * 32 + (tid >> 5) * 4;
    const float inv_ss = 1.f / (float)SS;
#pragma unroll
    for (int i = 0; i < 4; i++) {
        int j = j0 + i;
        const float* wrow = Wm + (size_t)j * DD + h * HD;
        float acc = 0.f;
#pragma unroll
        for (int e = 0; e < HD; e++) acc += KVsT[e][d] * wrow[e];
        ((__half*)g_G)[((size_t)n * DD + j) * DD + h * HD + d] =
            __float2half_rn(acc * inv_ss);
    }
}

// ---------------- host ----------------
static float* sym_f(const void* s) { void* p = nullptr; cudaGetSymbolAddress(&p, s); return (float*)p; }
static __half* sym_h(const void* s) { void* p = nullptr; cudaGetSymbolAddress(&p, s); return (__half*)p; }

extern "C" void kernel_launch(void* const* d_in, const int* in_sizes, int n_in,
                              void* d_out, int out_size)
{
    const float* x           = (const float*)d_in[0];
    const float* source      = (const float*)d_in[1];
    const float* x_mask      = (const float*)d_in[2];
    const float* source_mask = (const float*)d_in[3];
    const float* Wq          = (const float*)d_in[4];
    const float* Wk          = (const float*)d_in[5];
    const float* Wv          = (const float*)d_in[6];
    const float* Wm          = (const float*)d_in[7];
    const float* W1          = (const float*)d_in[8];
    const float* W2          = (const float*)d_in[9];
    const float* g1          = (const float*)d_in[10];
    const float* b1          = (const float*)d_in[11];
    const float* g2          = (const float*)d_in[12];
    const float* b2          = (const float*)d_in[13];
    float* out = (float*)d_out;

    float* pKsum = sym_f(g_Ksum);

    __half *pss = sym_h(g_ss_h), *pqz = sym_h(g_qz_h);
    __half *pct = sym_h(g_cat_h), *ph1 = sym_h(g_h1_h);
    __half *pkvh = sym_h(g_kvh);
    __half *pwq = sym_h(g_wq), *pwkv = sym_h(g_wkv);
    __half *pw1 = sym_h(g_w1), *pw2 = sym_h(g_w2), *pG = sym_h(g_G);

    cudaFuncSetAttribute(gemm128p<ACT_KVMIX, true,  EPI_HALF>, cudaFuncAttributeMaxDynamicSharedMemorySize, GSMEM128);
    cudaFuncSetAttribute(gemm128p<ACT_ELU1,  true,  EPI_QZ  >, cudaFuncAttributeMaxDynamicSharedMemorySize, GSMEM128);
    cudaFuncSetAttribute(gemm128p<ACT_RELU,  false, EPI_HALF>, cudaFuncAttributeMaxDynamicSharedMemorySize, GSMEM128);
    cudaFuncSetAttribute(gemm256p<EPI_LNCAT, true >, cudaFuncAttributeMaxDynamicSharedMemorySize, GSMEM256);
    cudaFuncSetAttribute(gemm256p<EPI_LNRES, false>, cudaFuncAttributeMaxDynamicSharedMemorySize, GSMEM256);

    int nsm = 148;
    cudaDeviceGetAttribute(&nsm, cudaDevAttrMultiProcessorCount, 0);
    const int pgrid = 2 * nsm;

    // one-time side stream + events (host objects; no device allocation)
    static cudaStream_t s1 = nullptr;
    static cudaEvent_t evStart, evB, evK, evG;
    if (s1 == nullptr) {
        cudaStreamCreateWithFlags(&s1, cudaStreamNonBlocking);
        cudaEventCreateWithFlags(&evStart, cudaEventDisableTiming);
        cudaEventCreateWithFlags(&evB,     cudaEventDisableTiming);
        cudaEventCreateWithFlags(&evK,     cudaEventDisableTiming);
        cudaEventCreateWithFlags(&evG,     cudaEventDisableTiming);
    }

    dim3 blk(256);

    // fork: s1 branch handles x->cat while s0 runs the KV chain
    cudaEventRecord(evStart, 0);
    cudaStreamWaitEvent(s1, evStart, 0);

    // s1: x -> cat[:,0:256]
    prep_b_kernel<<<(NACT + 255) / 256, blk, 0, s1>>>(x);
    cudaEventRecord(evB, s1);

    // s0: weights + source converts + zero accumulators
    prep_a_kernel<<<(PREPA_TOTAL + 255) / 256, blk>>>(Wq, Wk, Wv, W1, W2, source);

    // s0: merged K|V projection -> g_kvh (fp16), elu1 on K half only
    gemm128p<ACT_KVMIX, true, EPI_HALF><<<pgrid, blk, GSMEM128>>>(pss, pwkv, DD,
        nullptr, pkvh, D2, DD, source_mask, 1.f, nullptr);

    // s0: KV + Ksum via tensor cores
    kv_tc<<<dim3(NB * HH, SS / 256), blk>>>(pkvh);
    cudaEventRecord(evK, 0);

    // s1: G = (KV@Wm)/SS  (overlaps with qz GEMM on s0)
    cudaStreamWaitEvent(s1, evK, 0);
    g_kernel<<<dim3(HH, NB, 8), blk, 0, s1>>>(Wm);
    cudaEventRecord(evG, s1);

    // s0: Q projection with fused Z (needs cat from s1 + Ksum)
    cudaStreamWaitEvent(0, evB, 0);
    gemm128p<ACT_ELU1, true, EPI_QZ><<<pgrid, blk, GSMEM128>>>(pct, pwq, D2,
        nullptr, pqz, DD, DD, x_mask, 1.f, pKsum);

    // s0: msg2 = qz @ G[n].T with fused LN(g1,b1) -> cat[:,256:512] (join evG)
    cudaStreamWaitEvent(0, evG, 0);
    gemm256p<EPI_LNCAT, true><<<pgrid, blk, GSMEM256>>>(pqz, pG, DD, DD,
        g1, b1, nullptr, nullptr, pct);

    // s0: h1 = relu(cat @ W1.T)
    gemm128p<ACT_RELU, false, EPI_HALF><<<pgrid, blk, GSMEM128>>>(pct, pw1, D2,
        nullptr, ph1, D2, D2, nullptr, 1.f, nullptr);

    // s0: out = x + LN(h1 @ W2.T)
    gemm256p<EPI_LNRES, false><<<pgrid, blk, GSMEM256>>>(ph1, pw2, D2, D2,
        g2, b2, x, out, nullptr);
}